// round 5
// baseline (speedup 1.0000x reference)
#include <cuda_runtime.h>
#include <cuda_bf16.h>
#include <cstdint>
#include <math.h>

#define CB 32
#define CS 512
#define CE 512
#define CDK 128
#define CH 6
#define CD2 1024
#define CHD 768

// ---------------- sizes (elements) ----------------
constexpr long NB_XP  = (long)CB*CS*CE;
constexpr long NB_QKV = (long)CB*CH*CS*CDK;
constexpr long NB_SC  = (long)CB*CH*CS*CS;
constexpr long NB_Z   = (long)CB*CS*CHD;
constexpr long NB_D2  = (long)CB*CS*CD2;
constexpr long NW_QKV1 = (long)CH*CE*CDK;
constexpr long NW_QKV2 = (long)CH*CD2*CDK;
constexpr long NW_O   = (long)CHD*CD2;
constexpr long NW_F   = (long)CD2*CD2;

// ---------------- f32 scratch offsets ----------------
constexpr long OF_POS = 0;
constexpr long OF_XP  = OF_POS + (long)CS*CE;
constexpr long OF_V   = OF_XP + NB_XP;
constexpr long OF_SC  = OF_V + NB_QKV;
constexpr long OF_A   = OF_SC + NB_SC;
constexpr long OF_N1  = OF_A + NB_D2;
constexpr long OF_N2  = OF_N1 + NB_D2;
constexpr long OF_N3  = OF_N2 + NB_D2;
constexpr long OF_F   = OF_N3 + NB_D2;
constexpr long F32_END = OF_F + NB_D2;

// ---------------- bf16 scratch offsets ----------------
constexpr long HB_XPH = 0;
constexpr long HB_XPL = HB_XPH + NB_XP;
constexpr long HB_QH  = HB_XPL + NB_XP;
constexpr long HB_QL  = HB_QH + NB_QKV;
constexpr long HB_KH  = HB_QL + NB_QKV;
constexpr long HB_KL  = HB_KH + NB_QKV;
constexpr long HB_VTH = HB_KL + NB_QKV;
constexpr long HB_VTL = HB_VTH + NB_QKV;
constexpr long HB_ATH = HB_VTL + NB_QKV;
constexpr long HB_ATL = HB_ATH + NB_SC;
constexpr long HB_ZH  = HB_ATL + NB_SC;
constexpr long HB_ZL  = HB_ZH + NB_Z;
constexpr long HB_N1H = HB_ZL + NB_Z;
constexpr long HB_N1L = HB_N1H + NB_D2;
constexpr long HB_N2H = HB_N1L + NB_D2;
constexpr long HB_N2L = HB_N2H + NB_D2;
constexpr long HB_N3H = HB_N2L + NB_D2;
constexpr long HB_N3L = HB_N3H + NB_D2;
constexpr long HB_W1QH = HB_N3L + NB_D2;
constexpr long HB_W1QL = HB_W1QH + NW_QKV1;
constexpr long HB_W1KH = HB_W1QL + NW_QKV1;
constexpr long HB_W1KL = HB_W1KH + NW_QKV1;
constexpr long HB_W1VH = HB_W1KL + NW_QKV1;
constexpr long HB_W1VL = HB_W1VH + NW_QKV1;
constexpr long HB_W1OH = HB_W1VL + NW_QKV1;
constexpr long HB_W1OL = HB_W1OH + NW_O;
constexpr long HB_W1FH = HB_W1OL + NW_O;
constexpr long HB_W1FL = HB_W1FH + NW_F;
constexpr long HB_W2QH = HB_W1FL + NW_F;
constexpr long HB_W2QL = HB_W2QH + NW_QKV2;
constexpr long HB_W2KH = HB_W2QL + NW_QKV2;
constexpr long HB_W2KL = HB_W2KH + NW_QKV2;
constexpr long HB_W2VH = HB_W2KL + NW_QKV2;
constexpr long HB_W2VL = HB_W2VH + NW_QKV2;
constexpr long HB_W2OH = HB_W2VL + NW_QKV2;
constexpr long HB_W2OL = HB_W2OH + NW_O;
constexpr long HB_W2FH = HB_W2OL + NW_O;
constexpr long HB_W2FL = HB_W2FH + NW_F;
constexpr long HB_END  = HB_W2FL + NW_F;

constexpr long SCRATCH_TOT = F32_END + (HB_END + 1) / 2 + 64;
__device__ float g_scratch[SCRATCH_TOT];

// ---------------- helpers ----------------
__device__ __forceinline__ void f2hilo(float v, __nv_bfloat16& h, __nv_bfloat16& l) {
    h = __float2bfloat16(v);
    l = __float2bfloat16(v - __bfloat162float(h));
}

__device__ __forceinline__ void cp16(uint32_t d, const void* s) {
    asm volatile("cp.async.cg.shared.global [%0], [%1], 16;\n" :: "r"(d), "l"(s));
}

#define MMA16816(c, a, b0, b1)                                              \
    asm volatile("mma.sync.aligned.m16n8k16.row.col.f32.bf16.bf16.f32 "     \
                 "{%0,%1,%2,%3},{%4,%5,%6,%7},{%8,%9},{%0,%1,%2,%3};"       \
                 : "+f"((c)[0]), "+f"((c)[1]), "+f"((c)[2]), "+f"((c)[3])   \
                 : "r"((a)[0]), "r"((a)[1]), "r"((a)[2]), "r"((a)[3]),      \
                   "r"(b0), "r"(b1))

// ---------------- positional encoding ----------------
__global__ void posgen_kernel(float* __restrict__ pos) {
    int idx = blockIdx.x * blockDim.x + threadIdx.x;
    if (idx >= CS * CE) return;
    int s = idx >> 9;
    int e = idx & 511;
    int m = e >> 1;
    double ang = (m >= 128) ? ((double)s / 10000.0) : (double)s;
    pos[idx] = (e & 1) ? (float)cos(ang) : (float)sin(ang);
}

__global__ void addpos_hilo(const float* __restrict__ X,
                            const float* __restrict__ pos,
                            float* __restrict__ xp,
                            __nv_bfloat16* __restrict__ xh,
                            __nv_bfloat16* __restrict__ xl, long n) {
    long idx = (long)blockIdx.x * blockDim.x + threadIdx.x;
    if (idx >= n) return;
    float v = X[idx] + pos[idx % (CS * CE)];
    xp[idx] = v;
    f2hilo(v, xh[idx], xl[idx]);
}

// ---------------- transpose + hi/lo convert ----------------
__global__ void transpose_hilo(const float* __restrict__ in,
                               __nv_bfloat16* __restrict__ oh,
                               __nv_bfloat16* __restrict__ ol,
                               int R, int C) {
    __shared__ float t[32][33];
    long zo = (long)blockIdx.z * R * C;
    int c0 = blockIdx.x * 32, r0 = blockIdx.y * 32;
    int tx = threadIdx.x, ty = threadIdx.y;
    #pragma unroll
    for (int i = 0; i < 32; i += 8)
        t[ty + i][tx] = in[zo + (long)(r0 + ty + i) * C + c0 + tx];
    __syncthreads();
    #pragma unroll
    for (int i = 0; i < 32; i += 8) {
        float v = t[tx][ty + i];
        long o = zo + (long)(c0 + ty + i) * R + r0 + tx;
        __nv_bfloat16 h, l;
        f2hilo(v, h, l);
        oh[o] = h; ol[o] = l;
    }
}

// ---------------- 3xBF16 tensor-core GEMM, 256x128 tiles ----------------
// C = alpha * A @ B^T (+bias)(+tanh). A: [M][K] hi/lo bf16, B: [N][K] hi/lo bf16.
// 256 threads, 8 warps (4m x 2n), warp tile 64x64, BK=32, 3-stage cp.async.
// Stage layout (80B pitch rows): Ah @0 (20480), Al @20480, Bh @40960 (10240), Bl @51200.
#define STG 61440
#define NSTG 3
#define G4SMEM (NSTG * STG)   // 184320

__device__ __forceinline__ void g4_load(
    uint32_t sbase, int stage,
    const __nv_bfloat16* ga_h, const __nv_bfloat16* ga_l,
    const __nv_bfloat16* gb_h, const __nv_bfloat16* gb_l,
    int k0, int tid)
{
    uint32_t d = sbase + stage * STG;
    uint32_t da = d + tid * 80;
    #pragma unroll
    for (int c = 0; c < 4; ++c) {
        cp16(da + c * 16,         ga_h + k0 + c * 8);
        cp16(da + 20480 + c * 16, ga_l + k0 + c * 8);
    }
    int bc = (tid >> 7) * 2;   // 0 or 2
    uint32_t db = d + 40960 + (tid & 127) * 80 + bc * 16;
    #pragma unroll
    for (int c = 0; c < 2; ++c) {
        cp16(db + c * 16,         gb_h + k0 + (bc + c) * 8);
        cp16(db + 10240 + c * 16, gb_l + k0 + (bc + c) * 8);
    }
    asm volatile("cp.async.commit_group;");
}

template<int OUTMODE, bool TANH>
__global__ void __launch_bounds__(256, 1) gemm4(
    const __nv_bfloat16* __restrict__ Ah, const __nv_bfloat16* __restrict__ Al,
    const __nv_bfloat16* __restrict__ Bh, const __nv_bfloat16* __restrict__ Bl,
    const float* __restrict__ biasb,
    float* __restrict__ Cf,
    __nv_bfloat16* __restrict__ Ch, __nv_bfloat16* __restrict__ Cl,
    int K, int lda, int ldb, int ldc, int Hdiv,
    long sA_b, long sA_h, long sB_b, long sB_h,
    long sC_b, long sC_h, long sBias_h, float alpha)
{
    extern __shared__ uint8_t smem[];
    uint32_t sbase = (uint32_t)__cvta_generic_to_shared(smem);
    int z = blockIdx.z, zb = z / Hdiv, zh_ = z - zb * Hdiv;
    const __nv_bfloat16* Ahp = Ah + zb * sA_b + zh_ * sA_h;
    const __nv_bfloat16* Alp = Al + zb * sA_b + zh_ * sA_h;
    const __nv_bfloat16* Bhp = Bh + zb * sB_b + zh_ * sB_h;
    const __nv_bfloat16* Blp = Bl + zb * sB_b + zh_ * sB_h;
    int m0 = blockIdx.y * 256, n0 = blockIdx.x * 128;
    int tid = threadIdx.x, wid = tid >> 5, lane = tid & 31;
    int g = lane >> 2, tig = lane & 3;
    int wm = (wid & 3) * 64, wn = (wid >> 2) * 64;

    float acc[4][8][4];
    #pragma unroll
    for (int i = 0; i < 4; ++i)
        #pragma unroll
        for (int j = 0; j < 8; ++j)
            #pragma unroll
            for (int q = 0; q < 4; ++q) acc[i][j][q] = 0.f;

    const __nv_bfloat16* ga_h = Ahp + (long)(m0 + tid) * lda;
    const __nv_bfloat16* ga_l = Alp + (long)(m0 + tid) * lda;
    const __nv_bfloat16* gb_h = Bhp + (long)(n0 + (tid & 127)) * ldb;
    const __nv_bfloat16* gb_l = Blp + (long)(n0 + (tid & 127)) * ldb;

    int nk = K / 32;
    g4_load(sbase, 0, ga_h, ga_l, gb_h, gb_l, 0, tid);
    g4_load(sbase, 1, ga_h, ga_l, gb_h, gb_l, 32, tid);

    for (int kc = 0; kc < nk; ++kc) {
        if (kc + 1 < nk) asm volatile("cp.async.wait_group 1;");
        else             asm volatile("cp.async.wait_group 0;");
        __syncthreads();

        const uint8_t* sA = smem + (kc % NSTG) * STG;
        const uint8_t* sBh_ = sA + 40960;
        #pragma unroll
        for (int ks = 0; ks < 2; ++ks) {
            int cb = ks * 32 + tig * 4;
            uint32_t ah[4][4], al2[4][4];
            #pragma unroll
            for (int mt = 0; mt < 4; ++mt) {
                const uint8_t* p = sA + (wm + mt * 16 + g) * 80 + cb;
                ah[mt][0] = *(const uint32_t*)(p);
                ah[mt][1] = *(const uint32_t*)(p + 8 * 80);
                ah[mt][2] = *(const uint32_t*)(p + 16);
                ah[mt][3] = *(const uint32_t*)(p + 8 * 80 + 16);
                const uint8_t* q_ = p + 20480;
                al2[mt][0] = *(const uint32_t*)(q_);
                al2[mt][1] = *(const uint32_t*)(q_ + 8 * 80);
                al2[mt][2] = *(const uint32_t*)(q_ + 16);
                al2[mt][3] = *(const uint32_t*)(q_ + 8 * 80 + 16);
            }
            #pragma unroll
            for (int nt = 0; nt < 8; ++nt) {
                const uint8_t* pb = sBh_ + (wn + nt * 8 + g) * 80 + cb;
                uint32_t bh0 = *(const uint32_t*)(pb);
                uint32_t bh1 = *(const uint32_t*)(pb + 16);
                uint32_t bl0 = *(const uint32_t*)(pb + 10240);
                uint32_t bl1 = *(const uint32_t*)(pb + 10240 + 16);
                #pragma unroll
                for (int mt = 0; mt < 4; ++mt) {
                    MMA16816(acc[mt][nt], ah[mt], bh0, bh1);   // hi*hi
                    MMA16816(acc[mt][nt], al2[mt], bh0, bh1);  // lo*hi
                    MMA16816(acc[mt][nt], ah[mt], bl0, bl1);   // hi*lo
                }
            }
        }
        __syncthreads();
        if (kc + 2 < nk)
            g4_load(sbase, (kc + 2) % NSTG, ga_h, ga_l, gb_h, gb_l, (kc + 2) * 32, tid);
    }

    // epilogue
    float* Cfp = nullptr;
    __nv_bfloat16 *Chp = nullptr, *Clp = nullptr;
    if (OUTMODE == 0) Cfp = Cf + zb * sC_b + zh_ * sC_h;
    else { Chp = Ch + zb * sC_b + zh_ * sC_h; Clp = Cl + zb * sC_b + zh_ * sC_h; }
    const float* bias = biasb ? biasb + (long)zh_ * sBias_h : nullptr;

    #pragma unroll
    for (int nt = 0; nt < 8; ++nt) {
        int col = n0 + wn + nt * 8 + tig * 2;
        float bb0 = 0.f, bb1 = 0.f;
        if (bias) { bb0 = bias[col]; bb1 = bias[col + 1]; }
        #pragma unroll
        for (int mt = 0; mt < 4; ++mt) {
            int r0 = m0 + wm + mt * 16 + g;
            float v00 = acc[mt][nt][0] * alpha + bb0;
            float v01 = acc[mt][nt][1] * alpha + bb1;
            float v10 = acc[mt][nt][2] * alpha + bb0;
            float v11 = acc[mt][nt][3] * alpha + bb1;
            if (TANH) { v00 = tanhf(v00); v01 = tanhf(v01); v10 = tanhf(v10); v11 = tanhf(v11); }
            if (OUTMODE == 0) {
                *(float2*)(Cfp + (long)r0 * ldc + col) = make_float2(v00, v01);
                *(float2*)(Cfp + (long)(r0 + 8) * ldc + col) = make_float2(v10, v11);
            } else {
                __nv_bfloat16 h0, l0, h1, l1;
                f2hilo(v00, h0, l0); f2hilo(v01, h1, l1);
                __nv_bfloat162 hh; hh.x = h0; hh.y = h1;
                __nv_bfloat162 ll; ll.x = l0; ll.y = l1;
                *(__nv_bfloat162*)(Chp + (long)r0 * ldc + col) = hh;
                *(__nv_bfloat162*)(Clp + (long)r0 * ldc + col) = ll;
                f2hilo(v10, h0, l0); f2hilo(v11, h1, l1);
                hh.x = h0; hh.y = h1; ll.x = l0; ll.y = l1;
                *(__nv_bfloat162*)(Chp + (long)(r0 + 8) * ldc + col) = hh;
                *(__nv_bfloat162*)(Clp + (long)(r0 + 8) * ldc + col) = ll;
            }
        }
    }
}

// ---------------- softmax over the QUERY axis, hi/lo output ----------------
__global__ void softmax_q_hilo(const float* __restrict__ Sc,
                               __nv_bfloat16* __restrict__ oh,
                               __nv_bfloat16* __restrict__ ol) {
    long base = (long)blockIdx.x * CS * CS;
    const float* p = Sc + base;
    int t = threadIdx.x;
    float m = -1e30f, l = 0.f;
    for (int s = 0; s < CS; ++s) {
        float x = p[(long)s * CS + t];
        float nm = fmaxf(m, x);
        l = l * __expf(m - nm) + __expf(x - nm);
        m = nm;
    }
    float inv = 1.f / l;
    for (int s = 0; s < CS; ++s) {
        float e = __expf(p[(long)s * CS + t] - m) * inv;
        __nv_bfloat16 h, lo;
        f2hilo(e, h, lo);
        oh[base + (long)s * CS + t] = h;
        ol[base + (long)s * CS + t] = lo;
    }
}

// ---------------- batch-norm over batch axis, fused residual add ----------
template<bool HILO>
__global__ void bn_kernel(const float* __restrict__ x,
                          const float* __restrict__ add, int addw,
                          float* __restrict__ out,
                          __nv_bfloat16* __restrict__ oh,
                          __nv_bfloat16* __restrict__ ol) {
    int j = blockIdx.x * blockDim.x + threadIdx.x;
    if (j >= CS * CD2) return;
    const long SD = (long)CS * CD2;
    int s = j >> 10;
    int e = j & 1023;
    int ae = e & (addw - 1);
    long aoff = (long)s * addw + ae;

    float v[CB];
    float sum = 0.f;
    #pragma unroll
    for (int b = 0; b < CB; ++b) {
        float t = x[(long)b * SD + j] + add[(long)b * CS * addw + aoff];
        v[b] = t;
        sum += t;
    }
    float mean = sum * (1.f / CB);
    float var = 0.f;
    #pragma unroll
    for (int b = 0; b < CB; ++b) {
        float d = v[b] - mean;
        var += d * d;
    }
    var *= (1.f / CB);
    float rstd = rsqrtf(var + 1e-3f);
    #pragma unroll
    for (int b = 0; b < CB; ++b) {
        float o = (v[b] - mean) * rstd;
        out[(long)b * SD + j] = o;
        if (HILO) {
            __nv_bfloat16 h, l;
            f2hilo(o, h, l);
            oh[(long)b * SD + j] = h;
            ol[(long)b * SD + j] = l;
        }
    }
}

// ---------------- host orchestration ----------------
struct Ptrs {
    float* f32;
    __nv_bfloat16* hb;
};

static void run_attn(int Din,
                     const __nv_bfloat16* xh, const __nv_bfloat16* xl,
                     const __nv_bfloat16* WqTh, const __nv_bfloat16* WqTl,
                     const __nv_bfloat16* WkTh, const __nv_bfloat16* WkTl,
                     const __nv_bfloat16* WvTh, const __nv_bfloat16* WvTl,
                     const float* bq, const float* bk, const float* bv,
                     const __nv_bfloat16* WoTh, const __nv_bfloat16* WoTl,
                     const float* bo, Ptrs p, float* aout)
{
    float* v  = p.f32 + OF_V;
    float* sc = p.f32 + OF_SC;
    __nv_bfloat16 *qh = p.hb + HB_QH, *ql = p.hb + HB_QL;
    __nv_bfloat16 *kh = p.hb + HB_KH, *kl = p.hb + HB_KL;
    __nv_bfloat16 *vth = p.hb + HB_VTH, *vtl = p.hb + HB_VTL;
    __nv_bfloat16 *ath = p.hb + HB_ATH, *atl = p.hb + HB_ATL;
    __nv_bfloat16 *zh = p.hb + HB_ZH, *zl = p.hb + HB_ZL;

    long sAb = (long)CS * Din, sBh = (long)CDK * Din;
    long sCb = (long)CH * CS * CDK, sCh = (long)CS * CDK;
    dim3 gq(1, CS / 256, CB * CH);
    gemm4<1, false><<<gq, 256, G4SMEM>>>(xh, xl, WqTh, WqTl, bq, nullptr, qh, ql,
        Din, Din, Din, CDK, CH, sAb, 0, 0, sBh, sCb, sCh, CDK, 1.f);
    gemm4<1, false><<<gq, 256, G4SMEM>>>(xh, xl, WkTh, WkTl, bk, nullptr, kh, kl,
        Din, Din, Din, CDK, CH, sAb, 0, 0, sBh, sCb, sCh, CDK, 1.f);
    gemm4<0, false><<<gq, 256, G4SMEM>>>(xh, xl, WvTh, WvTl, bv, v, nullptr, nullptr,
        Din, Din, Din, CDK, CH, sAb, 0, 0, sBh, sCb, sCh, CDK, 1.f);

    transpose_hilo<<<dim3(CDK / 32, CS / 32, CB * CH), dim3(32, 8)>>>(v, vth, vtl, CS, CDK);

    gemm4<0, false><<<dim3(CS / 128, CS / 256, CB * CH), 256, G4SMEM>>>(
        qh, ql, kh, kl, nullptr, sc, nullptr, nullptr,
        CDK, CDK, CDK, CS, 1,
        (long)CS * CDK, 0, (long)CS * CDK, 0, (long)CS * CS, 0, 0,
        0.08838834764831845f);

    softmax_q_hilo<<<CB * CH, CS>>>(sc, ath, atl);

    gemm4<1, false><<<dim3(1, CS / 256, CB * CH), 256, G4SMEM>>>(
        ath, atl, vth, vtl, nullptr, nullptr, zh, zl,
        CS, CS, CS, CHD, CH,
        (long)CH * CS * CS, (long)CS * CS,
        (long)CH * CDK * CS, (long)CDK * CS,
        (long)CS * CHD, CDK, 0, 1.f);

    gemm4<0, false><<<dim3(CD2 / 128, (CB * CS) / 256, 1), 256, G4SMEM>>>(
        zh, zl, WoTh, WoTl, bo, aout, nullptr, nullptr,
        CHD, CHD, CHD, CD2, 1, 0, 0, 0, 0, 0, 0, 0, 1.f);
}

extern "C" void kernel_launch(void* const* d_in, const int* in_sizes, int n_in,
                              void* d_out, int out_size)
{
    const float* X    = (const float*)d_in[0];
    const float* Wq1  = (const float*)d_in[1];
    const float* Wk1  = (const float*)d_in[2];
    const float* Wv1  = (const float*)d_in[3];
    const float* bq1  = (const float*)d_in[4];
    const float* bk1  = (const float*)d_in[5];
    const float* bv1  = (const float*)d_in[6];
    const float* Wo1  = (const float*)d_in[7];
    const float* bo1  = (const float*)d_in[8];
    const float* Wff1 = (const float*)d_in[9];
    const float* bff1 = (const float*)d_in[10];
    const float* Wq2  = (const float*)d_in[11];
    const float* Wk2  = (const float*)d_in[12];
    const float* Wv2  = (const float*)d_in[13];
    const float* bq2  = (const float*)d_in[14];
    const float* bk2  = (const float*)d_in[15];
    const float* bv2  = (const float*)d_in[16];
    const float* Wo2  = (const float*)d_in[17];
    const float* bo2  = (const float*)d_in[18];
    const float* Wff2 = (const float*)d_in[19];
    const float* bff2 = (const float*)d_in[20];
    float* out = (float*)d_out;

    float* sb = nullptr;
    cudaGetSymbolAddress((void**)&sb, g_scratch);
    Ptrs p;
    p.f32 = sb;
    p.hb = (__nv_bfloat16*)(sb + F32_END);

    cudaFuncSetAttribute(gemm4<0, false>, cudaFuncAttributeMaxDynamicSharedMemorySize, G4SMEM);
    cudaFuncSetAttribute(gemm4<0, true>,  cudaFuncAttributeMaxDynamicSharedMemorySize, G4SMEM);
    cudaFuncSetAttribute(gemm4<1, false>, cudaFuncAttributeMaxDynamicSharedMemorySize, G4SMEM);

    // ----- weight transpose + hi/lo convert -----
    dim3 tb(32, 8);
    transpose_hilo<<<dim3(CDK/32, CE/32, CH),   tb>>>(Wq1, p.hb+HB_W1QH, p.hb+HB_W1QL, CE,  CDK);
    transpose_hilo<<<dim3(CDK/32, CE/32, CH),   tb>>>(Wk1, p.hb+HB_W1KH, p.hb+HB_W1KL, CE,  CDK);
    transpose_hilo<<<dim3(CDK/32, CE/32, CH),   tb>>>(Wv1, p.hb+HB_W1VH, p.hb+HB_W1VL, CE,  CDK);
    transpose_hilo<<<dim3(CD2/32, CHD/32, 1),   tb>>>(Wo1, p.hb+HB_W1OH, p.hb+HB_W1OL, CHD, CD2);
    transpose_hilo<<<dim3(CD2/32, CD2/32, 1),   tb>>>(Wff1,p.hb+HB_W1FH, p.hb+HB_W1FL, CD2, CD2);
    transpose_hilo<<<dim3(CDK/32, CD2/32, CH),  tb>>>(Wq2, p.hb+HB_W2QH, p.hb+HB_W2QL, CD2, CDK);
    transpose_hilo<<<dim3(CDK/32, CD2/32, CH),  tb>>>(Wk2, p.hb+HB_W2KH, p.hb+HB_W2KL, CD2, CDK);
    transpose_hilo<<<dim3(CDK/32, CD2/32, CH),  tb>>>(Wv2, p.hb+HB_W2VH, p.hb+HB_W2VL, CD2, CDK);
    transpose_hilo<<<dim3(CD2/32, CHD/32, 1),   tb>>>(Wo2, p.hb+HB_W2OH, p.hb+HB_W2OL, CHD, CD2);
    transpose_hilo<<<dim3(CD2/32, CD2/32, 1),   tb>>>(Wff2,p.hb+HB_W2FH, p.hb+HB_W2FL, CD2, CD2);

    // ----- positional encoding -----
    float* pos = sb + OF_POS;
    float* xp  = sb + OF_XP;
    posgen_kernel<<<(CS * CE + 255) / 256, 256>>>(pos);
    addpos_hilo<<<(unsigned)((NB_XP + 255) / 256), 256>>>(X, pos, xp,
        p.hb + HB_XPH, p.hb + HB_XPL, NB_XP);

    float* a  = sb + OF_A;
    float* n1 = sb + OF_N1;
    float* n2 = sb + OF_N2;
    float* n3 = sb + OF_N3;
    float* f  = sb + OF_F;
    int nbn = (CS * CD2 + 255) / 256;
    dim3 gff(CD2 / 128, (CB * CS) / 256, 1);

    // ----- block 1: attention (Din = 512) -----
    run_attn(CE, p.hb + HB_XPH, p.hb + HB_XPL,
             p.hb+HB_W1QH, p.hb+HB_W1QL, p.hb+HB_W1KH, p.hb+HB_W1KL,
             p.hb+HB_W1VH, p.hb+HB_W1VL, bq1, bk1, bv1,
             p.hb+HB_W1OH, p.hb+HB_W1OL, bo1, p, a);
    bn_kernel<true><<<nbn, 256>>>(a, xp, CE, n1, p.hb + HB_N1H, p.hb + HB_N1L);

    // ----- block 2: FFN -----
    gemm4<0, true><<<gff, 256, G4SMEM>>>(
        p.hb + HB_N1H, p.hb + HB_N1L, p.hb + HB_W1FH, p.hb + HB_W1FL, bff1,
        f, nullptr, nullptr, CD2, CD2, CD2, CD2, 1, 0, 0, 0, 0, 0, 0, 0, 1.f);
    bn_kernel<true><<<nbn, 256>>>(f, n1, CD2, n2, p.hb + HB_N2H, p.hb + HB_N2L);

    // ----- block 3: attention (Din = 1024) -----
    run_attn(CD2, p.hb + HB_N2H, p.hb + HB_N2L,
             p.hb+HB_W2QH, p.hb+HB_W2QL, p.hb+HB_W2KH, p.hb+HB_W2KL,
             p.hb+HB_W2VH, p.hb+HB_W2VL, bq2, bk2, bv2,
             p.hb+HB_W2OH, p.hb+HB_W2OL, bo2, p, a);
    bn_kernel<true><<<nbn, 256>>>(a, n2, CD2, n3, p.hb + HB_N3H, p.hb + HB_N3L);

    // ----- block 4: FFN -----
    gemm4<0, true><<<gff, 256, G4SMEM>>>(
        p.hb + HB_N3H, p.hb + HB_N3L, p.hb + HB_W2FH, p.hb + HB_W2FL, bff2,
        f, nullptr, nullptr, CD2, CD2, CD2, CD2, 1, 0, 0, 0, 0, 0, 0, 0, 1.f);
    bn_kernel<false><<<nbn, 256>>>(f, n3, CD2, out, nullptr, nullptr);
}

// round 6
// speedup vs baseline: 1.0192x; 1.0192x over previous
#include <cuda_runtime.h>
#include <cuda_bf16.h>
#include <cstdint>
#include <math.h>

#define CB 32
#define CS 512
#define CE 512
#define CDK 128
#define CH 6
#define CD2 1024
#define CHD 768

// ---------------- sizes (elements) ----------------
constexpr long NB_XP  = (long)CB*CS*CE;
constexpr long NB_QKV = (long)CB*CH*CS*CDK;
constexpr long NB_SC  = (long)CB*CH*CS*CS;
constexpr long NB_Z   = (long)CB*CS*CHD;
constexpr long NB_D2  = (long)CB*CS*CD2;
constexpr long NW_QKV1 = (long)CH*CE*CDK;
constexpr long NW_QKV2 = (long)CH*CD2*CDK;
constexpr long NW_O   = (long)CHD*CD2;
constexpr long NW_F   = (long)CD2*CD2;

// ---------------- f32 scratch offsets ----------------
constexpr long OF_POS = 0;
constexpr long OF_XP  = OF_POS + (long)CS*CE;
constexpr long OF_V   = OF_XP + NB_XP;
constexpr long OF_SC  = OF_V + NB_QKV;
constexpr long OF_A   = OF_SC + NB_SC;
constexpr long OF_N1  = OF_A + NB_D2;
constexpr long OF_N2  = OF_N1 + NB_D2;
constexpr long OF_N3  = OF_N2 + NB_D2;
constexpr long OF_F   = OF_N3 + NB_D2;
constexpr long F32_END = OF_F + NB_D2;

// ---------------- bf16 scratch offsets ----------------
constexpr long HB_XPH = 0;
constexpr long HB_XPL = HB_XPH + NB_XP;
constexpr long HB_QH  = HB_XPL + NB_XP;
constexpr long HB_QL  = HB_QH + NB_QKV;
constexpr long HB_KH  = HB_QL + NB_QKV;
constexpr long HB_KL  = HB_KH + NB_QKV;
constexpr long HB_VTH = HB_KL + NB_QKV;
constexpr long HB_VTL = HB_VTH + NB_QKV;
constexpr long HB_ATH = HB_VTL + NB_QKV;
constexpr long HB_ATL = HB_ATH + NB_SC;
constexpr long HB_ZH  = HB_ATL + NB_SC;
constexpr long HB_ZL  = HB_ZH + NB_Z;
constexpr long HB_N1H = HB_ZL + NB_Z;
constexpr long HB_N1L = HB_N1H + NB_D2;
constexpr long HB_N2H = HB_N1L + NB_D2;
constexpr long HB_N2L = HB_N2H + NB_D2;
constexpr long HB_N3H = HB_N2L + NB_D2;
constexpr long HB_N3L = HB_N3H + NB_D2;
constexpr long HB_W1QH = HB_N3L + NB_D2;
constexpr long HB_W1QL = HB_W1QH + NW_QKV1;
constexpr long HB_W1KH = HB_W1QL + NW_QKV1;
constexpr long HB_W1KL = HB_W1KH + NW_QKV1;
constexpr long HB_W1VH = HB_W1KL + NW_QKV1;
constexpr long HB_W1VL = HB_W1VH + NW_QKV1;
constexpr long HB_W1OH = HB_W1VL + NW_QKV1;
constexpr long HB_W1OL = HB_W1OH + NW_O;
constexpr long HB_W1FH = HB_W1OL + NW_O;
constexpr long HB_W1FL = HB_W1FH + NW_F;
constexpr long HB_W2QH = HB_W1FL + NW_F;
constexpr long HB_W2QL = HB_W2QH + NW_QKV2;
constexpr long HB_W2KH = HB_W2QL + NW_QKV2;
constexpr long HB_W2KL = HB_W2KH + NW_QKV2;
constexpr long HB_W2VH = HB_W2KL + NW_QKV2;
constexpr long HB_W2VL = HB_W2VH + NW_QKV2;
constexpr long HB_W2OH = HB_W2VL + NW_QKV2;
constexpr long HB_W2OL = HB_W2OH + NW_O;
constexpr long HB_W2FH = HB_W2OL + NW_O;
constexpr long HB_W2FL = HB_W2FH + NW_F;
constexpr long HB_END  = HB_W2FL + NW_F;

constexpr long SCRATCH_TOT = F32_END + (HB_END + 1) / 2 + 64;
__device__ float g_scratch[SCRATCH_TOT];

// ---------------- helpers ----------------
__device__ __forceinline__ void f2hilo(float v, __nv_bfloat16& h, __nv_bfloat16& l) {
    h = __float2bfloat16(v);
    l = __float2bfloat16(v - __bfloat162float(h));
}

__device__ __forceinline__ void cp16(uint32_t d, const void* s) {
    asm volatile("cp.async.cg.shared.global [%0], [%1], 16;\n" :: "r"(d), "l"(s));
}

#define MMA16816(c, a, b0, b1)                                              \
    asm volatile("mma.sync.aligned.m16n8k16.row.col.f32.bf16.bf16.f32 "     \
                 "{%0,%1,%2,%3},{%4,%5,%6,%7},{%8,%9},{%0,%1,%2,%3};"       \
                 : "+f"((c)[0]), "+f"((c)[1]), "+f"((c)[2]), "+f"((c)[3])   \
                 : "r"((a)[0]), "r"((a)[1]), "r"((a)[2]), "r"((a)[3]),      \
                   "r"(b0), "r"(b1))

// ---------------- positional encoding ----------------
__global__ void posgen_kernel(float* __restrict__ pos) {
    int idx = blockIdx.x * blockDim.x + threadIdx.x;
    if (idx >= CS * CE) return;
    int s = idx >> 9;
    int e = idx & 511;
    int m = e >> 1;
    double ang = (m >= 128) ? ((double)s / 10000.0) : (double)s;
    pos[idx] = (e & 1) ? (float)cos(ang) : (float)sin(ang);
}

__global__ void addpos_hilo(const float* __restrict__ X,
                            const float* __restrict__ pos,
                            float* __restrict__ xp,
                            __nv_bfloat16* __restrict__ xh,
                            __nv_bfloat16* __restrict__ xl, long n) {
    long idx = (long)blockIdx.x * blockDim.x + threadIdx.x;
    if (idx >= n) return;
    float v = X[idx] + pos[idx % (CS * CE)];
    xp[idx] = v;
    f2hilo(v, xh[idx], xl[idx]);
}

// ---------------- transpose + hi/lo convert ----------------
__global__ void transpose_hilo(const float* __restrict__ in,
                               __nv_bfloat16* __restrict__ oh,
                               __nv_bfloat16* __restrict__ ol,
                               int R, int C) {
    __shared__ float t[32][33];
    long zo = (long)blockIdx.z * R * C;
    int c0 = blockIdx.x * 32, r0 = blockIdx.y * 32;
    int tx = threadIdx.x, ty = threadIdx.y;
    #pragma unroll
    for (int i = 0; i < 32; i += 8)
        t[ty + i][tx] = in[zo + (long)(r0 + ty + i) * C + c0 + tx];
    __syncthreads();
    #pragma unroll
    for (int i = 0; i < 32; i += 8) {
        float v = t[tx][ty + i];
        long o = zo + (long)(c0 + ty + i) * R + r0 + tx;
        __nv_bfloat16 h, l;
        f2hilo(v, h, l);
        oh[o] = h; ol[o] = l;
    }
}

// ---------------- 3xBF16 tensor-core GEMM ----------------
// C = alpha * A @ B^T(+bias)(+tanh). A: [M][K] hi/lo bf16. B: [N][K] hi/lo bf16.
// CTA 128x128, BK=32, 4 warps (each 64x64), double-buffered cp.async.
// MMA schedule: nt-pairs, hh x8 / lh x8 / hl x8 -> same-acc distance 8 (hides HMMA latency).
#define GSMEM 81920   // 2 stages * 4 tiles * 128 rows * 80B

template<int OUTMODE, bool TANH>
__global__ void __launch_bounds__(128, 2) gemm3(
    const __nv_bfloat16* __restrict__ Ah, const __nv_bfloat16* __restrict__ Al,
    const __nv_bfloat16* __restrict__ Bh, const __nv_bfloat16* __restrict__ Bl,
    const float* __restrict__ biasb,
    float* __restrict__ Cf,
    __nv_bfloat16* __restrict__ Ch, __nv_bfloat16* __restrict__ Cl,
    int K, int lda, int ldb, int ldc, int Hdiv,
    long sA_b, long sA_h, long sB_b, long sB_h,
    long sC_b, long sC_h, long sBias_h, float alpha)
{
    extern __shared__ uint8_t smem[];
    int z = blockIdx.z, zb = z / Hdiv, zh_ = z - zb * Hdiv;
    const __nv_bfloat16* Ahp = Ah + zb * sA_b + zh_ * sA_h;
    const __nv_bfloat16* Alp = Al + zb * sA_b + zh_ * sA_h;
    const __nv_bfloat16* Bhp = Bh + zb * sB_b + zh_ * sB_h;
    const __nv_bfloat16* Blp = Bl + zb * sB_b + zh_ * sB_h;
    int m0 = blockIdx.y * 128, n0 = blockIdx.x * 128;
    int tid = threadIdx.x;
    int wid = tid >> 5, lane = tid & 31;
    int g = lane >> 2, tig = lane & 3;
    int wm = (wid & 1) * 64, wn = (wid >> 1) * 64;

    uint32_t sbase = (uint32_t)__cvta_generic_to_shared(smem);

    float acc[4][8][4];
    #pragma unroll
    for (int i = 0; i < 4; ++i)
        #pragma unroll
        for (int j = 0; j < 8; ++j)
            #pragma unroll
            for (int q = 0; q < 4; ++q) acc[i][j][q] = 0.f;

    const __nv_bfloat16* ga_h = Ahp + (long)(m0 + tid) * lda;
    const __nv_bfloat16* ga_l = Alp + (long)(m0 + tid) * lda;
    const __nv_bfloat16* gb_h = Bhp + (long)(n0 + tid) * ldb;
    const __nv_bfloat16* gb_l = Blp + (long)(n0 + tid) * ldb;

    int nk = K / 32;
    {
        uint32_t d = sbase + tid * 80;
        #pragma unroll
        for (int c = 0; c < 4; ++c) {
            cp16(d + c * 16,         ga_h + c * 8);
            cp16(d + 10240 + c * 16, ga_l + c * 8);
            cp16(d + 20480 + c * 16, gb_h + c * 8);
            cp16(d + 30720 + c * 16, gb_l + c * 8);
        }
        asm volatile("cp.async.commit_group;");
    }

    for (int kc = 0; kc < nk; ++kc) {
        if (kc + 1 < nk) {
            int k0 = (kc + 1) * 32;
            uint32_t d = sbase + ((kc + 1) & 1) * 40960 + tid * 80;
            #pragma unroll
            for (int c = 0; c < 4; ++c) {
                cp16(d + c * 16,         ga_h + k0 + c * 8);
                cp16(d + 10240 + c * 16, ga_l + k0 + c * 8);
                cp16(d + 20480 + c * 16, gb_h + k0 + c * 8);
                cp16(d + 30720 + c * 16, gb_l + k0 + c * 8);
            }
            asm volatile("cp.async.commit_group;");
            asm volatile("cp.async.wait_group 1;");
        } else {
            asm volatile("cp.async.wait_group 0;");
        }
        __syncthreads();

        const uint8_t* sb_ = smem + (kc & 1) * 40960;
        #pragma unroll
        for (int ks = 0; ks < 2; ++ks) {
            int cb = ks * 32 + tig * 4;
            uint32_t ah[4][4], al2[4][4];
            #pragma unroll
            for (int mt = 0; mt < 4; ++mt) {
                const uint8_t* p = sb_ + (wm + mt * 16 + g) * 80 + cb;
                ah[mt][0] = *(const uint32_t*)(p);
                ah[mt][1] = *(const uint32_t*)(p + 8 * 80);
                ah[mt][2] = *(const uint32_t*)(p + 16);
                ah[mt][3] = *(const uint32_t*)(p + 8 * 80 + 16);
                const uint8_t* q_ = p + 10240;
                al2[mt][0] = *(const uint32_t*)(q_);
                al2[mt][1] = *(const uint32_t*)(q_ + 8 * 80);
                al2[mt][2] = *(const uint32_t*)(q_ + 16);
                al2[mt][3] = *(const uint32_t*)(q_ + 8 * 80 + 16);
            }
            #pragma unroll
            for (int ntp = 0; ntp < 4; ++ntp) {
                uint32_t bh0[2], bh1[2], bl0[2], bl1[2];
                #pragma unroll
                for (int u = 0; u < 2; ++u) {
                    int nt = ntp * 2 + u;
                    const uint8_t* pb = sb_ + 20480 + (wn + nt * 8 + g) * 80 + cb;
                    bh0[u] = *(const uint32_t*)(pb);
                    bh1[u] = *(const uint32_t*)(pb + 16);
                    bl0[u] = *(const uint32_t*)(pb + 10240);
                    bl1[u] = *(const uint32_t*)(pb + 10240 + 16);
                }
                // hh for 8 distinct accumulators
                #pragma unroll
                for (int u = 0; u < 2; ++u)
                    #pragma unroll
                    for (int mt = 0; mt < 4; ++mt)
                        MMA16816(acc[mt][ntp * 2 + u], ah[mt], bh0[u], bh1[u]);
                // lh
                #pragma unroll
                for (int u = 0; u < 2; ++u)
                    #pragma unroll
                    for (int mt = 0; mt < 4; ++mt)
                        MMA16816(acc[mt][ntp * 2 + u], al2[mt], bh0[u], bh1[u]);
                // hl
                #pragma unroll
                for (int u = 0; u < 2; ++u)
                    #pragma unroll
                    for (int mt = 0; mt < 4; ++mt)
                        MMA16816(acc[mt][ntp * 2 + u], ah[mt], bl0[u], bl1[u]);
            }
        }
        __syncthreads();
    }

    // epilogue
    float* Cfp = nullptr;
    __nv_bfloat16 *Chp = nullptr, *Clp = nullptr;
    if (OUTMODE == 0) Cfp = Cf + zb * sC_b + zh_ * sC_h;
    else { Chp = Ch + zb * sC_b + zh_ * sC_h; Clp = Cl + zb * sC_b + zh_ * sC_h; }
    const float* bias = biasb ? biasb + (long)zh_ * sBias_h : nullptr;

    #pragma unroll
    for (int nt = 0; nt < 8; ++nt) {
        int col = n0 + wn + nt * 8 + tig * 2;
        float bb0 = 0.f, bb1 = 0.f;
        if (bias) { bb0 = bias[col]; bb1 = bias[col + 1]; }
        #pragma unroll
        for (int mt = 0; mt < 4; ++mt) {
            int r0 = m0 + wm + mt * 16 + g;
            float v00 = acc[mt][nt][0] * alpha + bb0;
            float v01 = acc[mt][nt][1] * alpha + bb1;
            float v10 = acc[mt][nt][2] * alpha + bb0;
            float v11 = acc[mt][nt][3] * alpha + bb1;
            if (TANH) { v00 = tanhf(v00); v01 = tanhf(v01); v10 = tanhf(v10); v11 = tanhf(v11); }
            if (OUTMODE == 0) {
                *(float2*)(Cfp + (long)r0 * ldc + col) = make_float2(v00, v01);
                *(float2*)(Cfp + (long)(r0 + 8) * ldc + col) = make_float2(v10, v11);
            } else {
                __nv_bfloat16 h0, l0, h1, l1;
                f2hilo(v00, h0, l0); f2hilo(v01, h1, l1);
                __nv_bfloat162 hh; hh.x = h0; hh.y = h1;
                __nv_bfloat162 ll; ll.x = l0; ll.y = l1;
                *(__nv_bfloat162*)(Chp + (long)r0 * ldc + col) = hh;
                *(__nv_bfloat162*)(Clp + (long)r0 * ldc + col) = ll;
                f2hilo(v10, h0, l0); f2hilo(v11, h1, l1);
                hh.x = h0; hh.y = h1; ll.x = l0; ll.y = l1;
                *(__nv_bfloat162*)(Chp + (long)(r0 + 8) * ldc + col) = hh;
                *(__nv_bfloat162*)(Clp + (long)(r0 + 8) * ldc + col) = ll;
            }
        }
    }
}

// ---------------- softmax over the QUERY axis, hi/lo output ----------------
__global__ void softmax_q_hilo(const float* __restrict__ Sc,
                               __nv_bfloat16* __restrict__ oh,
                               __nv_bfloat16* __restrict__ ol) {
    long base = (long)blockIdx.x * CS * CS;
    const float* p = Sc + base;
    int t = threadIdx.x;
    float m = -1e30f, l = 0.f;
    for (int s = 0; s < CS; ++s) {
        float x = p[(long)s * CS + t];
        float nm = fmaxf(m, x);
        l = l * __expf(m - nm) + __expf(x - nm);
        m = nm;
    }
    float inv = 1.f / l;
    for (int s = 0; s < CS; ++s) {
        float e = __expf(p[(long)s * CS + t] - m) * inv;
        __nv_bfloat16 h, lo;
        f2hilo(e, h, lo);
        oh[base + (long)s * CS + t] = h;
        ol[base + (long)s * CS + t] = lo;
    }
}

// ---------------- batch-norm over batch axis, fused residual add ----------
template<bool HILO>
__global__ void bn_kernel(const float* __restrict__ x,
                          const float* __restrict__ add, int addw,
                          float* __restrict__ out,
                          __nv_bfloat16* __restrict__ oh,
                          __nv_bfloat16* __restrict__ ol) {
    int j = blockIdx.x * blockDim.x + threadIdx.x;
    if (j >= CS * CD2) return;
    const long SD = (long)CS * CD2;
    int s = j >> 10;
    int e = j & 1023;
    int ae = e & (addw - 1);
    long aoff = (long)s * addw + ae;

    float v[CB];
    float sum = 0.f;
    #pragma unroll
    for (int b = 0; b < CB; ++b) {
        float t = x[(long)b * SD + j] + add[(long)b * CS * addw + aoff];
        v[b] = t;
        sum += t;
    }
    float mean = sum * (1.f / CB);
    float var = 0.f;
    #pragma unroll
    for (int b = 0; b < CB; ++b) {
        float d = v[b] - mean;
        var += d * d;
    }
    var *= (1.f / CB);
    float rstd = rsqrtf(var + 1e-3f);
    #pragma unroll
    for (int b = 0; b < CB; ++b) {
        float o = (v[b] - mean) * rstd;
        out[(long)b * SD + j] = o;
        if (HILO) {
            __nv_bfloat16 h, l;
            f2hilo(o, h, l);
            oh[(long)b * SD + j] = h;
            ol[(long)b * SD + j] = l;
        }
    }
}

// ---------------- host orchestration ----------------
struct Ptrs {
    float* f32;
    __nv_bfloat16* hb;
};

static void run_attn(int Din,
                     const __nv_bfloat16* xh, const __nv_bfloat16* xl,
                     const __nv_bfloat16* WqTh, const __nv_bfloat16* WqTl,
                     const __nv_bfloat16* WkTh, const __nv_bfloat16* WkTl,
                     const __nv_bfloat16* WvTh, const __nv_bfloat16* WvTl,
                     const float* bq, const float* bk, const float* bv,
                     const __nv_bfloat16* WoTh, const __nv_bfloat16* WoTl,
                     const float* bo, Ptrs p, float* aout)
{
    float* v  = p.f32 + OF_V;
    float* sc = p.f32 + OF_SC;
    __nv_bfloat16 *qh = p.hb + HB_QH, *ql = p.hb + HB_QL;
    __nv_bfloat16 *kh = p.hb + HB_KH, *kl = p.hb + HB_KL;
    __nv_bfloat16 *vth = p.hb + HB_VTH, *vtl = p.hb + HB_VTL;
    __nv_bfloat16 *ath = p.hb + HB_ATH, *atl = p.hb + HB_ATL;
    __nv_bfloat16 *zh = p.hb + HB_ZH, *zl = p.hb + HB_ZL;

    long sAb = (long)CS * Din, sBh = (long)CDK * Din;
    long sCb = (long)CH * CS * CDK, sCh = (long)CS * CDK;
    dim3 gq(1, CS / 128, CB * CH);
    gemm3<1, false><<<gq, 128, GSMEM>>>(xh, xl, WqTh, WqTl, bq, nullptr, qh, ql,
        Din, Din, Din, CDK, CH, sAb, 0, 0, sBh, sCb, sCh, CDK, 1.f);
    gemm3<1, false><<<gq, 128, GSMEM>>>(xh, xl, WkTh, WkTl, bk, nullptr, kh, kl,
        Din, Din, Din, CDK, CH, sAb, 0, 0, sBh, sCb, sCh, CDK, 1.f);
    gemm3<0, false><<<gq, 128, GSMEM>>>(xh, xl, WvTh, WvTl, bv, v, nullptr, nullptr,
        Din, Din, Din, CDK, CH, sAb, 0, 0, sBh, sCb, sCh, CDK, 1.f);

    transpose_hilo<<<dim3(CDK / 32, CS / 32, CB * CH), dim3(32, 8)>>>(v, vth, vtl, CS, CDK);

    gemm3<0, false><<<dim3(CS / 128, CS / 128, CB * CH), 128, GSMEM>>>(
        qh, ql, kh, kl, nullptr, sc, nullptr, nullptr,
        CDK, CDK, CDK, CS, 1,
        (long)CS * CDK, 0, (long)CS * CDK, 0, (long)CS * CS, 0, 0,
        0.08838834764831845f);

    softmax_q_hilo<<<CB * CH, CS>>>(sc, ath, atl);

    gemm3<1, false><<<dim3(1, CS / 128, CB * CH), 128, GSMEM>>>(
        ath, atl, vth, vtl, nullptr, nullptr, zh, zl,
        CS, CS, CS, CHD, CH,
        (long)CH * CS * CS, (long)CS * CS,
        (long)CH * CDK * CS, (long)CDK * CS,
        (long)CS * CHD, CDK, 0, 1.f);

    gemm3<0, false><<<dim3(CD2 / 128, (CB * CS) / 128, 1), 128, GSMEM>>>(
        zh, zl, WoTh, WoTl, bo, aout, nullptr, nullptr,
        CHD, CHD, CHD, CD2, 1, 0, 0, 0, 0, 0, 0, 0, 1.f);
}

extern "C" void kernel_launch(void* const* d_in, const int* in_sizes, int n_in,
                              void* d_out, int out_size)
{
    const float* X    = (const float*)d_in[0];
    const float* Wq1  = (const float*)d_in[1];
    const float* Wk1  = (const float*)d_in[2];
    const float* Wv1  = (const float*)d_in[3];
    const float* bq1  = (const float*)d_in[4];
    const float* bk1  = (const float*)d_in[5];
    const float* bv1  = (const float*)d_in[6];
    const float* Wo1  = (const float*)d_in[7];
    const float* bo1  = (const float*)d_in[8];
    const float* Wff1 = (const float*)d_in[9];
    const float* bff1 = (const float*)d_in[10];
    const float* Wq2  = (const float*)d_in[11];
    const float* Wk2  = (const float*)d_in[12];
    const float* Wv2  = (const float*)d_in[13];
    const float* bq2  = (const float*)d_in[14];
    const float* bk2  = (const float*)d_in[15];
    const float* bv2  = (const float*)d_in[16];
    const float* Wo2  = (const float*)d_in[17];
    const float* bo2  = (const float*)d_in[18];
    const float* Wff2 = (const float*)d_in[19];
    const float* bff2 = (const float*)d_in[20];
    float* out = (float*)d_out;

    float* sb = nullptr;
    cudaGetSymbolAddress((void**)&sb, g_scratch);
    Ptrs p;
    p.f32 = sb;
    p.hb = (__nv_bfloat16*)(sb + F32_END);

    cudaFuncSetAttribute(gemm3<0, false>, cudaFuncAttributeMaxDynamicSharedMemorySize, GSMEM);
    cudaFuncSetAttribute(gemm3<0, true>,  cudaFuncAttributeMaxDynamicSharedMemorySize, GSMEM);
    cudaFuncSetAttribute(gemm3<1, false>, cudaFuncAttributeMaxDynamicSharedMemorySize, GSMEM);

    // ----- weight transpose + hi/lo convert -----
    dim3 tb(32, 8);
    transpose_hilo<<<dim3(CDK/32, CE/32, CH),   tb>>>(Wq1, p.hb+HB_W1QH, p.hb+HB_W1QL, CE,  CDK);
    transpose_hilo<<<dim3(CDK/32, CE/32, CH),   tb>>>(Wk1, p.hb+HB_W1KH, p.hb+HB_W1KL, CE,  CDK);
    transpose_hilo<<<dim3(CDK/32, CE/32, CH),   tb>>>(Wv1, p.hb+HB_W1VH, p.hb+HB_W1VL, CE,  CDK);
    transpose_hilo<<<dim3(CD2/32, CHD/32, 1),   tb>>>(Wo1, p.hb+HB_W1OH, p.hb+HB_W1OL, CHD, CD2);
    transpose_hilo<<<dim3(CD2/32, CD2/32, 1),   tb>>>(Wff1,p.hb+HB_W1FH, p.hb+HB_W1FL, CD2, CD2);
    transpose_hilo<<<dim3(CDK/32, CD2/32, CH),  tb>>>(Wq2, p.hb+HB_W2QH, p.hb+HB_W2QL, CD2, CDK);
    transpose_hilo<<<dim3(CDK/32, CD2/32, CH),  tb>>>(Wk2, p.hb+HB_W2KH, p.hb+HB_W2KL, CD2, CDK);
    transpose_hilo<<<dim3(CDK/32, CD2/32, CH),  tb>>>(Wv2, p.hb+HB_W2VH, p.hb+HB_W2VL, CD2, CDK);
    transpose_hilo<<<dim3(CD2/32, CHD/32, 1),   tb>>>(Wo2, p.hb+HB_W2OH, p.hb+HB_W2OL, CHD, CD2);
    transpose_hilo<<<dim3(CD2/32, CD2/32, 1),   tb>>>(Wff2,p.hb+HB_W2FH, p.hb+HB_W2FL, CD2, CD2);

    // ----- positional encoding -----
    float* pos = sb + OF_POS;
    float* xp  = sb + OF_XP;
    posgen_kernel<<<(CS * CE + 255) / 256, 256>>>(pos);
    addpos_hilo<<<(unsigned)((NB_XP + 255) / 256), 256>>>(X, pos, xp,
        p.hb + HB_XPH, p.hb + HB_XPL, NB_XP);

    float* a  = sb + OF_A;
    float* n1 = sb + OF_N1;
    float* n2 = sb + OF_N2;
    float* n3 = sb + OF_N3;
    float* f  = sb + OF_F;
    int nbn = (CS * CD2 + 255) / 256;
    dim3 gff(CD2 / 128, (CB * CS) / 128, 1);

    // ----- block 1: attention (Din = 512) -----
    run_attn(CE, p.hb + HB_XPH, p.hb + HB_XPL,
             p.hb+HB_W1QH, p.hb+HB_W1QL, p.hb+HB_W1KH, p.hb+HB_W1KL,
             p.hb+HB_W1VH, p.hb+HB_W1VL, bq1, bk1, bv1,
             p.hb+HB_W1OH, p.hb+HB_W1OL, bo1, p, a);
    bn_kernel<true><<<nbn, 256>>>(a, xp, CE, n1, p.hb + HB_N1H, p.hb + HB_N1L);

    // ----- block 2: FFN -----
    gemm3<0, true><<<gff, 128, GSMEM>>>(
        p.hb + HB_N1H, p.hb + HB_N1L, p.hb + HB_W1FH, p.hb + HB_W1FL, bff1,
        f, nullptr, nullptr, CD2, CD2, CD2, CD2, 1, 0, 0, 0, 0, 0, 0, 0, 1.f);
    bn_kernel<true><<<nbn, 256>>>(f, n1, CD2, n2, p.hb + HB_N2H, p.hb + HB_N2L);

    // ----- block 3: attention (Din = 1024) -----
    run_attn(CD2, p.hb + HB_N2H, p.hb + HB_N2L,
             p.hb+HB_W2QH, p.hb+HB_W2QL, p.hb+HB_W2KH, p.hb+HB_W2KL,
             p.hb+HB_W2VH, p.hb+HB_W2VL, bq2, bk2, bv2,
             p.hb+HB_W2OH, p.hb+HB_W2OL, bo2, p, a);
    bn_kernel<true><<<nbn, 256>>>(a, n2, CD2, n3, p.hb + HB_N3H, p.hb + HB_N3L);

    // ----- block 4: FFN -----
    gemm3<0, true><<<gff, 128, GSMEM>>>(
        p.hb + HB_N3H, p.hb + HB_N3L, p.hb + HB_W2FH, p.hb + HB_W2FL, bff2,
        f, nullptr, nullptr, CD2, CD2, CD2, CD2, 1, 0, 0, 0, 0, 0, 0, 0, 1.f);
    bn_kernel<false><<<nbn, 256>>>(f, n3, CD2, out, nullptr, nullptr);
}

// round 7
// speedup vs baseline: 1.3306x; 1.3055x over previous
#include <cuda_runtime.h>
#include <cuda_fp16.h>
#include <cstdint>
#include <math.h>

#define CB 32
#define CS 512
#define CE 512
#define CDK 128
#define CH 6
#define CD2 1024
#define CHD 768

// ---------------- sizes (elements) ----------------
constexpr long NB_XP  = (long)CB*CS*CE;
constexpr long NB_QKV = (long)CB*CH*CS*CDK;
constexpr long NB_SC  = (long)CB*CH*CS*CS;
constexpr long NB_Z   = (long)CB*CS*CHD;
constexpr long NB_D2  = (long)CB*CS*CD2;
constexpr long NW_QKV1 = (long)CH*CE*CDK;
constexpr long NW_QKV2 = (long)CH*CD2*CDK;
constexpr long NW_O   = (long)CHD*CD2;
constexpr long NW_F   = (long)CD2*CD2;

// ---------------- f32 scratch offsets ----------------
constexpr long OF_POS = 0;
constexpr long OF_XP  = OF_POS + (long)CS*CE;
constexpr long OF_V   = OF_XP + NB_XP;
constexpr long OF_SC  = OF_V + NB_QKV;
constexpr long OF_A   = OF_SC + NB_SC;
constexpr long OF_N1  = OF_A + NB_D2;
constexpr long OF_N2  = OF_N1 + NB_D2;
constexpr long OF_N3  = OF_N2 + NB_D2;
constexpr long OF_F   = OF_N3 + NB_D2;
constexpr long F32_END = OF_F + NB_D2;

// ---------------- fp16 scratch offsets (half elems) ----------------
constexpr long HB_XPH = 0;
constexpr long HB_XPL = HB_XPH + NB_XP;
constexpr long HB_QH  = HB_XPL + NB_XP;
constexpr long HB_QL  = HB_QH + NB_QKV;
constexpr long HB_KH  = HB_QL + NB_QKV;      // K: hi only (B side)
constexpr long HB_VTH = HB_KH + NB_QKV;      // V^T: hi only (B side)
constexpr long HB_ATH = HB_VTH + NB_QKV;
constexpr long HB_ATL = HB_ATH + NB_SC;
constexpr long HB_ZH  = HB_ATL + NB_SC;
constexpr long HB_ZL  = HB_ZH + NB_Z;
constexpr long HB_N1H = HB_ZL + NB_Z;
constexpr long HB_N1L = HB_N1H + NB_D2;
constexpr long HB_N2H = HB_N1L + NB_D2;
constexpr long HB_N2L = HB_N2H + NB_D2;
constexpr long HB_N3H = HB_N2L + NB_D2;
constexpr long HB_N3L = HB_N3H + NB_D2;
// weights: hi only (all are B-side)
constexpr long HB_W1Q = HB_N3L + NB_D2;
constexpr long HB_W1K = HB_W1Q + NW_QKV1;
constexpr long HB_W1V = HB_W1K + NW_QKV1;
constexpr long HB_W1O = HB_W1V + NW_QKV1;
constexpr long HB_W1F = HB_W1O + NW_O;
constexpr long HB_W2Q = HB_W1F + NW_F;
constexpr long HB_W2K = HB_W2Q + NW_QKV2;
constexpr long HB_W2V = HB_W2K + NW_QKV2;
constexpr long HB_W2O = HB_W2V + NW_QKV2;
constexpr long HB_W2F = HB_W2O + NW_O;
constexpr long HB_END = HB_W2F + NW_F;

constexpr long SCRATCH_TOT = F32_END + (HB_END + 1) / 2 + 64;
__device__ float g_scratch[SCRATCH_TOT];

// ---------------- helpers ----------------
__device__ __forceinline__ void f2hilo(float v, __half& h, __half& l) {
    h = __float2half(v);
    l = __float2half(v - __half2float(h));
}

__device__ __forceinline__ void cp16(uint32_t d, const void* s) {
    asm volatile("cp.async.cg.shared.global [%0], [%1], 16;\n" :: "r"(d), "l"(s));
}

#define MMA16816(c, a, b0, b1)                                              \
    asm volatile("mma.sync.aligned.m16n8k16.row.col.f32.f16.f16.f32 "       \
                 "{%0,%1,%2,%3},{%4,%5,%6,%7},{%8,%9},{%0,%1,%2,%3};"       \
                 : "+f"((c)[0]), "+f"((c)[1]), "+f"((c)[2]), "+f"((c)[3])   \
                 : "r"((a)[0]), "r"((a)[1]), "r"((a)[2]), "r"((a)[3]),      \
                   "r"(b0), "r"(b1))

// ---------------- positional encoding ----------------
__global__ void posgen_kernel(float* __restrict__ pos) {
    int idx = blockIdx.x * blockDim.x + threadIdx.x;
    if (idx >= CS * CE) return;
    int s = idx >> 9;
    int e = idx & 511;
    int m = e >> 1;
    double ang = (m >= 128) ? ((double)s / 10000.0) : (double)s;
    pos[idx] = (e & 1) ? (float)cos(ang) : (float)sin(ang);
}

__global__ void addpos_hilo(const float* __restrict__ X,
                            const float* __restrict__ pos,
                            float* __restrict__ xp,
                            __half* __restrict__ xh,
                            __half* __restrict__ xl, long n) {
    long idx = (long)blockIdx.x * blockDim.x + threadIdx.x;
    if (idx >= n) return;
    float v = X[idx] + pos[idx % (CS * CE)];
    xp[idx] = v;
    f2hilo(v, xh[idx], xl[idx]);
}

// ---------------- transpose + hi-only convert (B-side operands) ----------
__global__ void transpose_hi(const float* __restrict__ in,
                             __half* __restrict__ oh,
                             int R, int C) {
    __shared__ float t[32][33];
    long zo = (long)blockIdx.z * R * C;
    int c0 = blockIdx.x * 32, r0 = blockIdx.y * 32;
    int tx = threadIdx.x, ty = threadIdx.y;
    #pragma unroll
    for (int i = 0; i < 32; i += 8)
        t[ty + i][tx] = in[zo + (long)(r0 + ty + i) * C + c0 + tx];
    __syncthreads();
    #pragma unroll
    for (int i = 0; i < 32; i += 8) {
        float v = t[tx][ty + i];
        long o = zo + (long)(c0 + ty + i) * R + r0 + tx;
        oh[o] = __float2half(v);
    }
}

// ---------------- 2xFP16 tensor-core GEMM ----------------
// C = alpha * (A_hi + A_lo) @ B_hi^T (+bias)(+tanh).
// A: [M][K] hi/lo fp16, B: [N][K] hi fp16. CTA 128x128, BK=32, 4 warps,
// double-buffered cp.async. OUTMODE: 0=f32, 1=fp16 hi+lo, 2=fp16 hi only.
#define STGB 30720          // Ah 10240 | Al 10240 | Bh 10240 (80B-pitch rows)
#define GSMEM (2 * STGB)    // 61440

template<int OUTMODE, bool TANH>
__global__ void __launch_bounds__(128, 2) gemm3(
    const __half* __restrict__ Ah, const __half* __restrict__ Al,
    const __half* __restrict__ Bh,
    const float* __restrict__ biasb,
    float* __restrict__ Cf,
    __half* __restrict__ Ch, __half* __restrict__ Cl,
    int K, int lda, int ldb, int ldc, int Hdiv,
    long sA_b, long sA_h, long sB_b, long sB_h,
    long sC_b, long sC_h, long sBias_h, float alpha)
{
    extern __shared__ uint8_t smem[];
    int z = blockIdx.z, zb = z / Hdiv, zh_ = z - zb * Hdiv;
    const __half* Ahp = Ah + zb * sA_b + zh_ * sA_h;
    const __half* Alp = Al + zb * sA_b + zh_ * sA_h;
    const __half* Bhp = Bh + zb * sB_b + zh_ * sB_h;
    int m0 = blockIdx.y * 128, n0 = blockIdx.x * 128;
    int tid = threadIdx.x;
    int wid = tid >> 5, lane = tid & 31;
    int g = lane >> 2, tig = lane & 3;
    int wm = (wid & 1) * 64, wn = (wid >> 1) * 64;

    uint32_t sbase = (uint32_t)__cvta_generic_to_shared(smem);

    float acc[4][8][4];
    #pragma unroll
    for (int i = 0; i < 4; ++i)
        #pragma unroll
        for (int j = 0; j < 8; ++j)
            #pragma unroll
            for (int q = 0; q < 4; ++q) acc[i][j][q] = 0.f;

    const __half* ga_h = Ahp + (long)(m0 + tid) * lda;
    const __half* ga_l = Alp + (long)(m0 + tid) * lda;
    const __half* gb_h = Bhp + (long)(n0 + tid) * ldb;

    int nk = K / 32;
    {
        uint32_t d = sbase + tid * 80;
        #pragma unroll
        for (int c = 0; c < 4; ++c) {
            cp16(d + c * 16,         ga_h + c * 8);
            cp16(d + 10240 + c * 16, ga_l + c * 8);
            cp16(d + 20480 + c * 16, gb_h + c * 8);
        }
        asm volatile("cp.async.commit_group;");
    }

    for (int kc = 0; kc < nk; ++kc) {
        if (kc + 1 < nk) {
            int k0 = (kc + 1) * 32;
            uint32_t d = sbase + ((kc + 1) & 1) * STGB + tid * 80;
            #pragma unroll
            for (int c = 0; c < 4; ++c) {
                cp16(d + c * 16,         ga_h + k0 + c * 8);
                cp16(d + 10240 + c * 16, ga_l + k0 + c * 8);
                cp16(d + 20480 + c * 16, gb_h + k0 + c * 8);
            }
            asm volatile("cp.async.commit_group;");
            asm volatile("cp.async.wait_group 1;");
        } else {
            asm volatile("cp.async.wait_group 0;");
        }
        __syncthreads();

        const uint8_t* sb_ = smem + (kc & 1) * STGB;
        #pragma unroll
        for (int ks = 0; ks < 2; ++ks) {
            int cb = ks * 32 + tig * 4;
            uint32_t ah[4][4], al2[4][4];
            #pragma unroll
            for (int mt = 0; mt < 4; ++mt) {
                const uint8_t* p = sb_ + (wm + mt * 16 + g) * 80 + cb;
                ah[mt][0] = *(const uint32_t*)(p);
                ah[mt][1] = *(const uint32_t*)(p + 8 * 80);
                ah[mt][2] = *(const uint32_t*)(p + 16);
                ah[mt][3] = *(const uint32_t*)(p + 8 * 80 + 16);
                const uint8_t* q_ = p + 10240;
                al2[mt][0] = *(const uint32_t*)(q_);
                al2[mt][1] = *(const uint32_t*)(q_ + 8 * 80);
                al2[mt][2] = *(const uint32_t*)(q_ + 16);
                al2[mt][3] = *(const uint32_t*)(q_ + 8 * 80 + 16);
            }
            #pragma unroll
            for (int ntp = 0; ntp < 4; ++ntp) {
                uint32_t bh0[2], bh1[2];
                #pragma unroll
                for (int u = 0; u < 2; ++u) {
                    int nt = ntp * 2 + u;
                    const uint8_t* pb = sb_ + 20480 + (wn + nt * 8 + g) * 80 + cb;
                    bh0[u] = *(const uint32_t*)(pb);
                    bh1[u] = *(const uint32_t*)(pb + 16);
                }
                // hh for 8 distinct accumulators
                #pragma unroll
                for (int u = 0; u < 2; ++u)
                    #pragma unroll
                    for (int mt = 0; mt < 4; ++mt)
                        MMA16816(acc[mt][ntp * 2 + u], ah[mt], bh0[u], bh1[u]);
                // lh
                #pragma unroll
                for (int u = 0; u < 2; ++u)
                    #pragma unroll
                    for (int mt = 0; mt < 4; ++mt)
                        MMA16816(acc[mt][ntp * 2 + u], al2[mt], bh0[u], bh1[u]);
            }
        }
        __syncthreads();
    }

    // epilogue
    float* Cfp = nullptr;
    __half *Chp = nullptr, *Clp = nullptr;
    if (OUTMODE == 0) Cfp = Cf + zb * sC_b + zh_ * sC_h;
    else { Chp = Ch + zb * sC_b + zh_ * sC_h; if (OUTMODE == 1) Clp = Cl + zb * sC_b + zh_ * sC_h; }
    const float* bias = biasb ? biasb + (long)zh_ * sBias_h : nullptr;

    #pragma unroll
    for (int nt = 0; nt < 8; ++nt) {
        int col = n0 + wn + nt * 8 + tig * 2;
        float bb0 = 0.f, bb1 = 0.f;
        if (bias) { bb0 = bias[col]; bb1 = bias[col + 1]; }
        #pragma unroll
        for (int mt = 0; mt < 4; ++mt) {
            int r0 = m0 + wm + mt * 16 + g;
            float v00 = acc[mt][nt][0] * alpha + bb0;
            float v01 = acc[mt][nt][1] * alpha + bb1;
            float v10 = acc[mt][nt][2] * alpha + bb0;
            float v11 = acc[mt][nt][3] * alpha + bb1;
            if (TANH) { v00 = tanhf(v00); v01 = tanhf(v01); v10 = tanhf(v10); v11 = tanhf(v11); }
            if (OUTMODE == 0) {
                *(float2*)(Cfp + (long)r0 * ldc + col) = make_float2(v00, v01);
                *(float2*)(Cfp + (long)(r0 + 8) * ldc + col) = make_float2(v10, v11);
            } else if (OUTMODE == 2) {
                __half2 hh;
                hh.x = __float2half(v00); hh.y = __float2half(v01);
                *(__half2*)(Chp + (long)r0 * ldc + col) = hh;
                hh.x = __float2half(v10); hh.y = __float2half(v11);
                *(__half2*)(Chp + (long)(r0 + 8) * ldc + col) = hh;
            } else {
                __half h0, l0, h1, l1;
                f2hilo(v00, h0, l0); f2hilo(v01, h1, l1);
                __half2 hh; hh.x = h0; hh.y = h1;
                __half2 ll; ll.x = l0; ll.y = l1;
                *(__half2*)(Chp + (long)r0 * ldc + col) = hh;
                *(__half2*)(Clp + (long)r0 * ldc + col) = ll;
                f2hilo(v10, h0, l0); f2hilo(v11, h1, l1);
                hh.x = h0; hh.y = h1; ll.x = l0; ll.y = l1;
                *(__half2*)(Chp + (long)(r0 + 8) * ldc + col) = hh;
                *(__half2*)(Clp + (long)(r0 + 8) * ldc + col) = ll;
            }
        }
    }
}

// ---------------- softmax over the QUERY axis, hi/lo output ----------------
__global__ void softmax_q_hilo(const float* __restrict__ Sc,
                               __half* __restrict__ oh,
                               __half* __restrict__ ol) {
    long base = (long)blockIdx.x * CS * CS;
    const float* p = Sc + base;
    int t = threadIdx.x;
    float m = -1e30f, l = 0.f;
    for (int s = 0; s < CS; ++s) {
        float x = p[(long)s * CS + t];
        float nm = fmaxf(m, x);
        l = l * __expf(m - nm) + __expf(x - nm);
        m = nm;
    }
    float inv = 1.f / l;
    for (int s = 0; s < CS; ++s) {
        float e = __expf(p[(long)s * CS + t] - m) * inv;
        __half h, lo;
        f2hilo(e, h, lo);
        oh[base + (long)s * CS + t] = h;
        ol[base + (long)s * CS + t] = lo;
    }
}

// ---------------- batch-norm over batch axis, fused residual add ----------
template<bool HILO>
__global__ void bn_kernel(const float* __restrict__ x,
                          const float* __restrict__ add, int addw,
                          float* __restrict__ out,
                          __half* __restrict__ oh,
                          __half* __restrict__ ol) {
    int j = blockIdx.x * blockDim.x + threadIdx.x;
    if (j >= CS * CD2) return;
    const long SD = (long)CS * CD2;
    int s = j >> 10;
    int e = j & 1023;
    int ae = e & (addw - 1);
    long aoff = (long)s * addw + ae;

    float v[CB];
    float sum = 0.f;
    #pragma unroll
    for (int b = 0; b < CB; ++b) {
        float t = x[(long)b * SD + j] + add[(long)b * CS * addw + aoff];
        v[b] = t;
        sum += t;
    }
    float mean = sum * (1.f / CB);
    float var = 0.f;
    #pragma unroll
    for (int b = 0; b < CB; ++b) {
        float d = v[b] - mean;
        var += d * d;
    }
    var *= (1.f / CB);
    float rstd = rsqrtf(var + 1e-3f);
    #pragma unroll
    for (int b = 0; b < CB; ++b) {
        float o = (v[b] - mean) * rstd;
        out[(long)b * SD + j] = o;
        if (HILO) {
            __half h, l;
            f2hilo(o, h, l);
            oh[(long)b * SD + j] = h;
            ol[(long)b * SD + j] = l;
        }
    }
}

// ---------------- host orchestration ----------------
struct Ptrs {
    float* f32;
    __half* hb;
};

static void run_attn(int Din,
                     const __half* xh, const __half* xl,
                     const __half* WqT, const __half* WkT, const __half* WvT,
                     const float* bq, const float* bk, const float* bv,
                     const __half* WoT, const float* bo, Ptrs p, float* aout)
{
    float* v  = p.f32 + OF_V;
    float* sc = p.f32 + OF_SC;
    __half *qh = p.hb + HB_QH, *ql = p.hb + HB_QL;
    __half *kh = p.hb + HB_KH;
    __half *vth = p.hb + HB_VTH;
    __half *ath = p.hb + HB_ATH, *atl = p.hb + HB_ATL;
    __half *zh = p.hb + HB_ZH, *zl = p.hb + HB_ZL;

    long sAb = (long)CS * Din, sBh = (long)CDK * Din;
    long sCb = (long)CH * CS * CDK, sCh = (long)CS * CDK;
    dim3 gq(1, CS / 128, CB * CH);
    // Q: hi/lo (A of scores). K: hi only (B of scores). V: f32 (for transpose).
    gemm3<1, false><<<gq, 128, GSMEM>>>(xh, xl, WqT, bq, nullptr, qh, ql,
        Din, Din, Din, CDK, CH, sAb, 0, 0, sBh, sCb, sCh, CDK, 1.f);
    gemm3<2, false><<<gq, 128, GSMEM>>>(xh, xl, WkT, bk, nullptr, kh, nullptr,
        Din, Din, Din, CDK, CH, sAb, 0, 0, sBh, sCb, sCh, CDK, 1.f);
    gemm3<0, false><<<gq, 128, GSMEM>>>(xh, xl, WvT, bv, v, nullptr, nullptr,
        Din, Din, Din, CDK, CH, sAb, 0, 0, sBh, sCb, sCh, CDK, 1.f);

    // V transpose: [z][t][dk] -> [z][dk][t], hi only (B of AV)
    transpose_hi<<<dim3(CDK / 32, CS / 32, CB * CH), dim3(32, 8)>>>(v, vth, CS, CDK);

    // scores = Q @ K^T * 1/sqrt(dk)
    gemm3<0, false><<<dim3(CS / 128, CS / 128, CB * CH), 128, GSMEM>>>(
        qh, ql, kh, nullptr, sc, nullptr, nullptr,
        CDK, CDK, CDK, CS, 1,
        (long)CS * CDK, 0, (long)CS * CDK, 0, (long)CS * CS, 0, 0,
        0.08838834764831845f);

    softmax_q_hilo<<<CB * CH, CS>>>(sc, ath, atl);

    // z = attn @ V^T
    gemm3<1, false><<<dim3(1, CS / 128, CB * CH), 128, GSMEM>>>(
        ath, atl, vth, nullptr, nullptr, zh, zl,
        CS, CS, CS, CHD, CH,
        (long)CH * CS * CS, (long)CS * CS,
        (long)CH * CDK * CS, (long)CDK * CS,
        (long)CS * CHD, CDK, 0, 1.f);

    // out projection: (B*S,768) @ (768,1024)
    gemm3<0, false><<<dim3(CD2 / 128, (CB * CS) / 128, 1), 128, GSMEM>>>(
        zh, zl, WoT, bo, aout, nullptr, nullptr,
        CHD, CHD, CHD, CD2, 1, 0, 0, 0, 0, 0, 0, 0, 1.f);
}

extern "C" void kernel_launch(void* const* d_in, const int* in_sizes, int n_in,
                              void* d_out, int out_size)
{
    const float* X    = (const float*)d_in[0];
    const float* Wq1  = (const float*)d_in[1];
    const float* Wk1  = (const float*)d_in[2];
    const float* Wv1  = (const float*)d_in[3];
    const float* bq1  = (const float*)d_in[4];
    const float* bk1  = (const float*)d_in[5];
    const float* bv1  = (const float*)d_in[6];
    const float* Wo1  = (const float*)d_in[7];
    const float* bo1  = (const float*)d_in[8];
    const float* Wff1 = (const float*)d_in[9];
    const float* bff1 = (const float*)d_in[10];
    const float* Wq2  = (const float*)d_in[11];
    const float* Wk2  = (const float*)d_in[12];
    const float* Wv2  = (const float*)d_in[13];
    const float* bq2  = (const float*)d_in[14];
    const float* bk2  = (const float*)d_in[15];
    const float* bv2  = (const float*)d_in[16];
    const float* Wo2  = (const float*)d_in[17];
    const float* bo2  = (const float*)d_in[18];
    const float* Wff2 = (const float*)d_in[19];
    const float* bff2 = (const float*)d_in[20];
    float* out = (float*)d_out;

    float* sb = nullptr;
    cudaGetSymbolAddress((void**)&sb, g_scratch);
    Ptrs p;
    p.f32 = sb;
    p.hb = (__half*)(sb + F32_END);

    cudaFuncSetAttribute(gemm3<0, false>, cudaFuncAttributeMaxDynamicSharedMemorySize, GSMEM);
    cudaFuncSetAttribute(gemm3<0, true>,  cudaFuncAttributeMaxDynamicSharedMemorySize, GSMEM);
    cudaFuncSetAttribute(gemm3<1, false>, cudaFuncAttributeMaxDynamicSharedMemorySize, GSMEM);
    cudaFuncSetAttribute(gemm3<2, false>, cudaFuncAttributeMaxDynamicSharedMemorySize, GSMEM);

    // ----- weight transpose + hi convert (weights are B-side: hi only) -----
    dim3 tb(32, 8);
    transpose_hi<<<dim3(CDK/32, CE/32, CH),   tb>>>(Wq1, p.hb+HB_W1Q, CE,  CDK);
    transpose_hi<<<dim3(CDK/32, CE/32, CH),   tb>>>(Wk1, p.hb+HB_W1K, CE,  CDK);
    transpose_hi<<<dim3(CDK/32, CE/32, CH),   tb>>>(Wv1, p.hb+HB_W1V, CE,  CDK);
    transpose_hi<<<dim3(CD2/32, CHD/32, 1),   tb>>>(Wo1, p.hb+HB_W1O, CHD, CD2);
    transpose_hi<<<dim3(CD2/32, CD2/32, 1),   tb>>>(Wff1,p.hb+HB_W1F, CD2, CD2);
    transpose_hi<<<dim3(CDK/32, CD2/32, CH),  tb>>>(Wq2, p.hb+HB_W2Q, CD2, CDK);
    transpose_hi<<<dim3(CDK/32, CD2/32, CH),  tb>>>(Wk2, p.hb+HB_W2K, CD2, CDK);
    transpose_hi<<<dim3(CDK/32, CD2/32, CH),  tb>>>(Wv2, p.hb+HB_W2V, CD2, CDK);
    transpose_hi<<<dim3(CD2/32, CHD/32, 1),   tb>>>(Wo2, p.hb+HB_W2O, CHD, CD2);
    transpose_hi<<<dim3(CD2/32, CD2/32, 1),   tb>>>(Wff2,p.hb+HB_W2F, CD2, CD2);

    // ----- positional encoding -----
    float* pos = sb + OF_POS;
    float* xp  = sb + OF_XP;
    posgen_kernel<<<(CS * CE + 255) / 256, 256>>>(pos);
    addpos_hilo<<<(unsigned)((NB_XP + 255) / 256), 256>>>(X, pos, xp,
        p.hb + HB_XPH, p.hb + HB_XPL, NB_XP);

    float* a  = sb + OF_A;
    float* n1 = sb + OF_N1;
    float* n2 = sb + OF_N2;
    float* n3 = sb + OF_N3;
    float* f  = sb + OF_F;
    int nbn = (CS * CD2 + 255) / 256;
    dim3 gff(CD2 / 128, (CB * CS) / 128, 1);

    // ----- block 1: attention (Din = 512) -----
    run_attn(CE, p.hb + HB_XPH, p.hb + HB_XPL,
             p.hb+HB_W1Q, p.hb+HB_W1K, p.hb+HB_W1V, bq1, bk1, bv1,
             p.hb+HB_W1O, bo1, p, a);
    bn_kernel<true><<<nbn, 256>>>(a, xp, CE, n1, p.hb + HB_N1H, p.hb + HB_N1L);

    // ----- block 2: FFN -----
    gemm3<0, true><<<gff, 128, GSMEM>>>(
        p.hb + HB_N1H, p.hb + HB_N1L, p.hb + HB_W1F, bff1,
        f, nullptr, nullptr, CD2, CD2, CD2, CD2, 1, 0, 0, 0, 0, 0, 0, 0, 1.f);
    bn_kernel<true><<<nbn, 256>>>(f, n1, CD2, n2, p.hb + HB_N2H, p.hb + HB_N2L);

    // ----- block 3: attention (Din = 1024) -----
    run_attn(CD2, p.hb + HB_N2H, p.hb + HB_N2L,
             p.hb+HB_W2Q, p.hb+HB_W2K, p.hb+HB_W2V, bq2, bk2, bv2,
             p.hb+HB_W2O, bo2, p, a);
    bn_kernel<true><<<nbn, 256>>>(a, n2, CD2, n3, p.hb + HB_N3H, p.hb + HB_N3L);

    // ----- block 4: FFN -----
    gemm3<0, true><<<gff, 128, GSMEM>>>(
        p.hb + HB_N3H, p.hb + HB_N3L, p.hb + HB_W2F, bff2,
        f, nullptr, nullptr, CD2, CD2, CD2, CD2, 1, 0, 0, 0, 0, 0, 0, 0, 1.f);
    bn_kernel<false><<<nbn, 256>>>(f, n3, CD2, out, nullptr, nullptr);
}

// round 8
// speedup vs baseline: 1.5835x; 1.1900x over previous
#include <cuda_runtime.h>
#include <cuda_fp16.h>
#include <cstdint>
#include <math.h>

#define CB 32
#define CS 512
#define CE 512
#define CDK 128
#define CH 6
#define CD2 1024
#define CHD 768

// ---------------- sizes (elements) ----------------
constexpr long NB_XP  = (long)CB*CS*CE;
constexpr long NB_QKV = (long)CB*CH*CS*CDK;
constexpr long NB_SC  = (long)CB*CH*CS*CS;
constexpr long NB_Z   = (long)CB*CS*CHD;
constexpr long NB_D2  = (long)CB*CS*CD2;
constexpr long NW_QKV1 = (long)CH*CE*CDK;
constexpr long NW_QKV2 = (long)CH*CD2*CDK;
constexpr long NW_O   = (long)CHD*CD2;
constexpr long NW_F   = (long)CD2*CD2;

// ---------------- f32 scratch offsets ----------------
constexpr long OF_POS = 0;
constexpr long OF_XP  = OF_POS + (long)CS*CE;
constexpr long OF_V   = OF_XP + NB_XP;
constexpr long OF_SC  = OF_V + NB_QKV;
constexpr long OF_A   = OF_SC + NB_SC;
constexpr long OF_N1  = OF_A + NB_D2;
constexpr long OF_N2  = OF_N1 + NB_D2;
constexpr long OF_N3  = OF_N2 + NB_D2;
constexpr long OF_F   = OF_N3 + NB_D2;
constexpr long F32_END = OF_F + NB_D2;

// ---------------- fp16 scratch offsets (half elems) ----------------
constexpr long HB_XPH = 0;
constexpr long HB_XPL = HB_XPH + NB_XP;
constexpr long HB_QH  = HB_XPL + NB_XP;
constexpr long HB_QL  = HB_QH + NB_QKV;
constexpr long HB_KH  = HB_QL + NB_QKV;      // K: hi only (B side)
constexpr long HB_VTH = HB_KH + NB_QKV;      // V^T: hi only (B side)
constexpr long HB_ATH = HB_VTH + NB_QKV;
constexpr long HB_ATL = HB_ATH + NB_SC;
constexpr long HB_ZH  = HB_ATL + NB_SC;      // z: hi only (outproj A 1-pass)
constexpr long HB_N1H = HB_ZH + NB_Z;        // n1: hi only (FFN1 A 1-pass)
constexpr long HB_N2H = HB_N1H + NB_D2;
constexpr long HB_N2L = HB_N2H + NB_D2;
constexpr long HB_N3H = HB_N2L + NB_D2;      // n3: hi only (FFN2 A 1-pass)
// weights: hi only (all are B-side)
constexpr long HB_W1Q = HB_N3H + NB_D2;
constexpr long HB_W1K = HB_W1Q + NW_QKV1;
constexpr long HB_W1V = HB_W1K + NW_QKV1;
constexpr long HB_W1O = HB_W1V + NW_QKV1;
constexpr long HB_W1F = HB_W1O + NW_O;
constexpr long HB_W2Q = HB_W1F + NW_F;
constexpr long HB_W2K = HB_W2Q + NW_QKV2;
constexpr long HB_W2V = HB_W2K + NW_QKV2;
constexpr long HB_W2O = HB_W2V + NW_QKV2;
constexpr long HB_W2F = HB_W2O + NW_O;
constexpr long HB_END = HB_W2F + NW_F;

constexpr long SCRATCH_TOT = F32_END + (HB_END + 1) / 2 + 64;
__device__ float g_scratch[SCRATCH_TOT];

// ---------------- helpers ----------------
__device__ __forceinline__ void f2hilo(float v, __half& h, __half& l) {
    h = __float2half(v);
    l = __float2half(v - __half2float(h));
}

__device__ __forceinline__ void cp16(uint32_t d, const void* s) {
    asm volatile("cp.async.cg.shared.global [%0], [%1], 16;\n" :: "r"(d), "l"(s));
}

#define MMA16816(c, a, b0, b1)                                              \
    asm volatile("mma.sync.aligned.m16n8k16.row.col.f32.f16.f16.f32 "       \
                 "{%0,%1,%2,%3},{%4,%5,%6,%7},{%8,%9},{%0,%1,%2,%3};"       \
                 : "+f"((c)[0]), "+f"((c)[1]), "+f"((c)[2]), "+f"((c)[3])   \
                 : "r"((a)[0]), "r"((a)[1]), "r"((a)[2]), "r"((a)[3]),      \
                   "r"(b0), "r"(b1))

// ---------------- positional encoding ----------------
__global__ void posgen_kernel(float* __restrict__ pos) {
    int idx = blockIdx.x * blockDim.x + threadIdx.x;
    if (idx >= CS * CE) return;
    int s = idx >> 9;
    int e = idx & 511;
    int m = e >> 1;
    double ang = (m >= 128) ? ((double)s / 10000.0) : (double)s;
    pos[idx] = (e & 1) ? (float)cos(ang) : (float)sin(ang);
}

__global__ void addpos_hilo(const float* __restrict__ X,
                            const float* __restrict__ pos,
                            float* __restrict__ xp,
                            __half* __restrict__ xh,
                            __half* __restrict__ xl, long n) {
    long idx = (long)blockIdx.x * blockDim.x + threadIdx.x;
    if (idx >= n) return;
    float v = X[idx] + pos[idx % (CS * CE)];
    xp[idx] = v;
    f2hilo(v, xh[idx], xl[idx]);
}

// ---------------- transpose + hi-only convert (B-side operands) ----------
__global__ void transpose_hi(const float* __restrict__ in,
                             __half* __restrict__ oh,
                             int R, int C) {
    __shared__ float t[32][33];
    long zo = (long)blockIdx.z * R * C;
    int c0 = blockIdx.x * 32, r0 = blockIdx.y * 32;
    int tx = threadIdx.x, ty = threadIdx.y;
    #pragma unroll
    for (int i = 0; i < 32; i += 8)
        t[ty + i][tx] = in[zo + (long)(r0 + ty + i) * C + c0 + tx];
    __syncthreads();
    #pragma unroll
    for (int i = 0; i < 32; i += 8) {
        float v = t[tx][ty + i];
        long o = zo + (long)(c0 + ty + i) * R + r0 + tx;
        oh[o] = __float2half(v);
    }
}

// ---------------- fp16 tensor-core GEMM ----------------
// C = alpha * (A_hi [+ A_lo]) @ B_hi^T (+bias)(+tanh).
// TWOPASS: include the A_lo correction pass.
// OUTMODE: 0=f32, 1=fp16 hi+lo, 2=fp16 hi only.
#define STGB 30720          // Ah 10240 | Al 10240 | Bh 10240 (80B-pitch rows)
#define GSMEM (2 * STGB)    // 61440

template<int OUTMODE, bool TANH, bool TWOPASS>
__global__ void __launch_bounds__(128, 2) gemm3(
    const __half* __restrict__ Ah, const __half* __restrict__ Al,
    const __half* __restrict__ Bh,
    const float* __restrict__ biasb,
    float* __restrict__ Cf,
    __half* __restrict__ Ch, __half* __restrict__ Cl,
    int K, int lda, int ldb, int ldc, int Hdiv,
    long sA_b, long sA_h, long sB_b, long sB_h,
    long sC_b, long sC_h, long sBias_h, float alpha)
{
    extern __shared__ uint8_t smem[];
    int z = blockIdx.z, zb = z / Hdiv, zh_ = z - zb * Hdiv;
    const __half* Ahp = Ah + zb * sA_b + zh_ * sA_h;
    const __half* Alp = TWOPASS ? (Al + zb * sA_b + zh_ * sA_h) : nullptr;
    const __half* Bhp = Bh + zb * sB_b + zh_ * sB_h;
    int m0 = blockIdx.y * 128, n0 = blockIdx.x * 128;
    int tid = threadIdx.x;
    int wid = tid >> 5, lane = tid & 31;
    int g = lane >> 2, tig = lane & 3;
    int wm = (wid & 1) * 64, wn = (wid >> 1) * 64;

    uint32_t sbase = (uint32_t)__cvta_generic_to_shared(smem);

    float acc[4][8][4];
    #pragma unroll
    for (int i = 0; i < 4; ++i)
        #pragma unroll
        for (int j = 0; j < 8; ++j)
            #pragma unroll
            for (int q = 0; q < 4; ++q) acc[i][j][q] = 0.f;

    const __half* ga_h = Ahp + (long)(m0 + tid) * lda;
    const __half* ga_l = TWOPASS ? (Alp + (long)(m0 + tid) * lda) : nullptr;
    const __half* gb_h = Bhp + (long)(n0 + tid) * ldb;

    int nk = K / 32;
    {
        uint32_t d = sbase + tid * 80;
        #pragma unroll
        for (int c = 0; c < 4; ++c) {
            cp16(d + c * 16,         ga_h + c * 8);
            if (TWOPASS) cp16(d + 10240 + c * 16, ga_l + c * 8);
            cp16(d + 20480 + c * 16, gb_h + c * 8);
        }
        asm volatile("cp.async.commit_group;");
    }

    for (int kc = 0; kc < nk; ++kc) {
        if (kc + 1 < nk) {
            int k0 = (kc + 1) * 32;
            uint32_t d = sbase + ((kc + 1) & 1) * STGB + tid * 80;
            #pragma unroll
            for (int c = 0; c < 4; ++c) {
                cp16(d + c * 16,         ga_h + k0 + c * 8);
                if (TWOPASS) cp16(d + 10240 + c * 16, ga_l + k0 + c * 8);
                cp16(d + 20480 + c * 16, gb_h + k0 + c * 8);
            }
            asm volatile("cp.async.commit_group;");
            asm volatile("cp.async.wait_group 1;");
        } else {
            asm volatile("cp.async.wait_group 0;");
        }
        __syncthreads();

        const uint8_t* sb_ = smem + (kc & 1) * STGB;
        #pragma unroll
        for (int ks = 0; ks < 2; ++ks) {
            int cb = ks * 32 + tig * 4;
            uint32_t ah[4][4], al2[4][4];
            #pragma unroll
            for (int mt = 0; mt < 4; ++mt) {
                const uint8_t* p = sb_ + (wm + mt * 16 + g) * 80 + cb;
                ah[mt][0] = *(const uint32_t*)(p);
                ah[mt][1] = *(const uint32_t*)(p + 8 * 80);
                ah[mt][2] = *(const uint32_t*)(p + 16);
                ah[mt][3] = *(const uint32_t*)(p + 8 * 80 + 16);
                if (TWOPASS) {
                    const uint8_t* q_ = p + 10240;
                    al2[mt][0] = *(const uint32_t*)(q_);
                    al2[mt][1] = *(const uint32_t*)(q_ + 8 * 80);
                    al2[mt][2] = *(const uint32_t*)(q_ + 16);
                    al2[mt][3] = *(const uint32_t*)(q_ + 8 * 80 + 16);
                }
            }
            #pragma unroll
            for (int ntp = 0; ntp < 4; ++ntp) {
                uint32_t bh0[2], bh1[2];
                #pragma unroll
                for (int u = 0; u < 2; ++u) {
                    int nt = ntp * 2 + u;
                    const uint8_t* pb = sb_ + 20480 + (wn + nt * 8 + g) * 80 + cb;
                    bh0[u] = *(const uint32_t*)(pb);
                    bh1[u] = *(const uint32_t*)(pb + 16);
                }
                #pragma unroll
                for (int u = 0; u < 2; ++u)
                    #pragma unroll
                    for (int mt = 0; mt < 4; ++mt)
                        MMA16816(acc[mt][ntp * 2 + u], ah[mt], bh0[u], bh1[u]);
                if (TWOPASS) {
                    #pragma unroll
                    for (int u = 0; u < 2; ++u)
                        #pragma unroll
                        for (int mt = 0; mt < 4; ++mt)
                            MMA16816(acc[mt][ntp * 2 + u], al2[mt], bh0[u], bh1[u]);
                }
            }
        }
        __syncthreads();
    }

    // epilogue
    float* Cfp = nullptr;
    __half *Chp = nullptr, *Clp = nullptr;
    if (OUTMODE == 0) Cfp = Cf + zb * sC_b + zh_ * sC_h;
    else { Chp = Ch + zb * sC_b + zh_ * sC_h; if (OUTMODE == 1) Clp = Cl + zb * sC_b + zh_ * sC_h; }
    const float* bias = biasb ? biasb + (long)zh_ * sBias_h : nullptr;

    #pragma unroll
    for (int nt = 0; nt < 8; ++nt) {
        int col = n0 + wn + nt * 8 + tig * 2;
        float bb0 = 0.f, bb1 = 0.f;
        if (bias) { bb0 = bias[col]; bb1 = bias[col + 1]; }
        #pragma unroll
        for (int mt = 0; mt < 4; ++mt) {
            int r0 = m0 + wm + mt * 16 + g;
            float v00 = acc[mt][nt][0] * alpha + bb0;
            float v01 = acc[mt][nt][1] * alpha + bb1;
            float v10 = acc[mt][nt][2] * alpha + bb0;
            float v11 = acc[mt][nt][3] * alpha + bb1;
            if (TANH) { v00 = tanhf(v00); v01 = tanhf(v01); v10 = tanhf(v10); v11 = tanhf(v11); }
            if (OUTMODE == 0) {
                *(float2*)(Cfp + (long)r0 * ldc + col) = make_float2(v00, v01);
                *(float2*)(Cfp + (long)(r0 + 8) * ldc + col) = make_float2(v10, v11);
            } else if (OUTMODE == 2) {
                __half2 hh;
                hh.x = __float2half(v00); hh.y = __float2half(v01);
                *(__half2*)(Chp + (long)r0 * ldc + col) = hh;
                hh.x = __float2half(v10); hh.y = __float2half(v11);
                *(__half2*)(Chp + (long)(r0 + 8) * ldc + col) = hh;
            } else {
                __half h0, l0, h1, l1;
                f2hilo(v00, h0, l0); f2hilo(v01, h1, l1);
                __half2 hh; hh.x = h0; hh.y = h1;
                __half2 ll; ll.x = l0; ll.y = l1;
                *(__half2*)(Chp + (long)r0 * ldc + col) = hh;
                *(__half2*)(Clp + (long)r0 * ldc + col) = ll;
                f2hilo(v10, h0, l0); f2hilo(v11, h1, l1);
                hh.x = h0; hh.y = h1; ll.x = l0; ll.y = l1;
                *(__half2*)(Chp + (long)(r0 + 8) * ldc + col) = hh;
                *(__half2*)(Clp + (long)(r0 + 8) * ldc + col) = ll;
            }
        }
    }
}

// ---------------- softmax over the QUERY axis (parallelized) ----------
// grid (CB*CH, CS/32); block 512 = 16 warps. Warp w owns rows [w*32, w*32+32)
// of a 512x32 column slab; values kept in registers; (m,l) combined in smem.
__global__ void __launch_bounds__(512) softmax_q2(const float* __restrict__ Sc,
                                                  __half* __restrict__ oh,
                                                  __half* __restrict__ ol) {
    __shared__ float sm[16][32], sl[16][32];
    long base = (long)blockIdx.x * CS * CS + blockIdx.y * 32;
    int w = threadIdx.x >> 5, lane = threadIdx.x & 31;
    const float* p = Sc + base + (long)w * 32 * CS + lane;
    float v[32];
    float m = -1e30f, l = 0.f;
    #pragma unroll
    for (int i = 0; i < 32; ++i) {
        float x = p[(long)i * CS];
        v[i] = x;
        float nm = fmaxf(m, x);
        l = l * __expf(m - nm) + __expf(x - nm);
        m = nm;
    }
    sm[w][lane] = m; sl[w][lane] = l;
    __syncthreads();
    float M = -1e30f;
    #pragma unroll
    for (int ww = 0; ww < 16; ++ww) M = fmaxf(M, sm[ww][lane]);
    float L = 0.f;
    #pragma unroll
    for (int ww = 0; ww < 16; ++ww) L += sl[ww][lane] * __expf(sm[ww][lane] - M);
    float inv = 1.f / L;
    __half* po = oh + base + (long)w * 32 * CS + lane;
    __half* pl = ol + base + (long)w * 32 * CS + lane;
    #pragma unroll
    for (int i = 0; i < 32; ++i) {
        float e = __expf(v[i] - M) * inv;
        __half h, lo;
        f2hilo(e, h, lo);
        po[(long)i * CS] = h;
        pl[(long)i * CS] = lo;
    }
}

// ---------------- batch-norm over batch axis, fused residual add ----------
// OMODE: 0 = f32 only, 1 = f32 + fp16 hi, 2 = f32 + fp16 hi/lo
template<int OMODE>
__global__ void bn_kernel(const float* __restrict__ x,
                          const float* __restrict__ add, int addw,
                          float* __restrict__ out,
                          __half* __restrict__ oh,
                          __half* __restrict__ ol) {
    int j = blockIdx.x * blockDim.x + threadIdx.x;
    if (j >= CS * CD2) return;
    const long SD = (long)CS * CD2;
    int s = j >> 10;
    int e = j & 1023;
    int ae = e & (addw - 1);
    long aoff = (long)s * addw + ae;

    float v[CB];
    float sum = 0.f;
    #pragma unroll
    for (int b = 0; b < CB; ++b) {
        float t = x[(long)b * SD + j] + add[(long)b * CS * addw + aoff];
        v[b] = t;
        sum += t;
    }
    float mean = sum * (1.f / CB);
    float var = 0.f;
    #pragma unroll
    for (int b = 0; b < CB; ++b) {
        float d = v[b] - mean;
        var += d * d;
    }
    var *= (1.f / CB);
    float rstd = rsqrtf(var + 1e-3f);
    #pragma unroll
    for (int b = 0; b < CB; ++b) {
        float o = (v[b] - mean) * rstd;
        out[(long)b * SD + j] = o;
        if (OMODE == 1) {
            oh[(long)b * SD + j] = __float2half(o);
        } else if (OMODE == 2) {
            __half h, l;
            f2hilo(o, h, l);
            oh[(long)b * SD + j] = h;
            ol[(long)b * SD + j] = l;
        }
    }
}

// ---------------- host orchestration ----------------
struct Ptrs {
    float* f32;
    __half* hb;
};

static void run_attn(int Din,
                     const __half* xh, const __half* xl,
                     const __half* WqT, const __half* WkT, const __half* WvT,
                     const float* bq, const float* bk, const float* bv,
                     const __half* WoT, const float* bo, Ptrs p, float* aout)
{
    float* v  = p.f32 + OF_V;
    float* sc = p.f32 + OF_SC;
    __half *qh = p.hb + HB_QH, *ql = p.hb + HB_QL;
    __half *kh = p.hb + HB_KH;
    __half *vth = p.hb + HB_VTH;
    __half *ath = p.hb + HB_ATH, *atl = p.hb + HB_ATL;
    __half *zh = p.hb + HB_ZH;

    long sAb = (long)CS * Din, sBh = (long)CDK * Din;
    long sCb = (long)CH * CS * CDK, sCh = (long)CS * CDK;
    dim3 gq(1, CS / 128, CB * CH);
    // Q: hi/lo (A of scores). K: hi only (B of scores). V: f32 (for transpose).
    gemm3<1, false, true><<<gq, 128, GSMEM>>>(xh, xl, WqT, bq, nullptr, qh, ql,
        Din, Din, Din, CDK, CH, sAb, 0, 0, sBh, sCb, sCh, CDK, 1.f);
    gemm3<2, false, true><<<gq, 128, GSMEM>>>(xh, xl, WkT, bk, nullptr, kh, nullptr,
        Din, Din, Din, CDK, CH, sAb, 0, 0, sBh, sCb, sCh, CDK, 1.f);
    gemm3<0, false, true><<<gq, 128, GSMEM>>>(xh, xl, WvT, bv, v, nullptr, nullptr,
        Din, Din, Din, CDK, CH, sAb, 0, 0, sBh, sCb, sCh, CDK, 1.f);

    // V transpose: [z][t][dk] -> [z][dk][t], hi only (B of AV)
    transpose_hi<<<dim3(CDK / 32, CS / 32, CB * CH), dim3(32, 8)>>>(v, vth, CS, CDK);

    // scores = Q @ K^T * 1/sqrt(dk)
    gemm3<0, false, true><<<dim3(CS / 128, CS / 128, CB * CH), 128, GSMEM>>>(
        qh, ql, kh, nullptr, sc, nullptr, nullptr,
        CDK, CDK, CDK, CS, 1,
        (long)CS * CDK, 0, (long)CS * CDK, 0, (long)CS * CS, 0, 0,
        0.08838834764831845f);

    softmax_q2<<<dim3(CB * CH, CS / 32), 512>>>(sc, ath, atl);

    // z = attn @ V^T  (z hi only: out-proj uses 1-pass A)
    gemm3<2, false, true><<<dim3(1, CS / 128, CB * CH), 128, GSMEM>>>(
        ath, atl, vth, nullptr, nullptr, zh, nullptr,
        CS, CS, CS, CHD, CH,
        (long)CH * CS * CS, (long)CS * CS,
        (long)CH * CDK * CS, (long)CDK * CS,
        (long)CS * CHD, CDK, 0, 1.f);

    // out projection: (B*S,768) @ (768,1024), single-pass A
    gemm3<0, false, false><<<dim3(CD2 / 128, (CB * CS) / 128, 1), 128, GSMEM>>>(
        zh, nullptr, WoT, bo, aout, nullptr, nullptr,
        CHD, CHD, CHD, CD2, 1, 0, 0, 0, 0, 0, 0, 0, 1.f);
}

extern "C" void kernel_launch(void* const* d_in, const int* in_sizes, int n_in,
                              void* d_out, int out_size)
{
    const float* X    = (const float*)d_in[0];
    const float* Wq1  = (const float*)d_in[1];
    const float* Wk1  = (const float*)d_in[2];
    const float* Wv1  = (const float*)d_in[3];
    const float* bq1  = (const float*)d_in[4];
    const float* bk1  = (const float*)d_in[5];
    const float* bv1  = (const float*)d_in[6];
    const float* Wo1  = (const float*)d_in[7];
    const float* bo1  = (const float*)d_in[8];
    const float* Wff1 = (const float*)d_in[9];
    const float* bff1 = (const float*)d_in[10];
    const float* Wq2  = (const float*)d_in[11];
    const float* Wk2  = (const float*)d_in[12];
    const float* Wv2  = (const float*)d_in[13];
    const float* bq2  = (const float*)d_in[14];
    const float* bk2  = (const float*)d_in[15];
    const float* bv2  = (const float*)d_in[16];
    const float* Wo2  = (const float*)d_in[17];
    const float* bo2  = (const float*)d_in[18];
    const float* Wff2 = (const float*)d_in[19];
    const float* bff2 = (const float*)d_in[20];
    float* out = (float*)d_out;

    float* sb = nullptr;
    cudaGetSymbolAddress((void**)&sb, g_scratch);
    Ptrs p;
    p.f32 = sb;
    p.hb = (__half*)(sb + F32_END);

    cudaFuncSetAttribute(gemm3<0, false, true>,  cudaFuncAttributeMaxDynamicSharedMemorySize, GSMEM);
    cudaFuncSetAttribute(gemm3<1, false, true>,  cudaFuncAttributeMaxDynamicSharedMemorySize, GSMEM);
    cudaFuncSetAttribute(gemm3<2, false, true>,  cudaFuncAttributeMaxDynamicSharedMemorySize, GSMEM);
    cudaFuncSetAttribute(gemm3<0, false, false>, cudaFuncAttributeMaxDynamicSharedMemorySize, GSMEM);
    cudaFuncSetAttribute(gemm3<0, true, false>,  cudaFuncAttributeMaxDynamicSharedMemorySize, GSMEM);

    // ----- weight transpose + hi convert (weights are B-side: hi only) -----
    dim3 tb(32, 8);
    transpose_hi<<<dim3(CDK/32, CE/32, CH),   tb>>>(Wq1, p.hb+HB_W1Q, CE,  CDK);
    transpose_hi<<<dim3(CDK/32, CE/32, CH),   tb>>>(Wk1, p.hb+HB_W1K, CE,  CDK);
    transpose_hi<<<dim3(CDK/32, CE/32, CH),   tb>>>(Wv1, p.hb+HB_W1V, CE,  CDK);
    transpose_hi<<<dim3(CD2/32, CHD/32, 1),   tb>>>(Wo1, p.hb+HB_W1O, CHD, CD2);
    transpose_hi<<<dim3(CD2/32, CD2/32, 1),   tb>>>(Wff1,p.hb+HB_W1F, CD2, CD2);
    transpose_hi<<<dim3(CDK/32, CD2/32, CH),  tb>>>(Wq2, p.hb+HB_W2Q, CD2, CDK);
    transpose_hi<<<dim3(CDK/32, CD2/32, CH),  tb>>>(Wk2, p.hb+HB_W2K, CD2, CDK);
    transpose_hi<<<dim3(CDK/32, CD2/32, CH),  tb>>>(Wv2, p.hb+HB_W2V, CD2, CDK);
    transpose_hi<<<dim3(CD2/32, CHD/32, 1),   tb>>>(Wo2, p.hb+HB_W2O, CHD, CD2);
    transpose_hi<<<dim3(CD2/32, CD2/32, 1),   tb>>>(Wff2,p.hb+HB_W2F, CD2, CD2);

    // ----- positional encoding -----
    float* pos = sb + OF_POS;
    float* xp  = sb + OF_XP;
    posgen_kernel<<<(CS * CE + 255) / 256, 256>>>(pos);
    addpos_hilo<<<(unsigned)((NB_XP + 255) / 256), 256>>>(X, pos, xp,
        p.hb + HB_XPH, p.hb + HB_XPL, NB_XP);

    float* a  = sb + OF_A;
    float* n1 = sb + OF_N1;
    float* n2 = sb + OF_N2;
    float* n3 = sb + OF_N3;
    float* f  = sb + OF_F;
    int nbn = (CS * CD2 + 255) / 256;
    dim3 gff(CD2 / 128, (CB * CS) / 128, 1);

    // ----- block 1: attention (Din = 512) -----
    run_attn(CE, p.hb + HB_XPH, p.hb + HB_XPL,
             p.hb+HB_W1Q, p.hb+HB_W1K, p.hb+HB_W1V, bq1, bk1, bv1,
             p.hb+HB_W1O, bo1, p, a);
    bn_kernel<1><<<nbn, 256>>>(a, xp, CE, n1, p.hb + HB_N1H, nullptr);

    // ----- block 2: FFN (single-pass A) -----
    gemm3<0, true, false><<<gff, 128, GSMEM>>>(
        p.hb + HB_N1H, nullptr, p.hb + HB_W1F, bff1,
        f, nullptr, nullptr, CD2, CD2, CD2, CD2, 1, 0, 0, 0, 0, 0, 0, 0, 1.f);
    bn_kernel<2><<<nbn, 256>>>(f, n1, CD2, n2, p.hb + HB_N2H, p.hb + HB_N2L);

    // ----- block 3: attention (Din = 1024) -----
    run_attn(CD2, p.hb + HB_N2H, p.hb + HB_N2L,
             p.hb+HB_W2Q, p.hb+HB_W2K, p.hb+HB_W2V, bq2, bk2, bv2,
             p.hb+HB_W2O, bo2, p, a);
    bn_kernel<1><<<nbn, 256>>>(a, n2, CD2, n3, p.hb + HB_N3H, nullptr);

    // ----- block 4: FFN (single-pass A) -----
    gemm3<0, true, false><<<gff, 128, GSMEM>>>(
        p.hb + HB_N3H, nullptr, p.hb + HB_W2F, bff2,
        f, nullptr, nullptr, CD2, CD2, CD2, CD2, 1, 0, 0, 0, 0, 0, 0, 0, 1.f);
    bn_kernel<0><<<nbn, 256>>>(f, n3, CD2, out, nullptr, nullptr);
}

// round 9
// speedup vs baseline: 1.8672x; 1.1792x over previous
#include <cuda_runtime.h>
#include <cuda_fp16.h>
#include <cstdint>
#include <math.h>

#define CB 32
#define CS 512
#define CE 512
#define CDK 128
#define CH 6
#define CD2 1024
#define CHD 768

// ---------------- sizes (elements) ----------------
constexpr long NB_XP  = (long)CB*CS*CE;
constexpr long NB_QKV = (long)CB*CH*CS*CDK;
constexpr long NB_SC  = (long)CB*CH*CS*CS;
constexpr long NB_Z   = (long)CB*CS*CHD;
constexpr long NB_D2  = (long)CB*CS*CD2;
constexpr long NW_QKV1 = (long)CH*CE*CDK;
constexpr long NW_QKV2 = (long)CH*CD2*CDK;
constexpr long NW_O   = (long)CHD*CD2;
constexpr long NW_F   = (long)CD2*CD2;

// ---------------- f32 scratch offsets ----------------
constexpr long OF_POS = 0;
constexpr long OF_XP  = OF_POS + (long)CS*CE;
constexpr long OF_V   = OF_XP + NB_XP;
constexpr long OF_SC  = OF_V + NB_QKV;
constexpr long OF_A   = OF_SC + NB_SC;
constexpr long OF_N1  = OF_A + NB_D2;
constexpr long OF_N2  = OF_N1 + NB_D2;
constexpr long OF_N3  = OF_N2 + NB_D2;
constexpr long OF_F   = OF_N3 + NB_D2;
constexpr long F32_END = OF_F + NB_D2;

// ---------------- fp16 scratch offsets (half elems) ----------------
constexpr long HB_XPH = 0;                    // xp: hi only (QKV A 1-pass)
constexpr long HB_QH  = HB_XPH + NB_XP;
constexpr long HB_QL  = HB_QH + NB_QKV;
constexpr long HB_KH  = HB_QL + NB_QKV;       // K: hi only (B side)
constexpr long HB_VTH = HB_KH + NB_QKV;       // V^T: hi only (B side)
constexpr long HB_ATH = HB_VTH + NB_QKV;
constexpr long HB_ATL = HB_ATH + NB_SC;
constexpr long HB_ZH  = HB_ATL + NB_SC;       // z: hi only
constexpr long HB_N1H = HB_ZH + NB_Z;         // n1: hi only
constexpr long HB_N2H = HB_N1H + NB_D2;       // n2: hi only (layer2 QKV 1-pass)
constexpr long HB_N3H = HB_N2H + NB_D2;       // n3: hi only
// weights: hi only (all are B-side)
constexpr long HB_W1Q = HB_N3H + NB_D2;
constexpr long HB_W1K = HB_W1Q + NW_QKV1;
constexpr long HB_W1V = HB_W1K + NW_QKV1;
constexpr long HB_W1O = HB_W1V + NW_QKV1;
constexpr long HB_W1F = HB_W1O + NW_O;
constexpr long HB_W2Q = HB_W1F + NW_F;
constexpr long HB_W2K = HB_W2Q + NW_QKV2;
constexpr long HB_W2V = HB_W2K + NW_QKV2;
constexpr long HB_W2O = HB_W2V + NW_QKV2;
constexpr long HB_W2F = HB_W2O + NW_O;
constexpr long HB_END = HB_W2F + NW_F;

constexpr long SCRATCH_TOT = F32_END + (HB_END + 1) / 2 + 64;
__device__ float g_scratch[SCRATCH_TOT];

// ---------------- helpers ----------------
__device__ __forceinline__ void f2hilo(float v, __half& h, __half& l) {
    h = __float2half(v);
    l = __float2half(v - __half2float(h));
}

__device__ __forceinline__ void cp16(uint32_t d, const void* s) {
    asm volatile("cp.async.cg.shared.global [%0], [%1], 16;\n" :: "r"(d), "l"(s));
}

#define MMA16816(c, a, b0, b1)                                              \
    asm volatile("mma.sync.aligned.m16n8k16.row.col.f32.f16.f16.f32 "       \
                 "{%0,%1,%2,%3},{%4,%5,%6,%7},{%8,%9},{%0,%1,%2,%3};"       \
                 : "+f"((c)[0]), "+f"((c)[1]), "+f"((c)[2]), "+f"((c)[3])   \
                 : "r"((a)[0]), "r"((a)[1]), "r"((a)[2]), "r"((a)[3]),      \
                   "r"(b0), "r"(b1))

// ---------------- positional encoding ----------------
__global__ void posgen_kernel(float* __restrict__ pos) {
    int idx = blockIdx.x * blockDim.x + threadIdx.x;
    if (idx >= CS * CE) return;
    int s = idx >> 9;
    int e = idx & 511;
    int m = e >> 1;
    double ang = (m >= 128) ? ((double)s / 10000.0) : (double)s;
    pos[idx] = (e & 1) ? (float)cos(ang) : (float)sin(ang);
}

__global__ void addpos_hi(const float* __restrict__ X,
                          const float* __restrict__ pos,
                          float* __restrict__ xp,
                          __half* __restrict__ xh, long n) {
    long idx = (long)blockIdx.x * blockDim.x + threadIdx.x;
    if (idx >= n) return;
    float v = X[idx] + pos[idx % (CS * CE)];
    xp[idx] = v;
    xh[idx] = __float2half(v);
}

// ---------------- transpose + hi-only convert (B-side operands) ----------
__global__ void transpose_hi(const float* __restrict__ in,
                             __half* __restrict__ oh,
                             int R, int C) {
    __shared__ float t[32][33];
    long zo = (long)blockIdx.z * R * C;
    int c0 = blockIdx.x * 32, r0 = blockIdx.y * 32;
    int tx = threadIdx.x, ty = threadIdx.y;
    #pragma unroll
    for (int i = 0; i < 32; i += 8)
        t[ty + i][tx] = in[zo + (long)(r0 + ty + i) * C + c0 + tx];
    __syncthreads();
    #pragma unroll
    for (int i = 0; i < 32; i += 8) {
        float v = t[tx][ty + i];
        long o = zo + (long)(c0 + ty + i) * R + r0 + tx;
        oh[o] = __float2half(v);
    }
}

// ---------------- fp16 tensor-core GEMM ----------------
// C = alpha * (A_hi [+ A_lo]) @ B_hi^T (+bias)(+tanh).
// TWOPASS: include the A_lo correction pass.
// OUTMODE: 0=f32, 1=fp16 hi+lo, 2=fp16 hi only.
#define STGB 30720          // Ah 10240 | Al 10240 | Bh 10240 (80B-pitch rows)
#define GSMEM (2 * STGB)    // 61440

template<int OUTMODE, bool TANH, bool TWOPASS>
__global__ void __launch_bounds__(128, 2) gemm3(
    const __half* __restrict__ Ah, const __half* __restrict__ Al,
    const __half* __restrict__ Bh,
    const float* __restrict__ biasb,
    float* __restrict__ Cf,
    __half* __restrict__ Ch, __half* __restrict__ Cl,
    int K, int lda, int ldb, int ldc, int Hdiv,
    long sA_b, long sA_h, long sB_b, long sB_h,
    long sC_b, long sC_h, long sBias_h, float alpha)
{
    extern __shared__ uint8_t smem[];
    int z = blockIdx.z, zb = z / Hdiv, zh_ = z - zb * Hdiv;
    const __half* Ahp = Ah + zb * sA_b + zh_ * sA_h;
    const __half* Alp = TWOPASS ? (Al + zb * sA_b + zh_ * sA_h) : nullptr;
    const __half* Bhp = Bh + zb * sB_b + zh_ * sB_h;
    int m0 = blockIdx.y * 128, n0 = blockIdx.x * 128;
    int tid = threadIdx.x;
    int wid = tid >> 5, lane = tid & 31;
    int g = lane >> 2, tig = lane & 3;
    int wm = (wid & 1) * 64, wn = (wid >> 1) * 64;

    uint32_t sbase = (uint32_t)__cvta_generic_to_shared(smem);

    float acc[4][8][4];
    #pragma unroll
    for (int i = 0; i < 4; ++i)
        #pragma unroll
        for (int j = 0; j < 8; ++j)
            #pragma unroll
            for (int q = 0; q < 4; ++q) acc[i][j][q] = 0.f;

    const __half* ga_h = Ahp + (long)(m0 + tid) * lda;
    const __half* ga_l = TWOPASS ? (Alp + (long)(m0 + tid) * lda) : nullptr;
    const __half* gb_h = Bhp + (long)(n0 + tid) * ldb;

    int nk = K / 32;
    {
        uint32_t d = sbase + tid * 80;
        #pragma unroll
        for (int c = 0; c < 4; ++c) {
            cp16(d + c * 16,         ga_h + c * 8);
            if (TWOPASS) cp16(d + 10240 + c * 16, ga_l + c * 8);
            cp16(d + 20480 + c * 16, gb_h + c * 8);
        }
        asm volatile("cp.async.commit_group;");
    }

    for (int kc = 0; kc < nk; ++kc) {
        if (kc + 1 < nk) {
            int k0 = (kc + 1) * 32;
            uint32_t d = sbase + ((kc + 1) & 1) * STGB + tid * 80;
            #pragma unroll
            for (int c = 0; c < 4; ++c) {
                cp16(d + c * 16,         ga_h + k0 + c * 8);
                if (TWOPASS) cp16(d + 10240 + c * 16, ga_l + k0 + c * 8);
                cp16(d + 20480 + c * 16, gb_h + k0 + c * 8);
            }
            asm volatile("cp.async.commit_group;");
            asm volatile("cp.async.wait_group 1;");
        } else {
            asm volatile("cp.async.wait_group 0;");
        }
        __syncthreads();

        const uint8_t* sb_ = smem + (kc & 1) * STGB;
        #pragma unroll
        for (int ks = 0; ks < 2; ++ks) {
            int cb = ks * 32 + tig * 4;
            uint32_t ah[4][4], al2[4][4];
            #pragma unroll
            for (int mt = 0; mt < 4; ++mt) {
                const uint8_t* p = sb_ + (wm + mt * 16 + g) * 80 + cb;
                ah[mt][0] = *(const uint32_t*)(p);
                ah[mt][1] = *(const uint32_t*)(p + 8 * 80);
                ah[mt][2] = *(const uint32_t*)(p + 16);
                ah[mt][3] = *(const uint32_t*)(p + 8 * 80 + 16);
                if (TWOPASS) {
                    const uint8_t* q_ = p + 10240;
                    al2[mt][0] = *(const uint32_t*)(q_);
                    al2[mt][1] = *(const uint32_t*)(q_ + 8 * 80);
                    al2[mt][2] = *(const uint32_t*)(q_ + 16);
                    al2[mt][3] = *(const uint32_t*)(q_ + 8 * 80 + 16);
                }
            }
            #pragma unroll
            for (int ntp = 0; ntp < 4; ++ntp) {
                uint32_t bh0[2], bh1[2];
                #pragma unroll
                for (int u = 0; u < 2; ++u) {
                    int nt = ntp * 2 + u;
                    const uint8_t* pb = sb_ + 20480 + (wn + nt * 8 + g) * 80 + cb;
                    bh0[u] = *(const uint32_t*)(pb);
                    bh1[u] = *(const uint32_t*)(pb + 16);
                }
                #pragma unroll
                for (int u = 0; u < 2; ++u)
                    #pragma unroll
                    for (int mt = 0; mt < 4; ++mt)
                        MMA16816(acc[mt][ntp * 2 + u], ah[mt], bh0[u], bh1[u]);
                if (TWOPASS) {
                    #pragma unroll
                    for (int u = 0; u < 2; ++u)
                        #pragma unroll
                        for (int mt = 0; mt < 4; ++mt)
                            MMA16816(acc[mt][ntp * 2 + u], al2[mt], bh0[u], bh1[u]);
                }
            }
        }
        __syncthreads();
    }

    // epilogue
    float* Cfp = nullptr;
    __half *Chp = nullptr, *Clp = nullptr;
    if (OUTMODE == 0) Cfp = Cf + zb * sC_b + zh_ * sC_h;
    else { Chp = Ch + zb * sC_b + zh_ * sC_h; if (OUTMODE == 1) Clp = Cl + zb * sC_b + zh_ * sC_h; }
    const float* bias = biasb ? biasb + (long)zh_ * sBias_h : nullptr;

    #pragma unroll
    for (int nt = 0; nt < 8; ++nt) {
        int col = n0 + wn + nt * 8 + tig * 2;
        float bb0 = 0.f, bb1 = 0.f;
        if (bias) { bb0 = bias[col]; bb1 = bias[col + 1]; }
        #pragma unroll
        for (int mt = 0; mt < 4; ++mt) {
            int r0 = m0 + wm + mt * 16 + g;
            float v00 = acc[mt][nt][0] * alpha + bb0;
            float v01 = acc[mt][nt][1] * alpha + bb1;
            float v10 = acc[mt][nt][2] * alpha + bb0;
            float v11 = acc[mt][nt][3] * alpha + bb1;
            if (TANH) { v00 = tanhf(v00); v01 = tanhf(v01); v10 = tanhf(v10); v11 = tanhf(v11); }
            if (OUTMODE == 0) {
                *(float2*)(Cfp + (long)r0 * ldc + col) = make_float2(v00, v01);
                *(float2*)(Cfp + (long)(r0 + 8) * ldc + col) = make_float2(v10, v11);
            } else if (OUTMODE == 2) {
                __half2 hh;
                hh.x = __float2half(v00); hh.y = __float2half(v01);
                *(__half2*)(Chp + (long)r0 * ldc + col) = hh;
                hh.x = __float2half(v10); hh.y = __float2half(v11);
                *(__half2*)(Chp + (long)(r0 + 8) * ldc + col) = hh;
            } else {
                __half h0, l0, h1, l1;
                f2hilo(v00, h0, l0); f2hilo(v01, h1, l1);
                __half2 hh; hh.x = h0; hh.y = h1;
                __half2 ll; ll.x = l0; ll.y = l1;
                *(__half2*)(Chp + (long)r0 * ldc + col) = hh;
                *(__half2*)(Clp + (long)r0 * ldc + col) = ll;
                f2hilo(v10, h0, l0); f2hilo(v11, h1, l1);
                hh.x = h0; hh.y = h1; ll.x = l0; ll.y = l1;
                *(__half2*)(Chp + (long)(r0 + 8) * ldc + col) = hh;
                *(__half2*)(Clp + (long)(r0 + 8) * ldc + col) = ll;
            }
        }
    }
}

// ---------------- softmax over the QUERY axis (parallelized) ----------
__global__ void __launch_bounds__(512) softmax_q2(const float* __restrict__ Sc,
                                                  __half* __restrict__ oh,
                                                  __half* __restrict__ ol) {
    __shared__ float sm[16][32], sl[16][32];
    long base = (long)blockIdx.x * CS * CS + blockIdx.y * 32;
    int w = threadIdx.x >> 5, lane = threadIdx.x & 31;
    const float* p = Sc + base + (long)w * 32 * CS + lane;
    float v[32];
    float m = -1e30f, l = 0.f;
    #pragma unroll
    for (int i = 0; i < 32; ++i) {
        float x = p[(long)i * CS];
        v[i] = x;
        float nm = fmaxf(m, x);
        l = l * __expf(m - nm) + __expf(x - nm);
        m = nm;
    }
    sm[w][lane] = m; sl[w][lane] = l;
    __syncthreads();
    float M = -1e30f;
    #pragma unroll
    for (int ww = 0; ww < 16; ++ww) M = fmaxf(M, sm[ww][lane]);
    float L = 0.f;
    #pragma unroll
    for (int ww = 0; ww < 16; ++ww) L += sl[ww][lane] * __expf(sm[ww][lane] - M);
    float inv = 1.f / L;
    __half* po = oh + base + (long)w * 32 * CS + lane;
    __half* pl = ol + base + (long)w * 32 * CS + lane;
    #pragma unroll
    for (int i = 0; i < 32; ++i) {
        float e = __expf(v[i] - M) * inv;
        __half h, lo;
        f2hilo(e, h, lo);
        po[(long)i * CS] = h;
        pl[(long)i * CS] = lo;
    }
}

// ---------------- batch-norm over batch axis, fused residual add ----------
// OMODE: 0 = f32 only, 1 = f32 + fp16 hi
template<int OMODE>
__global__ void bn_kernel(const float* __restrict__ x,
                          const float* __restrict__ add, int addw,
                          float* __restrict__ out,
                          __half* __restrict__ oh) {
    int j = blockIdx.x * blockDim.x + threadIdx.x;
    if (j >= CS * CD2) return;
    const long SD = (long)CS * CD2;
    int s = j >> 10;
    int e = j & 1023;
    int ae = e & (addw - 1);
    long aoff = (long)s * addw + ae;

    float v[CB];
    float sum = 0.f;
    #pragma unroll
    for (int b = 0; b < CB; ++b) {
        float t = x[(long)b * SD + j] + add[(long)b * CS * addw + aoff];
        v[b] = t;
        sum += t;
    }
    float mean = sum * (1.f / CB);
    float var = 0.f;
    #pragma unroll
    for (int b = 0; b < CB; ++b) {
        float d = v[b] - mean;
        var += d * d;
    }
    var *= (1.f / CB);
    float rstd = rsqrtf(var + 1e-3f);
    #pragma unroll
    for (int b = 0; b < CB; ++b) {
        float o = (v[b] - mean) * rstd;
        out[(long)b * SD + j] = o;
        if (OMODE == 1)
            oh[(long)b * SD + j] = __float2half(o);
    }
}

// ---------------- host orchestration ----------------
struct Ptrs {
    float* f32;
    __half* hb;
};

static void run_attn(int Din, const __half* xh,
                     const __half* WqT, const __half* WkT, const __half* WvT,
                     const float* bq, const float* bk, const float* bv,
                     const __half* WoT, const float* bo, Ptrs p, float* aout)
{
    float* v  = p.f32 + OF_V;
    float* sc = p.f32 + OF_SC;
    __half *qh = p.hb + HB_QH, *ql = p.hb + HB_QL;
    __half *kh = p.hb + HB_KH;
    __half *vth = p.hb + HB_VTH;
    __half *ath = p.hb + HB_ATH, *atl = p.hb + HB_ATL;
    __half *zh = p.hb + HB_ZH;

    long sAb = (long)CS * Din, sBh = (long)CDK * Din;
    long sCb = (long)CH * CS * CDK, sCh = (long)CS * CDK;
    dim3 gq(1, CS / 128, CB * CH);
    // QKV projections: single-pass A (x hi only)
    gemm3<1, false, false><<<gq, 128, GSMEM>>>(xh, nullptr, WqT, bq, nullptr, qh, ql,
        Din, Din, Din, CDK, CH, sAb, 0, 0, sBh, sCb, sCh, CDK, 1.f);
    gemm3<2, false, false><<<gq, 128, GSMEM>>>(xh, nullptr, WkT, bk, nullptr, kh, nullptr,
        Din, Din, Din, CDK, CH, sAb, 0, 0, sBh, sCb, sCh, CDK, 1.f);
    gemm3<0, false, false><<<gq, 128, GSMEM>>>(xh, nullptr, WvT, bv, v, nullptr, nullptr,
        Din, Din, Din, CDK, CH, sAb, 0, 0, sBh, sCb, sCh, CDK, 1.f);

    // V transpose: [z][t][dk] -> [z][dk][t], hi only (B of AV)
    transpose_hi<<<dim3(CDK / 32, CS / 32, CB * CH), dim3(32, 8)>>>(v, vth, CS, CDK);

    // scores = Q @ K^T * 1/sqrt(dk)  (2-pass A: Q hi/lo)
    gemm3<0, false, true><<<dim3(CS / 128, CS / 128, CB * CH), 128, GSMEM>>>(
        qh, ql, kh, nullptr, sc, nullptr, nullptr,
        CDK, CDK, CDK, CS, 1,
        (long)CS * CDK, 0, (long)CS * CDK, 0, (long)CS * CS, 0, 0,
        0.08838834764831845f);

    softmax_q2<<<dim3(CB * CH, CS / 32), 512>>>(sc, ath, atl);

    // z = attn @ V^T  (2-pass A: attn hi/lo; z hi only)
    gemm3<2, false, true><<<dim3(1, CS / 128, CB * CH), 128, GSMEM>>>(
        ath, atl, vth, nullptr, nullptr, zh, nullptr,
        CS, CS, CS, CHD, CH,
        (long)CH * CS * CS, (long)CS * CS,
        (long)CH * CDK * CS, (long)CDK * CS,
        (long)CS * CHD, CDK, 0, 1.f);

    // out projection: (B*S,768) @ (768,1024), single-pass A
    gemm3<0, false, false><<<dim3(CD2 / 128, (CB * CS) / 128, 1), 128, GSMEM>>>(
        zh, nullptr, WoT, bo, aout, nullptr, nullptr,
        CHD, CHD, CHD, CD2, 1, 0, 0, 0, 0, 0, 0, 0, 1.f);
}

extern "C" void kernel_launch(void* const* d_in, const int* in_sizes, int n_in,
                              void* d_out, int out_size)
{
    const float* X    = (const float*)d_in[0];
    const float* Wq1  = (const float*)d_in[1];
    const float* Wk1  = (const float*)d_in[2];
    const float* Wv1  = (const float*)d_in[3];
    const float* bq1  = (const float*)d_in[4];
    const float* bk1  = (const float*)d_in[5];
    const float* bv1  = (const float*)d_in[6];
    const float* Wo1  = (const float*)d_in[7];
    const float* bo1  = (const float*)d_in[8];
    const float* Wff1 = (const float*)d_in[9];
    const float* bff1 = (const float*)d_in[10];
    const float* Wq2  = (const float*)d_in[11];
    const float* Wk2  = (const float*)d_in[12];
    const float* Wv2  = (const float*)d_in[13];
    const float* bq2  = (const float*)d_in[14];
    const float* bk2  = (const float*)d_in[15];
    const float* bv2  = (const float*)d_in[16];
    const float* Wo2  = (const float*)d_in[17];
    const float* bo2  = (const float*)d_in[18];
    const float* Wff2 = (const float*)d_in[19];
    const float* bff2 = (const float*)d_in[20];
    float* out = (float*)d_out;

    float* sb = nullptr;
    cudaGetSymbolAddress((void**)&sb, g_scratch);
    Ptrs p;
    p.f32 = sb;
    p.hb = (__half*)(sb + F32_END);

    cudaFuncSetAttribute(gemm3<0, false, true>,  cudaFuncAttributeMaxDynamicSharedMemorySize, GSMEM);
    cudaFuncSetAttribute(gemm3<2, false, true>,  cudaFuncAttributeMaxDynamicSharedMemorySize, GSMEM);
    cudaFuncSetAttribute(gemm3<0, false, false>, cudaFuncAttributeMaxDynamicSharedMemorySize, GSMEM);
    cudaFuncSetAttribute(gemm3<1, false, false>, cudaFuncAttributeMaxDynamicSharedMemorySize, GSMEM);
    cudaFuncSetAttribute(gemm3<2, false, false>, cudaFuncAttributeMaxDynamicSharedMemorySize, GSMEM);
    cudaFuncSetAttribute(gemm3<0, true, false>,  cudaFuncAttributeMaxDynamicSharedMemorySize, GSMEM);

    // ----- weight transpose + hi convert (weights are B-side: hi only) -----
    dim3 tb(32, 8);
    transpose_hi<<<dim3(CDK/32, CE/32, CH),   tb>>>(Wq1, p.hb+HB_W1Q, CE,  CDK);
    transpose_hi<<<dim3(CDK/32, CE/32, CH),   tb>>>(Wk1, p.hb+HB_W1K, CE,  CDK);
    transpose_hi<<<dim3(CDK/32, CE/32, CH),   tb>>>(Wv1, p.hb+HB_W1V, CE,  CDK);
    transpose_hi<<<dim3(CD2/32, CHD/32, 1),   tb>>>(Wo1, p.hb+HB_W1O, CHD, CD2);
    transpose_hi<<<dim3(CD2/32, CD2/32, 1),   tb>>>(Wff1,p.hb+HB_W1F, CD2, CD2);
    transpose_hi<<<dim3(CDK/32, CD2/32, CH),  tb>>>(Wq2, p.hb+HB_W2Q, CD2, CDK);
    transpose_hi<<<dim3(CDK/32, CD2/32, CH),  tb>>>(Wk2, p.hb+HB_W2K, CD2, CDK);
    transpose_hi<<<dim3(CDK/32, CD2/32, CH),  tb>>>(Wv2, p.hb+HB_W2V, CD2, CDK);
    transpose_hi<<<dim3(CD2/32, CHD/32, 1),   tb>>>(Wo2, p.hb+HB_W2O, CHD, CD2);
    transpose_hi<<<dim3(CD2/32, CD2/32, 1),   tb>>>(Wff2,p.hb+HB_W2F, CD2, CD2);

    // ----- positional encoding -----
    float* pos = sb + OF_POS;
    float* xp  = sb + OF_XP;
    posgen_kernel<<<(CS * CE + 255) / 256, 256>>>(pos);
    addpos_hi<<<(unsigned)((NB_XP + 255) / 256), 256>>>(X, pos, xp,
        p.hb + HB_XPH, NB_XP);

    float* a  = sb + OF_A;
    float* n1 = sb + OF_N1;
    float* n2 = sb + OF_N2;
    float* n3 = sb + OF_N3;
    float* f  = sb + OF_F;
    int nbn = (CS * CD2 + 255) / 256;
    dim3 gff(CD2 / 128, (CB * CS) / 128, 1);

    // ----- block 1: attention (Din = 512) -----
    run_attn(CE, p.hb + HB_XPH,
             p.hb+HB_W1Q, p.hb+HB_W1K, p.hb+HB_W1V, bq1, bk1, bv1,
             p.hb+HB_W1O, bo1, p, a);
    bn_kernel<1><<<nbn, 256>>>(a, xp, CE, n1, p.hb + HB_N1H);

    // ----- block 2: FFN (single-pass A) -----
    gemm3<0, true, false><<<gff, 128, GSMEM>>>(
        p.hb + HB_N1H, nullptr, p.hb + HB_W1F, bff1,
        f, nullptr, nullptr, CD2, CD2, CD2, CD2, 1, 0, 0, 0, 0, 0, 0, 0, 1.f);
    bn_kernel<1><<<nbn, 256>>>(f, n1, CD2, n2, p.hb + HB_N2H);

    // ----- block 3: attention (Din = 1024) -----
    run_attn(CD2, p.hb + HB_N2H,
             p.hb+HB_W2Q, p.hb+HB_W2K, p.hb+HB_W2V, bq2, bk2, bv2,
             p.hb+HB_W2O, bo2, p, a);
    bn_kernel<1><<<nbn, 256>>>(a, n2, CD2, n3, p.hb + HB_N3H);

    // ----- block 4: FFN (single-pass A) -----
    gemm3<0, true, false><<<gff, 128, GSMEM>>>(
        p.hb + HB_N3H, nullptr, p.hb + HB_W2F, bff2,
        f, nullptr, nullptr, CD2, CD2, CD2, CD2, 1, 0, 0, 0, 0, 0, 0, 0, 1.f);
    bn_kernel<0><<<nbn, 256>>>(f, n3, CD2, out, nullptr);
}

// round 10
// speedup vs baseline: 2.0529x; 1.0995x over previous
#include <cuda_runtime.h>
#include <cuda_fp16.h>
#include <cstdint>
#include <math.h>

#define CB 32
#define CS 512
#define CE 512
#define CDK 128
#define CH 6
#define CD2 1024
#define CHD 768

// ---------------- sizes (elements) ----------------
constexpr long NB_XP  = (long)CB*CS*CE;
constexpr long NB_QKV = (long)CB*CH*CS*CDK;
constexpr long NB_SC  = (long)CB*CH*CS*CS;
constexpr long NB_Z   = (long)CB*CS*CHD;
constexpr long NB_D2  = (long)CB*CS*CD2;
constexpr long NW_QKV1 = (long)CH*CE*CDK;
constexpr long NW_QKV2 = (long)CH*CD2*CDK;
constexpr long NW_O   = (long)CHD*CD2;
constexpr long NW_F   = (long)CD2*CD2;

// ---------------- f32 scratch offsets ----------------
constexpr long OF_POS = 0;
constexpr long OF_XP  = OF_POS + (long)CS*CE;
constexpr long OF_V   = OF_XP + NB_XP;
constexpr long OF_SC  = OF_V + NB_QKV;
constexpr long OF_A   = OF_SC + NB_SC;
constexpr long OF_N1  = OF_A + NB_D2;
constexpr long OF_N2  = OF_N1 + NB_D2;
constexpr long OF_N3  = OF_N2 + NB_D2;
constexpr long OF_F   = OF_N3 + NB_D2;
constexpr long F32_END = OF_F + NB_D2;

// ---------------- fp16 scratch offsets (half elems) ----------------
constexpr long HB_XPH = 0;                    // xp: hi only
constexpr long HB_QH  = HB_XPH + NB_XP;       // Q: hi only
constexpr long HB_KH  = HB_QH + NB_QKV;       // K: hi only
constexpr long HB_VTH = HB_KH + NB_QKV;       // V^T: hi only
constexpr long HB_ATH = HB_VTH + NB_QKV;      // attn: hi only
constexpr long HB_ZH  = HB_ATH + NB_SC;       // z: hi only
constexpr long HB_N1H = HB_ZH + NB_Z;
constexpr long HB_N2H = HB_N1H + NB_D2;
constexpr long HB_N3H = HB_N2H + NB_D2;
// weights: hi only
constexpr long HB_W1Q = HB_N3H + NB_D2;
constexpr long HB_W1K = HB_W1Q + NW_QKV1;
constexpr long HB_W1V = HB_W1K + NW_QKV1;
constexpr long HB_W1O = HB_W1V + NW_QKV1;
constexpr long HB_W1F = HB_W1O + NW_O;
constexpr long HB_W2Q = HB_W1F + NW_F;
constexpr long HB_W2K = HB_W2Q + NW_QKV2;
constexpr long HB_W2V = HB_W2K + NW_QKV2;
constexpr long HB_W2O = HB_W2V + NW_QKV2;
constexpr long HB_W2F = HB_W2O + NW_O;
constexpr long HB_END = HB_W2F + NW_F;

constexpr long SCRATCH_TOT = F32_END + (HB_END + 1) / 2 + 64;
__device__ float g_scratch[SCRATCH_TOT];

// ---------------- helpers ----------------
__device__ __forceinline__ void cp16(uint32_t d, const void* s) {
    asm volatile("cp.async.cg.shared.global [%0], [%1], 16;\n" :: "r"(d), "l"(s));
}

#define MMA16816(c, a, b0, b1)                                              \
    asm volatile("mma.sync.aligned.m16n8k16.row.col.f32.f16.f16.f32 "       \
                 "{%0,%1,%2,%3},{%4,%5,%6,%7},{%8,%9},{%0,%1,%2,%3};"       \
                 : "+f"((c)[0]), "+f"((c)[1]), "+f"((c)[2]), "+f"((c)[3])   \
                 : "r"((a)[0]), "r"((a)[1]), "r"((a)[2]), "r"((a)[3]),      \
                   "r"(b0), "r"(b1))

// ---------------- positional encoding ----------------
__global__ void posgen_kernel(float* __restrict__ pos) {
    int idx = blockIdx.x * blockDim.x + threadIdx.x;
    if (idx >= CS * CE) return;
    int s = idx >> 9;
    int e = idx & 511;
    int m = e >> 1;
    double ang = (m >= 128) ? ((double)s / 10000.0) : (double)s;
    pos[idx] = (e & 1) ? (float)cos(ang) : (float)sin(ang);
}

__global__ void addpos_hi(const float* __restrict__ X,
                          const float* __restrict__ pos,
                          float* __restrict__ xp,
                          __half* __restrict__ xh, long n) {
    long idx = (long)blockIdx.x * blockDim.x + threadIdx.x;
    if (idx >= n) return;
    float v = X[idx] + pos[idx % (CS * CE)];
    xp[idx] = v;
    xh[idx] = __float2half(v);
}

// ---------------- transpose + hi-only convert ----------
__global__ void transpose_hi(const float* __restrict__ in,
                             __half* __restrict__ oh,
                             int R, int C) {
    __shared__ float t[32][33];
    long zo = (long)blockIdx.z * R * C;
    int c0 = blockIdx.x * 32, r0 = blockIdx.y * 32;
    int tx = threadIdx.x, ty = threadIdx.y;
    #pragma unroll
    for (int i = 0; i < 32; i += 8)
        t[ty + i][tx] = in[zo + (long)(r0 + ty + i) * C + c0 + tx];
    __syncthreads();
    #pragma unroll
    for (int i = 0; i < 32; i += 8) {
        float v = t[tx][ty + i];
        long o = zo + (long)(c0 + ty + i) * R + r0 + tx;
        oh[o] = __float2half(v);
    }
}

// ---------------- fp16 tensor-core GEMM (single-pass) ----------------
// C = alpha * A_hi @ B_hi^T (+bias)(+tanh). OUTMODE: 0=f32, 2=fp16 hi.
#define STGB 20480          // Ah 10240 | Bh 10240 (80B-pitch rows)
#define GSMEM (2 * STGB)    // 40960

template<int OUTMODE, bool TANH>
__global__ void __launch_bounds__(128, 2) gemm3(
    const __half* __restrict__ Ah,
    const __half* __restrict__ Bh,
    const float* __restrict__ biasb,
    float* __restrict__ Cf,
    __half* __restrict__ Ch,
    int K, int lda, int ldb, int ldc, int Hdiv,
    long sA_b, long sA_h, long sB_b, long sB_h,
    long sC_b, long sC_h, long sBias_h, float alpha)
{
    extern __shared__ uint8_t smem[];
    int z = blockIdx.z, zb = z / Hdiv, zh_ = z - zb * Hdiv;
    const __half* Ahp = Ah + zb * sA_b + zh_ * sA_h;
    const __half* Bhp = Bh + zb * sB_b + zh_ * sB_h;
    int m0 = blockIdx.y * 128, n0 = blockIdx.x * 128;
    int tid = threadIdx.x;
    int wid = tid >> 5, lane = tid & 31;
    int g = lane >> 2, tig = lane & 3;
    int wm = (wid & 1) * 64, wn = (wid >> 1) * 64;

    uint32_t sbase = (uint32_t)__cvta_generic_to_shared(smem);

    float acc[4][8][4];
    #pragma unroll
    for (int i = 0; i < 4; ++i)
        #pragma unroll
        for (int j = 0; j < 8; ++j)
            #pragma unroll
            for (int q = 0; q < 4; ++q) acc[i][j][q] = 0.f;

    const __half* ga_h = Ahp + (long)(m0 + tid) * lda;
    const __half* gb_h = Bhp + (long)(n0 + tid) * ldb;

    int nk = K / 32;
    {
        uint32_t d = sbase + tid * 80;
        #pragma unroll
        for (int c = 0; c < 4; ++c) {
            cp16(d + c * 16,         ga_h + c * 8);
            cp16(d + 10240 + c * 16, gb_h + c * 8);
        }
        asm volatile("cp.async.commit_group;");
    }

    for (int kc = 0; kc < nk; ++kc) {
        if (kc + 1 < nk) {
            int k0 = (kc + 1) * 32;
            uint32_t d = sbase + ((kc + 1) & 1) * STGB + tid * 80;
            #pragma unroll
            for (int c = 0; c < 4; ++c) {
                cp16(d + c * 16,         ga_h + k0 + c * 8);
                cp16(d + 10240 + c * 16, gb_h + k0 + c * 8);
            }
            asm volatile("cp.async.commit_group;");
            asm volatile("cp.async.wait_group 1;");
        } else {
            asm volatile("cp.async.wait_group 0;");
        }
        __syncthreads();

        const uint8_t* sb_ = smem + (kc & 1) * STGB;
        #pragma unroll
        for (int ks = 0; ks < 2; ++ks) {
            int cb = ks * 32 + tig * 4;
            uint32_t ah[4][4];
            #pragma unroll
            for (int mt = 0; mt < 4; ++mt) {
                const uint8_t* p = sb_ + (wm + mt * 16 + g) * 80 + cb;
                ah[mt][0] = *(const uint32_t*)(p);
                ah[mt][1] = *(const uint32_t*)(p + 8 * 80);
                ah[mt][2] = *(const uint32_t*)(p + 16);
                ah[mt][3] = *(const uint32_t*)(p + 8 * 80 + 16);
            }
            #pragma unroll
            for (int nt = 0; nt < 8; ++nt) {
                const uint8_t* pb = sb_ + 10240 + (wn + nt * 8 + g) * 80 + cb;
                uint32_t bh0 = *(const uint32_t*)(pb);
                uint32_t bh1 = *(const uint32_t*)(pb + 16);
                #pragma unroll
                for (int mt = 0; mt < 4; ++mt)
                    MMA16816(acc[mt][nt], ah[mt], bh0, bh1);
            }
        }
        __syncthreads();
    }

    // epilogue
    float* Cfp = nullptr;
    __half* Chp = nullptr;
    if (OUTMODE == 0) Cfp = Cf + zb * sC_b + zh_ * sC_h;
    else Chp = Ch + zb * sC_b + zh_ * sC_h;
    const float* bias = biasb ? biasb + (long)zh_ * sBias_h : nullptr;

    #pragma unroll
    for (int nt = 0; nt < 8; ++nt) {
        int col = n0 + wn + nt * 8 + tig * 2;
        float bb0 = 0.f, bb1 = 0.f;
        if (bias) { bb0 = bias[col]; bb1 = bias[col + 1]; }
        #pragma unroll
        for (int mt = 0; mt < 4; ++mt) {
            int r0 = m0 + wm + mt * 16 + g;
            float v00 = acc[mt][nt][0] * alpha + bb0;
            float v01 = acc[mt][nt][1] * alpha + bb1;
            float v10 = acc[mt][nt][2] * alpha + bb0;
            float v11 = acc[mt][nt][3] * alpha + bb1;
            if (TANH) { v00 = tanhf(v00); v01 = tanhf(v01); v10 = tanhf(v10); v11 = tanhf(v11); }
            if (OUTMODE == 0) {
                *(float2*)(Cfp + (long)r0 * ldc + col) = make_float2(v00, v01);
                *(float2*)(Cfp + (long)(r0 + 8) * ldc + col) = make_float2(v10, v11);
            } else {
                __half2 hh;
                hh.x = __float2half(v00); hh.y = __float2half(v01);
                *(__half2*)(Chp + (long)r0 * ldc + col) = hh;
                hh.x = __float2half(v10); hh.y = __float2half(v11);
                *(__half2*)(Chp + (long)(r0 + 8) * ldc + col) = hh;
            }
        }
    }
}

// ---------------- softmax over the QUERY axis (parallelized, hi out) -----
__global__ void __launch_bounds__(512) softmax_q2(const float* __restrict__ Sc,
                                                  __half* __restrict__ oh) {
    __shared__ float sm[16][32], sl[16][32];
    long base = (long)blockIdx.x * CS * CS + blockIdx.y * 32;
    int w = threadIdx.x >> 5, lane = threadIdx.x & 31;
    const float* p = Sc + base + (long)w * 32 * CS + lane;
    float v[32];
    float m = -1e30f, l = 0.f;
    #pragma unroll
    for (int i = 0; i < 32; ++i) {
        float x = p[(long)i * CS];
        v[i] = x;
        float nm = fmaxf(m, x);
        l = l * __expf(m - nm) + __expf(x - nm);
        m = nm;
    }
    sm[w][lane] = m; sl[w][lane] = l;
    __syncthreads();
    float M = -1e30f;
    #pragma unroll
    for (int ww = 0; ww < 16; ++ww) M = fmaxf(M, sm[ww][lane]);
    float L = 0.f;
    #pragma unroll
    for (int ww = 0; ww < 16; ++ww) L += sl[ww][lane] * __expf(sm[ww][lane] - M);
    float inv = 1.f / L;
    __half* po = oh + base + (long)w * 32 * CS + lane;
    #pragma unroll
    for (int i = 0; i < 32; ++i)
        po[(long)i * CS] = __float2half(__expf(v[i] - M) * inv);
}

// ---------------- batch-norm over batch axis, fused residual add ----------
// OMODE: 0 = f32 only, 1 = f32 + fp16 hi
template<int OMODE>
__global__ void bn_kernel(const float* __restrict__ x,
                          const float* __restrict__ add, int addw,
                          float* __restrict__ out,
                          __half* __restrict__ oh) {
    int j = blockIdx.x * blockDim.x + threadIdx.x;
    if (j >= CS * CD2) return;
    const long SD = (long)CS * CD2;
    int s = j >> 10;
    int e = j & 1023;
    int ae = e & (addw - 1);
    long aoff = (long)s * addw + ae;

    float v[CB];
    float sum = 0.f;
    #pragma unroll
    for (int b = 0; b < CB; ++b) {
        float t = x[(long)b * SD + j] + add[(long)b * CS * addw + aoff];
        v[b] = t;
        sum += t;
    }
    float mean = sum * (1.f / CB);
    float var = 0.f;
    #pragma unroll
    for (int b = 0; b < CB; ++b) {
        float d = v[b] - mean;
        var += d * d;
    }
    var *= (1.f / CB);
    float rstd = rsqrtf(var + 1e-3f);
    #pragma unroll
    for (int b = 0; b < CB; ++b) {
        float o = (v[b] - mean) * rstd;
        out[(long)b * SD + j] = o;
        if (OMODE == 1)
            oh[(long)b * SD + j] = __float2half(o);
    }
}

// ---------------- host orchestration ----------------
struct Ptrs {
    float* f32;
    __half* hb;
};

static void run_attn(int Din, const __half* xh,
                     const __half* WqT, const __half* WkT, const __half* WvT,
                     const float* bq, const float* bk, const float* bv,
                     const __half* WoT, const float* bo, Ptrs p, float* aout)
{
    float* v  = p.f32 + OF_V;
    float* sc = p.f32 + OF_SC;
    __half *qh = p.hb + HB_QH;
    __half *kh = p.hb + HB_KH;
    __half *vth = p.hb + HB_VTH;
    __half *ath = p.hb + HB_ATH;
    __half *zh = p.hb + HB_ZH;

    long sAb = (long)CS * Din, sBh = (long)CDK * Din;
    long sCb = (long)CH * CS * CDK, sCh = (long)CS * CDK;
    dim3 gq(1, CS / 128, CB * CH);
    gemm3<2, false><<<gq, 128, GSMEM>>>(xh, WqT, bq, nullptr, qh,
        Din, Din, Din, CDK, CH, sAb, 0, 0, sBh, sCb, sCh, CDK, 1.f);
    gemm3<2, false><<<gq, 128, GSMEM>>>(xh, WkT, bk, nullptr, kh,
        Din, Din, Din, CDK, CH, sAb, 0, 0, sBh, sCb, sCh, CDK, 1.f);
    gemm3<0, false><<<gq, 128, GSMEM>>>(xh, WvT, bv, v, nullptr,
        Din, Din, Din, CDK, CH, sAb, 0, 0, sBh, sCb, sCh, CDK, 1.f);

    // V transpose: [z][t][dk] -> [z][dk][t]
    transpose_hi<<<dim3(CDK / 32, CS / 32, CB * CH), dim3(32, 8)>>>(v, vth, CS, CDK);

    // scores = Q @ K^T * 1/sqrt(dk)
    gemm3<0, false><<<dim3(CS / 128, CS / 128, CB * CH), 128, GSMEM>>>(
        qh, kh, nullptr, sc, nullptr,
        CDK, CDK, CDK, CS, 1,
        (long)CS * CDK, 0, (long)CS * CDK, 0, (long)CS * CS, 0, 0,
        0.08838834764831845f);

    softmax_q2<<<dim3(CB * CH, CS / 32), 512>>>(sc, ath);

    // z = attn @ V^T
    gemm3<2, false><<<dim3(1, CS / 128, CB * CH), 128, GSMEM>>>(
        ath, vth, nullptr, nullptr, zh,
        CS, CS, CS, CHD, CH,
        (long)CH * CS * CS, (long)CS * CS,
        (long)CH * CDK * CS, (long)CDK * CS,
        (long)CS * CHD, CDK, 0, 1.f);

    // out projection: (B*S,768) @ (768,1024)
    gemm3<0, false><<<dim3(CD2 / 128, (CB * CS) / 128, 1), 128, GSMEM>>>(
        zh, WoT, bo, aout, nullptr,
        CHD, CHD, CHD, CD2, 1, 0, 0, 0, 0, 0, 0, 0, 1.f);
}

extern "C" void kernel_launch(void* const* d_in, const int* in_sizes, int n_in,
                              void* d_out, int out_size)
{
    const float* X    = (const float*)d_in[0];
    const float* Wq1  = (const float*)d_in[1];
    const float* Wk1  = (const float*)d_in[2];
    const float* Wv1  = (const float*)d_in[3];
    const float* bq1  = (const float*)d_in[4];
    const float* bk1  = (const float*)d_in[5];
    const float* bv1  = (const float*)d_in[6];
    const float* Wo1  = (const float*)d_in[7];
    const float* bo1  = (const float*)d_in[8];
    const float* Wff1 = (const float*)d_in[9];
    const float* bff1 = (const float*)d_in[10];
    const float* Wq2  = (const float*)d_in[11];
    const float* Wk2  = (const float*)d_in[12];
    const float* Wv2  = (const float*)d_in[13];
    const float* bq2  = (const float*)d_in[14];
    const float* bk2  = (const float*)d_in[15];
    const float* bv2  = (const float*)d_in[16];
    const float* Wo2  = (const float*)d_in[17];
    const float* bo2  = (const float*)d_in[18];
    const float* Wff2 = (const float*)d_in[19];
    const float* bff2 = (const float*)d_in[20];
    float* out = (float*)d_out;

    float* sb = nullptr;
    cudaGetSymbolAddress((void**)&sb, g_scratch);
    Ptrs p;
    p.f32 = sb;
    p.hb = (__half*)(sb + F32_END);

    cudaFuncSetAttribute(gemm3<0, false>, cudaFuncAttributeMaxDynamicSharedMemorySize, GSMEM);
    cudaFuncSetAttribute(gemm3<2, false>, cudaFuncAttributeMaxDynamicSharedMemorySize, GSMEM);
    cudaFuncSetAttribute(gemm3<0, true>,  cudaFuncAttributeMaxDynamicSharedMemorySize, GSMEM);

    // ----- weight transpose + hi convert -----
    dim3 tb(32, 8);
    transpose_hi<<<dim3(CDK/32, CE/32, CH),   tb>>>(Wq1, p.hb+HB_W1Q, CE,  CDK);
    transpose_hi<<<dim3(CDK/32, CE/32, CH),   tb>>>(Wk1, p.hb+HB_W1K, CE,  CDK);
    transpose_hi<<<dim3(CDK/32, CE/32, CH),   tb>>>(Wv1, p.hb+HB_W1V, CE,  CDK);
    transpose_hi<<<dim3(CD2/32, CHD/32, 1),   tb>>>(Wo1, p.hb+HB_W1O, CHD, CD2);
    transpose_hi<<<dim3(CD2/32, CD2/32, 1),   tb>>>(Wff1,p.hb+HB_W1F, CD2, CD2);
    transpose_hi<<<dim3(CDK/32, CD2/32, CH),  tb>>>(Wq2, p.hb+HB_W2Q, CD2, CDK);
    transpose_hi<<<dim3(CDK/32, CD2/32, CH),  tb>>>(Wk2, p.hb+HB_W2K, CD2, CDK);
    transpose_hi<<<dim3(CDK/32, CD2/32, CH),  tb>>>(Wv2, p.hb+HB_W2V, CD2, CDK);
    transpose_hi<<<dim3(CD2/32, CHD/32, 1),   tb>>>(Wo2, p.hb+HB_W2O, CHD, CD2);
    transpose_hi<<<dim3(CD2/32, CD2/32, 1),   tb>>>(Wff2,p.hb+HB_W2F, CD2, CD2);

    // ----- positional encoding -----
    float* pos = sb + OF_POS;
    float* xp  = sb + OF_XP;
    posgen_kernel<<<(CS * CE + 255) / 256, 256>>>(pos);
    addpos_hi<<<(unsigned)((NB_XP + 255) / 256), 256>>>(X, pos, xp,
        p.hb + HB_XPH, NB_XP);

    float* a  = sb + OF_A;
    float* n1 = sb + OF_N1;
    float* n2 = sb + OF_N2;
    float* n3 = sb + OF_N3;
    float* f  = sb + OF_F;
    int nbn = (CS * CD2 + 255) / 256;
    dim3 gff(CD2 / 128, (CB * CS) / 128, 1);

    // ----- block 1: attention (Din = 512) -----
    run_attn(CE, p.hb + HB_XPH,
             p.hb+HB_W1Q, p.hb+HB_W1K, p.hb+HB_W1V, bq1, bk1, bv1,
             p.hb+HB_W1O, bo1, p, a);
    bn_kernel<1><<<nbn, 256>>>(a, xp, CE, n1, p.hb + HB_N1H);

    // ----- block 2: FFN -----
    gemm3<0, true><<<gff, 128, GSMEM>>>(
        p.hb + HB_N1H, p.hb + HB_W1F, bff1,
        f, nullptr, CD2, CD2, CD2, CD2, 1, 0, 0, 0, 0, 0, 0, 0, 1.f);
    bn_kernel<1><<<nbn, 256>>>(f, n1, CD2, n2, p.hb + HB_N2H);

    // ----- block 3: attention (Din = 1024) -----
    run_attn(CD2, p.hb + HB_N2H,
             p.hb+HB_W2Q, p.hb+HB_W2K, p.hb+HB_W2V, bq2, bk2, bv2,
             p.hb+HB_W2O, bo2, p, a);
    bn_kernel<1><<<nbn, 256>>>(a, n2, CD2, n3, p.hb + HB_N3H);

    // ----- block 4: FFN -----
    gemm3<0, true><<<gff, 128, GSMEM>>>(
        p.hb + HB_N3H, p.hb + HB_W2F, bff2,
        f, nullptr, CD2, CD2, CD2, CD2, 1, 0, 0, 0, 0, 0, 0, 0, 1.f);
    bn_kernel<0><<<nbn, 256>>>(f, n3, CD2, out, nullptr);
}

// round 11
// speedup vs baseline: 2.1216x; 1.0335x over previous
#include <cuda_runtime.h>
#include <cuda_fp16.h>
#include <cstdint>
#include <math.h>

#define CB 32
#define CS 512
#define CE 512
#define CDK 128
#define CH 6
#define CD2 1024
#define CHD 768

// ---------------- sizes (elements) ----------------
constexpr long NB_XP  = (long)CB*CS*CE;
constexpr long NB_QKV = (long)CB*CH*CS*CDK;
constexpr long NB_SC  = (long)CB*CH*CS*CS;
constexpr long NB_Z   = (long)CB*CS*CHD;
constexpr long NB_D2  = (long)CB*CS*CD2;
constexpr long NW_QKV1 = (long)CH*CE*CDK;
constexpr long NW_QKV2 = (long)CH*CD2*CDK;
constexpr long NW_O   = (long)CHD*CD2;
constexpr long NW_F   = (long)CD2*CD2;

// ---------------- f32 scratch: positional encoding only ----------------
constexpr long OF_POS = 0;
constexpr long F32_END = OF_POS + (long)CS*CE;

// ---------------- fp16 scratch offsets (half elems) ----------------
constexpr long HB_XPH = 0;
constexpr long HB_QH  = HB_XPH + NB_XP;
constexpr long HB_KH  = HB_QH + NB_QKV;
constexpr long HB_VH  = HB_KH + NB_QKV;
constexpr long HB_VTH = HB_VH + NB_QKV;
constexpr long HB_SCH = HB_VTH + NB_QKV;
constexpr long HB_ATH = HB_SCH + NB_SC;
constexpr long HB_ZH  = HB_ATH + NB_SC;
constexpr long HB_AH  = HB_ZH + NB_Z;
constexpr long HB_FH  = HB_AH + NB_D2;
constexpr long HB_N1H = HB_FH + NB_D2;
constexpr long HB_N2H = HB_N1H + NB_D2;
constexpr long HB_N3H = HB_N2H + NB_D2;
constexpr long HB_W1Q = HB_N3H + NB_D2;
constexpr long HB_W1K = HB_W1Q + NW_QKV1;
constexpr long HB_W1V = HB_W1K + NW_QKV1;
constexpr long HB_W1O = HB_W1V + NW_QKV1;
constexpr long HB_W1F = HB_W1O + NW_O;
constexpr long HB_W2Q = HB_W1F + NW_F;
constexpr long HB_W2K = HB_W2Q + NW_QKV2;
constexpr long HB_W2V = HB_W2K + NW_QKV2;
constexpr long HB_W2O = HB_W2V + NW_QKV2;
constexpr long HB_W2F = HB_W2O + NW_O;
constexpr long HB_END = HB_W2F + NW_F;

constexpr long SCRATCH_TOT = F32_END + (HB_END + 1) / 2 + 64;
__device__ float g_scratch[SCRATCH_TOT];

// ---------------- helpers ----------------
__device__ __forceinline__ void cp16(uint32_t d, const void* s) {
    asm volatile("cp.async.cg.shared.global [%0], [%1], 16;\n" :: "r"(d), "l"(s));
}

#define MMA16816(c, a, b0, b1)                                              \
    asm volatile("mma.sync.aligned.m16n8k16.row.col.f32.f16.f16.f32 "       \
                 "{%0,%1,%2,%3},{%4,%5,%6,%7},{%8,%9},{%0,%1,%2,%3};"       \
                 : "+f"((c)[0]), "+f"((c)[1]), "+f"((c)[2]), "+f"((c)[3])   \
                 : "r"((a)[0]), "r"((a)[1]), "r"((a)[2]), "r"((a)[3]),      \
                   "r"(b0), "r"(b1))

// ---------------- positional encoding ----------------
__global__ void posgen_kernel(float* __restrict__ pos) {
    int idx = blockIdx.x * blockDim.x + threadIdx.x;
    if (idx >= CS * CE) return;
    int s = idx >> 9;
    int e = idx & 511;
    int m = e >> 1;
    double ang = (m >= 128) ? ((double)s / 10000.0) : (double)s;
    pos[idx] = (e & 1) ? (float)cos(ang) : (float)sin(ang);
}

__global__ void addpos_hi(const float* __restrict__ X,
                          const float* __restrict__ pos,
                          __half* __restrict__ xh, long n) {
    long idx = (long)blockIdx.x * blockDim.x + threadIdx.x;
    if (idx >= n) return;
    xh[idx] = __float2half(X[idx] + pos[idx % (CS * CE)]);
}

// ---------------- transpose f32->hi (weights) ----------
__global__ void transpose_hi(const float* __restrict__ in,
                             __half* __restrict__ oh,
                             int R, int C) {
    __shared__ float t[32][33];
    long zo = (long)blockIdx.z * R * C;
    int c0 = blockIdx.x * 32, r0 = blockIdx.y * 32;
    int tx = threadIdx.x, ty = threadIdx.y;
    #pragma unroll
    for (int i = 0; i < 32; i += 8)
        t[ty + i][tx] = in[zo + (long)(r0 + ty + i) * C + c0 + tx];
    __syncthreads();
    #pragma unroll
    for (int i = 0; i < 32; i += 8) {
        float v = t[tx][ty + i];
        long o = zo + (long)(c0 + ty + i) * R + r0 + tx;
        oh[o] = __float2half(v);
    }
}

// ---------------- transpose fp16->fp16 (V) ----------
__global__ void transpose_hh(const __half* __restrict__ in,
                             __half* __restrict__ oh,
                             int R, int C) {
    __shared__ __half t[32][34];
    long zo = (long)blockIdx.z * R * C;
    int c0 = blockIdx.x * 32, r0 = blockIdx.y * 32;
    int tx = threadIdx.x, ty = threadIdx.y;
    #pragma unroll
    for (int i = 0; i < 32; i += 8)
        t[ty + i][tx] = in[zo + (long)(r0 + ty + i) * C + c0 + tx];
    __syncthreads();
    #pragma unroll
    for (int i = 0; i < 32; i += 8) {
        long o = zo + (long)(c0 + ty + i) * R + r0 + tx;
        oh[o] = t[tx][ty + i];
    }
}

// ---------------- fp16 tensor-core GEMM (single-pass, fp16 out) -------
// C = alpha * A_hi @ B_hi^T (+bias)(+tanh), fp16 output.
#define STGB 20480          // Ah 10240 | Bh 10240 (80B-pitch rows)
#define GSMEM (2 * STGB)    // 40960

template<bool TANH>
__global__ void __launch_bounds__(128, 2) gemm3(
    const __half* __restrict__ Ah,
    const __half* __restrict__ Bh,
    const float* __restrict__ biasb,
    __half* __restrict__ Ch,
    int K, int lda, int ldb, int ldc, int Hdiv,
    long sA_b, long sA_h, long sB_b, long sB_h,
    long sC_b, long sC_h, long sBias_h, float alpha)
{
    extern __shared__ uint8_t smem[];
    int z = blockIdx.z, zb = z / Hdiv, zh_ = z - zb * Hdiv;
    const __half* Ahp = Ah + zb * sA_b + zh_ * sA_h;
    const __half* Bhp = Bh + zb * sB_b + zh_ * sB_h;
    int m0 = blockIdx.y * 128, n0 = blockIdx.x * 128;
    int tid = threadIdx.x;
    int wid = tid >> 5, lane = tid & 31;
    int g = lane >> 2, tig = lane & 3;
    int wm = (wid & 1) * 64, wn = (wid >> 1) * 64;

    uint32_t sbase = (uint32_t)__cvta_generic_to_shared(smem);

    float acc[4][8][4];
    #pragma unroll
    for (int i = 0; i < 4; ++i)
        #pragma unroll
        for (int j = 0; j < 8; ++j)
            #pragma unroll
            for (int q = 0; q < 4; ++q) acc[i][j][q] = 0.f;

    const __half* ga_h = Ahp + (long)(m0 + tid) * lda;
    const __half* gb_h = Bhp + (long)(n0 + tid) * ldb;

    int nk = K / 32;
    {
        uint32_t d = sbase + tid * 80;
        #pragma unroll
        for (int c = 0; c < 4; ++c) {
            cp16(d + c * 16,         ga_h + c * 8);
            cp16(d + 10240 + c * 16, gb_h + c * 8);
        }
        asm volatile("cp.async.commit_group;");
    }

    for (int kc = 0; kc < nk; ++kc) {
        if (kc + 1 < nk) {
            int k0 = (kc + 1) * 32;
            uint32_t d = sbase + ((kc + 1) & 1) * STGB + tid * 80;
            #pragma unroll
            for (int c = 0; c < 4; ++c) {
                cp16(d + c * 16,         ga_h + k0 + c * 8);
                cp16(d + 10240 + c * 16, gb_h + k0 + c * 8);
            }
            asm volatile("cp.async.commit_group;");
            asm volatile("cp.async.wait_group 1;");
        } else {
            asm volatile("cp.async.wait_group 0;");
        }
        __syncthreads();

        const uint8_t* sb_ = smem + (kc & 1) * STGB;
        #pragma unroll
        for (int ks = 0; ks < 2; ++ks) {
            int cb = ks * 32 + tig * 4;
            uint32_t ah[4][4];
            #pragma unroll
            for (int mt = 0; mt < 4; ++mt) {
                const uint8_t* p = sb_ + (wm + mt * 16 + g) * 80 + cb;
                ah[mt][0] = *(const uint32_t*)(p);
                ah[mt][1] = *(const uint32_t*)(p + 8 * 80);
                ah[mt][2] = *(const uint32_t*)(p + 16);
                ah[mt][3] = *(const uint32_t*)(p + 8 * 80 + 16);
            }
            #pragma unroll
            for (int nt = 0; nt < 8; ++nt) {
                const uint8_t* pb = sb_ + 10240 + (wn + nt * 8 + g) * 80 + cb;
                uint32_t bh0 = *(const uint32_t*)(pb);
                uint32_t bh1 = *(const uint32_t*)(pb + 16);
                #pragma unroll
                for (int mt = 0; mt < 4; ++mt)
                    MMA16816(acc[mt][nt], ah[mt], bh0, bh1);
            }
        }
        __syncthreads();
    }

    // epilogue (fp16 out)
    __half* Chp = Ch + zb * sC_b + zh_ * sC_h;
    const float* bias = biasb ? biasb + (long)zh_ * sBias_h : nullptr;

    #pragma unroll
    for (int nt = 0; nt < 8; ++nt) {
        int col = n0 + wn + nt * 8 + tig * 2;
        float bb0 = 0.f, bb1 = 0.f;
        if (bias) { bb0 = bias[col]; bb1 = bias[col + 1]; }
        #pragma unroll
        for (int mt = 0; mt < 4; ++mt) {
            int r0 = m0 + wm + mt * 16 + g;
            float v00 = acc[mt][nt][0] * alpha + bb0;
            float v01 = acc[mt][nt][1] * alpha + bb1;
            float v10 = acc[mt][nt][2] * alpha + bb0;
            float v11 = acc[mt][nt][3] * alpha + bb1;
            if (TANH) { v00 = tanhf(v00); v01 = tanhf(v01); v10 = tanhf(v10); v11 = tanhf(v11); }
            __half2 hh;
            hh.x = __float2half(v00); hh.y = __float2half(v01);
            *(__half2*)(Chp + (long)r0 * ldc + col) = hh;
            hh.x = __float2half(v10); hh.y = __float2half(v11);
            *(__half2*)(Chp + (long)(r0 + 8) * ldc + col) = hh;
        }
    }
}

// ---------------- softmax over the QUERY axis (fp16 in/out) ----------
__global__ void __launch_bounds__(512) softmax_q2(const __half* __restrict__ Sc,
                                                  __half* __restrict__ oh) {
    __shared__ float sm[16][32], sl[16][32];
    long base = (long)blockIdx.x * CS * CS + blockIdx.y * 32;
    int w = threadIdx.x >> 5, lane = threadIdx.x & 31;
    const __half* p = Sc + base + (long)w * 32 * CS + lane;
    float v[32];
    float m = -1e30f, l = 0.f;
    #pragma unroll
    for (int i = 0; i < 32; ++i) {
        float x = __half2float(p[(long)i * CS]);
        v[i] = x;
        float nm = fmaxf(m, x);
        l = l * __expf(m - nm) + __expf(x - nm);
        m = nm;
    }
    sm[w][lane] = m; sl[w][lane] = l;
    __syncthreads();
    float M = -1e30f;
    #pragma unroll
    for (int ww = 0; ww < 16; ++ww) M = fmaxf(M, sm[ww][lane]);
    float L = 0.f;
    #pragma unroll
    for (int ww = 0; ww < 16; ++ww) L += sl[ww][lane] * __expf(sm[ww][lane] - M);
    float inv = 1.f / L;
    __half* po = oh + base + (long)w * 32 * CS + lane;
    #pragma unroll
    for (int i = 0; i < 32; ++i)
        po[(long)i * CS] = __float2half(__expf(v[i] - M) * inv);
}

// ---------------- batch-norm (fp16 in, fused residual), stats in f32 ----
// OMODE: 0 = write f32 (final output), 1 = write fp16 hi
template<int OMODE>
__global__ void bn16(const __half* __restrict__ x,
                     const __half* __restrict__ add, int addw,
                     float* __restrict__ outf,
                     __half* __restrict__ oh) {
    int j = blockIdx.x * blockDim.x + threadIdx.x;
    if (j >= CS * CD2) return;
    const long SD = (long)CS * CD2;
    int s = j >> 10;
    int e = j & 1023;
    int ae = e & (addw - 1);
    long aoff = (long)s * addw + ae;

    float v[CB];
    float sum = 0.f;
    #pragma unroll
    for (int b = 0; b < CB; ++b) {
        float t = __half2float(x[(long)b * SD + j]) +
                  __half2float(add[(long)b * CS * addw + aoff]);
        v[b] = t;
        sum += t;
    }
    float mean = sum * (1.f / CB);
    float var = 0.f;
    #pragma unroll
    for (int b = 0; b < CB; ++b) {
        float d = v[b] - mean;
        var += d * d;
    }
    var *= (1.f / CB);
    float rstd = rsqrtf(var + 1e-3f);
    #pragma unroll
    for (int b = 0; b < CB; ++b) {
        float o = (v[b] - mean) * rstd;
        if (OMODE == 0) outf[(long)b * SD + j] = o;
        else            oh[(long)b * SD + j] = __float2half(o);
    }
}

// ---------------- host orchestration ----------------
struct Ptrs {
    float* f32;
    __half* hb;
};

static void run_attn(int Din, const __half* xh,
                     const __half* WqT, const __half* WkT, const __half* WvT,
                     const float* bq, const float* bk, const float* bv,
                     const __half* WoT, const float* bo, Ptrs p, __half* aout)
{
    __half *qh = p.hb + HB_QH;
    __half *kh = p.hb + HB_KH;
    __half *vh = p.hb + HB_VH;
    __half *vth = p.hb + HB_VTH;
    __half *sch = p.hb + HB_SCH;
    __half *ath = p.hb + HB_ATH;
    __half *zh = p.hb + HB_ZH;

    long sAb = (long)CS * Din, sBh = (long)CDK * Din;
    long sCb = (long)CH * CS * CDK, sCh = (long)CS * CDK;
    dim3 gq(1, CS / 128, CB * CH);
    gemm3<false><<<gq, 128, GSMEM>>>(xh, WqT, bq, qh,
        Din, Din, Din, CDK, CH, sAb, 0, 0, sBh, sCb, sCh, CDK, 1.f);
    gemm3<false><<<gq, 128, GSMEM>>>(xh, WkT, bk, kh,
        Din, Din, Din, CDK, CH, sAb, 0, 0, sBh, sCb, sCh, CDK, 1.f);
    gemm3<false><<<gq, 128, GSMEM>>>(xh, WvT, bv, vh,
        Din, Din, Din, CDK, CH, sAb, 0, 0, sBh, sCb, sCh, CDK, 1.f);

    // V transpose: [z][t][dk] -> [z][dk][t]
    transpose_hh<<<dim3(CDK / 32, CS / 32, CB * CH), dim3(32, 8)>>>(vh, vth, CS, CDK);

    // scores = Q @ K^T * 1/sqrt(dk) -> fp16
    gemm3<false><<<dim3(CS / 128, CS / 128, CB * CH), 128, GSMEM>>>(
        qh, kh, nullptr, sch,
        CDK, CDK, CDK, CS, 1,
        (long)CS * CDK, 0, (long)CS * CDK, 0, (long)CS * CS, 0, 0,
        0.08838834764831845f);

    softmax_q2<<<dim3(CB * CH, CS / 32), 512>>>(sch, ath);

    // z = attn @ V^T
    gemm3<false><<<dim3(1, CS / 128, CB * CH), 128, GSMEM>>>(
        ath, vth, nullptr, zh,
        CS, CS, CS, CHD, CH,
        (long)CH * CS * CS, (long)CS * CS,
        (long)CH * CDK * CS, (long)CDK * CS,
        (long)CS * CHD, CDK, 0, 1.f);

    // out projection: (B*S,768) @ (768,1024) -> fp16
    gemm3<false><<<dim3(CD2 / 128, (CB * CS) / 128, 1), 128, GSMEM>>>(
        zh, WoT, bo, aout,
        CHD, CHD, CHD, CD2, 1, 0, 0, 0, 0, 0, 0, 0, 1.f);
}

extern "C" void kernel_launch(void* const* d_in, const int* in_sizes, int n_in,
                              void* d_out, int out_size)
{
    const float* X    = (const float*)d_in[0];
    const float* Wq1  = (const float*)d_in[1];
    const float* Wk1  = (const float*)d_in[2];
    const float* Wv1  = (const float*)d_in[3];
    const float* bq1  = (const float*)d_in[4];
    const float* bk1  = (const float*)d_in[5];
    const float* bv1  = (const float*)d_in[6];
    const float* Wo1  = (const float*)d_in[7];
    const float* bo1  = (const float*)d_in[8];
    const float* Wff1 = (const float*)d_in[9];
    const float* bff1 = (const float*)d_in[10];
    const float* Wq2  = (const float*)d_in[11];
    const float* Wk2  = (const float*)d_in[12];
    const float* Wv2  = (const float*)d_in[13];
    const float* bq2  = (const float*)d_in[14];
    const float* bk2  = (const float*)d_in[15];
    const float* bv2  = (const float*)d_in[16];
    const float* Wo2  = (const float*)d_in[17];
    const float* bo2  = (const float*)d_in[18];
    const float* Wff2 = (const float*)d_in[19];
    const float* bff2 = (const float*)d_in[20];
    float* out = (float*)d_out;

    float* sb = nullptr;
    cudaGetSymbolAddress((void**)&sb, g_scratch);
    Ptrs p;
    p.f32 = sb;
    p.hb = (__half*)(sb + F32_END);

    cudaFuncSetAttribute(gemm3<false>, cudaFuncAttributeMaxDynamicSharedMemorySize, GSMEM);
    cudaFuncSetAttribute(gemm3<true>,  cudaFuncAttributeMaxDynamicSharedMemorySize, GSMEM);

    // ----- weight transpose + hi convert -----
    dim3 tb(32, 8);
    transpose_hi<<<dim3(CDK/32, CE/32, CH),   tb>>>(Wq1, p.hb+HB_W1Q, CE,  CDK);
    transpose_hi<<<dim3(CDK/32, CE/32, CH),   tb>>>(Wk1, p.hb+HB_W1K, CE,  CDK);
    transpose_hi<<<dim3(CDK/32, CE/32, CH),   tb>>>(Wv1, p.hb+HB_W1V, CE,  CDK);
    transpose_hi<<<dim3(CD2/32, CHD/32, 1),   tb>>>(Wo1, p.hb+HB_W1O, CHD, CD2);
    transpose_hi<<<dim3(CD2/32, CD2/32, 1),   tb>>>(Wff1,p.hb+HB_W1F, CD2, CD2);
    transpose_hi<<<dim3(CDK/32, CD2/32, CH),  tb>>>(Wq2, p.hb+HB_W2Q, CD2, CDK);
    transpose_hi<<<dim3(CDK/32, CD2/32, CH),  tb>>>(Wk2, p.hb+HB_W2K, CD2, CDK);
    transpose_hi<<<dim3(CDK/32, CD2/32, CH),  tb>>>(Wv2, p.hb+HB_W2V, CD2, CDK);
    transpose_hi<<<dim3(CD2/32, CHD/32, 1),   tb>>>(Wo2, p.hb+HB_W2O, CHD, CD2);
    transpose_hi<<<dim3(CD2/32, CD2/32, 1),   tb>>>(Wff2,p.hb+HB_W2F, CD2, CD2);

    // ----- positional encoding -----
    float* pos = sb + OF_POS;
    posgen_kernel<<<(CS * CE + 255) / 256, 256>>>(pos);
    addpos_hi<<<(unsigned)((NB_XP + 255) / 256), 256>>>(X, pos,
        p.hb + HB_XPH, NB_XP);

    __half* ah  = p.hb + HB_AH;
    __half* fh  = p.hb + HB_FH;
    __half* n1h = p.hb + HB_N1H;
    __half* n2h = p.hb + HB_N2H;
    __half* n3h = p.hb + HB_N3H;
    int nbn = (CS * CD2 + 255) / 256;
    dim3 gff(CD2 / 128, (CB * CS) / 128, 1);

    // ----- block 1: attention (Din = 512) -----
    run_attn(CE, p.hb + HB_XPH,
             p.hb+HB_W1Q, p.hb+HB_W1K, p.hb+HB_W1V, bq1, bk1, bv1,
             p.hb+HB_W1O, bo1, p, ah);
    bn16<1><<<nbn, 256>>>(ah, p.hb + HB_XPH, CE, nullptr, n1h);

    // ----- block 2: FFN -----
    gemm3<true><<<gff, 128, GSMEM>>>(
        n1h, p.hb + HB_W1F, bff1, fh,
        CD2, CD2, CD2, CD2, 1, 0, 0, 0, 0, 0, 0, 0, 1.f);
    bn16<1><<<nbn, 256>>>(fh, n1h, CD2, nullptr, n2h);

    // ----- block 3: attention (Din = 1024) -----
    run_attn(CD2, n2h,
             p.hb+HB_W2Q, p.hb+HB_W2K, p.hb+HB_W2V, bq2, bk2, bv2,
             p.hb+HB_W2O, bo2, p, ah);
    bn16<1><<<nbn, 256>>>(ah, n2h, CD2, nullptr, n3h);

    // ----- block 4: FFN -----
    gemm3<true><<<gff, 128, GSMEM>>>(
        n3h, p.hb + HB_W2F, bff2, fh,
        CD2, CD2, CD2, CD2, 1, 0, 0, 0, 0, 0, 0, 0, 1.f);
    bn16<0><<<nbn, 256>>>(fh, n3h, CD2, out, nullptr);
}

// round 12
// speedup vs baseline: 2.2016x; 1.0377x over previous
#include <cuda_runtime.h>
#include <cuda_fp16.h>
#include <cstdint>
#include <math.h>

#define CB 32
#define CS 512
#define CE 512
#define CDK 128
#define CH 6
#define CD2 1024
#define CHD 768

// ---------------- sizes (elements) ----------------
constexpr long NB_XP  = (long)CB*CS*CE;
constexpr long NB_QKV = (long)CB*CH*CS*CDK;
constexpr long NB_SC  = (long)CB*CH*CS*CS;
constexpr long NB_Z   = (long)CB*CS*CHD;
constexpr long NB_D2  = (long)CB*CS*CD2;
constexpr long NW_QKV1 = (long)CH*CE*CDK;
constexpr long NW_QKV2 = (long)CH*CD2*CDK;
constexpr long NW_O   = (long)CHD*CD2;
constexpr long NW_F   = (long)CD2*CD2;

// ---------------- f32 scratch: positional encoding only ----------------
constexpr long OF_POS = 0;
constexpr long F32_END = OF_POS + (long)CS*CE;

// ---------------- fp16 scratch offsets (half elems) ----------------
constexpr long HB_XPH = 0;
constexpr long HB_QH  = HB_XPH + NB_XP;
constexpr long HB_KH  = HB_QH + NB_QKV;
constexpr long HB_VH  = HB_KH + NB_QKV;
constexpr long HB_VTH = HB_VH + NB_QKV;
constexpr long HB_SCH = HB_VTH + NB_QKV;
constexpr long HB_ATH = HB_SCH + NB_SC;
constexpr long HB_ZH  = HB_ATH + NB_SC;
constexpr long HB_AH  = HB_ZH + NB_Z;
constexpr long HB_FH  = HB_AH + NB_D2;
constexpr long HB_N1H = HB_FH + NB_D2;
constexpr long HB_N2H = HB_N1H + NB_D2;
constexpr long HB_N3H = HB_N2H + NB_D2;
constexpr long HB_W1Q = HB_N3H + NB_D2;
constexpr long HB_W1K = HB_W1Q + NW_QKV1;
constexpr long HB_W1V = HB_W1K + NW_QKV1;
constexpr long HB_W1O = HB_W1V + NW_QKV1;
constexpr long HB_W1F = HB_W1O + NW_O;
constexpr long HB_W2Q = HB_W1F + NW_F;
constexpr long HB_W2K = HB_W2Q + NW_QKV2;
constexpr long HB_W2V = HB_W2K + NW_QKV2;
constexpr long HB_W2O = HB_W2V + NW_QKV2;
constexpr long HB_W2F = HB_W2O + NW_O;
constexpr long HB_END = HB_W2F + NW_F;

constexpr long SCRATCH_TOT = F32_END + (HB_END + 1) / 2 + 64;
__device__ float g_scratch[SCRATCH_TOT];

// ---------------- helpers ----------------
__device__ __forceinline__ void cp16(uint32_t d, const void* s) {
    asm volatile("cp.async.cg.shared.global [%0], [%1], 16;\n" :: "r"(d), "l"(s));
}

#define MMA16816(c, a, b0, b1)                                              \
    asm volatile("mma.sync.aligned.m16n8k16.row.col.f32.f16.f16.f32 "       \
                 "{%0,%1,%2,%3},{%4,%5,%6,%7},{%8,%9},{%0,%1,%2,%3};"       \
                 : "+f"((c)[0]), "+f"((c)[1]), "+f"((c)[2]), "+f"((c)[3])   \
                 : "r"((a)[0]), "r"((a)[1]), "r"((a)[2]), "r"((a)[3]),      \
                   "r"(b0), "r"(b1))

// ---------------- positional encoding ----------------
__global__ void posgen_kernel(float* __restrict__ pos) {
    int idx = blockIdx.x * blockDim.x + threadIdx.x;
    if (idx >= CS * CE) return;
    int s = idx >> 9;
    int e = idx & 511;
    int m = e >> 1;
    double ang = (m >= 128) ? ((double)s / 10000.0) : (double)s;
    pos[idx] = (e & 1) ? (float)cos(ang) : (float)sin(ang);
}

__global__ void addpos_hi(const float* __restrict__ X,
                          const float* __restrict__ pos,
                          __half* __restrict__ xh, long n) {
    long idx = (long)blockIdx.x * blockDim.x + threadIdx.x;
    if (idx >= n) return;
    xh[idx] = __float2half(X[idx] + pos[idx % (CS * CE)]);
}

// ---------------- transpose f32->hi (weights) ----------
__global__ void transpose_hi(const float* __restrict__ in,
                             __half* __restrict__ oh,
                             int R, int C) {
    __shared__ float t[32][33];
    long zo = (long)blockIdx.z * R * C;
    int c0 = blockIdx.x * 32, r0 = blockIdx.y * 32;
    int tx = threadIdx.x, ty = threadIdx.y;
    #pragma unroll
    for (int i = 0; i < 32; i += 8)
        t[ty + i][tx] = in[zo + (long)(r0 + ty + i) * C + c0 + tx];
    __syncthreads();
    #pragma unroll
    for (int i = 0; i < 32; i += 8) {
        float v = t[tx][ty + i];
        long o = zo + (long)(c0 + ty + i) * R + r0 + tx;
        oh[o] = __float2half(v);
    }
}

// ---------------- transpose fp16->fp16 (V) ----------
__global__ void transpose_hh(const __half* __restrict__ in,
                             __half* __restrict__ oh,
                             int R, int C) {
    __shared__ __half t[32][34];
    long zo = (long)blockIdx.z * R * C;
    int c0 = blockIdx.x * 32, r0 = blockIdx.y * 32;
    int tx = threadIdx.x, ty = threadIdx.y;
    #pragma unroll
    for (int i = 0; i < 32; i += 8)
        t[ty + i][tx] = in[zo + (long)(r0 + ty + i) * C + c0 + tx];
    __syncthreads();
    #pragma unroll
    for (int i = 0; i < 32; i += 8) {
        long o = zo + (long)(c0 + ty + i) * R + r0 + tx;
        oh[o] = t[tx][ty + i];
    }
}

// ================== GEMM core (shared device body) ==================
#define STGB 20480          // Ah 10240 | Bh 10240 (80B-pitch rows)
#define GSMEM (2 * STGB)    // 40960

template<bool TANH>
__device__ __forceinline__ void gemm_body(
    uint8_t* smem, const __half* ga_h, const __half* gb_h,
    const float* bias, __half* Chp,
    int K, int ldc, int m0, int n0, float alpha,
    int tid, int wid, int lane)
{
    int g = lane >> 2, tig = lane & 3;
    int wm = (wid & 1) * 64, wn = (wid >> 1) * 64;
    uint32_t sbase = (uint32_t)__cvta_generic_to_shared(smem);

    float acc[4][8][4];
    #pragma unroll
    for (int i = 0; i < 4; ++i)
        #pragma unroll
        for (int j = 0; j < 8; ++j)
            #pragma unroll
            for (int q = 0; q < 4; ++q) acc[i][j][q] = 0.f;

    int nk = K / 32;
    {
        uint32_t d = sbase + tid * 80;
        #pragma unroll
        for (int c = 0; c < 4; ++c) {
            cp16(d + c * 16,         ga_h + c * 8);
            cp16(d + 10240 + c * 16, gb_h + c * 8);
        }
        asm volatile("cp.async.commit_group;");
    }

    for (int kc = 0; kc < nk; ++kc) {
        if (kc + 1 < nk) {
            int k0 = (kc + 1) * 32;
            uint32_t d = sbase + ((kc + 1) & 1) * STGB + tid * 80;
            #pragma unroll
            for (int c = 0; c < 4; ++c) {
                cp16(d + c * 16,         ga_h + k0 + c * 8);
                cp16(d + 10240 + c * 16, gb_h + k0 + c * 8);
            }
            asm volatile("cp.async.commit_group;");
            asm volatile("cp.async.wait_group 1;");
        } else {
            asm volatile("cp.async.wait_group 0;");
        }
        __syncthreads();

        const uint8_t* sb_ = smem + (kc & 1) * STGB;
        #pragma unroll
        for (int ks = 0; ks < 2; ++ks) {
            int cb = ks * 32 + tig * 4;
            uint32_t ah[4][4];
            #pragma unroll
            for (int mt = 0; mt < 4; ++mt) {
                const uint8_t* p = sb_ + (wm + mt * 16 + g) * 80 + cb;
                ah[mt][0] = *(const uint32_t*)(p);
                ah[mt][1] = *(const uint32_t*)(p + 8 * 80);
                ah[mt][2] = *(const uint32_t*)(p + 16);
                ah[mt][3] = *(const uint32_t*)(p + 8 * 80 + 16);
            }
            #pragma unroll
            for (int nt = 0; nt < 8; ++nt) {
                const uint8_t* pb = sb_ + 10240 + (wn + nt * 8 + g) * 80 + cb;
                uint32_t bh0 = *(const uint32_t*)(pb);
                uint32_t bh1 = *(const uint32_t*)(pb + 16);
                #pragma unroll
                for (int mt = 0; mt < 4; ++mt)
                    MMA16816(acc[mt][nt], ah[mt], bh0, bh1);
            }
        }
        __syncthreads();
    }

    #pragma unroll
    for (int nt = 0; nt < 8; ++nt) {
        int col = n0 + wn + nt * 8 + tig * 2;
        float bb0 = 0.f, bb1 = 0.f;
        if (bias) { bb0 = bias[col - n0]; bb1 = bias[col - n0 + 1]; }
        #pragma unroll
        for (int mt = 0; mt < 4; ++mt) {
            int r0 = m0 + wm + mt * 16 + g;
            float v00 = acc[mt][nt][0] * alpha + bb0;
            float v01 = acc[mt][nt][1] * alpha + bb1;
            float v10 = acc[mt][nt][2] * alpha + bb0;
            float v11 = acc[mt][nt][3] * alpha + bb1;
            if (TANH) { v00 = tanhf(v00); v01 = tanhf(v01); v10 = tanhf(v10); v11 = tanhf(v11); }
            __half2 hh;
            hh.x = __float2half(v00); hh.y = __float2half(v01);
            *(__half2*)(Chp + (long)r0 * ldc + col) = hh;
            hh.x = __float2half(v10); hh.y = __float2half(v11);
            *(__half2*)(Chp + (long)(r0 + 8) * ldc + col) = hh;
        }
    }
}

// ---------------- generic GEMM (fp16 out) ----------------
template<bool TANH>
__global__ void __launch_bounds__(128, 2) gemm3(
    const __half* __restrict__ Ah,
    const __half* __restrict__ Bh,
    const float* __restrict__ biasb,
    __half* __restrict__ Ch,
    int K, int lda, int ldb, int ldc, int Hdiv,
    long sA_b, long sA_h, long sB_b, long sB_h,
    long sC_b, long sC_h, long sBias_h, float alpha)
{
    extern __shared__ uint8_t smem[];
    int z = blockIdx.z, zb = z / Hdiv, zh_ = z - zb * Hdiv;
    int m0 = blockIdx.y * 128, n0 = blockIdx.x * 128;
    int tid = threadIdx.x, wid = tid >> 5, lane = tid & 31;
    const __half* ga = Ah + zb * sA_b + zh_ * sA_h + (long)(m0 + tid) * lda;
    const __half* gb = Bh + zb * sB_b + zh_ * sB_h + (long)(n0 + tid) * ldb;
    __half* Chp = Ch + zb * sC_b + zh_ * sC_h;
    const float* bias = biasb ? biasb + (long)zh_ * sBias_h + n0 : nullptr;
    gemm_body<TANH>(smem, ga, gb, bias, Chp, K, ldc, m0, n0, alpha, tid, wid, lane);
}

// ---------------- merged QKV GEMM: blockIdx.x selects q/k/v -------------
__global__ void __launch_bounds__(128, 2) gemm_qkv(
    const __half* __restrict__ Ah,
    const __half* __restrict__ Bq, const __half* __restrict__ Bk,
    const __half* __restrict__ Bv,
    const float* __restrict__ bq, const float* __restrict__ bk,
    const float* __restrict__ bv,
    __half* __restrict__ Cq, __half* __restrict__ Ck, __half* __restrict__ Cv,
    int K)   // K = Din; lda=K, ldb=K, ldc=CDK
{
    extern __shared__ uint8_t smem[];
    int sel = blockIdx.x;
    int z = blockIdx.z, zb = z / CH, zh_ = z - zb * CH;
    int m0 = blockIdx.y * 128;
    int tid = threadIdx.x, wid = tid >> 5, lane = tid & 31;

    const __half* Bh = (sel == 0) ? Bq : (sel == 1) ? Bk : Bv;
    const float* bb  = (sel == 0) ? bq : (sel == 1) ? bk : bv;
    __half* Ch       = (sel == 0) ? Cq : (sel == 1) ? Ck : Cv;

    long sA_b = (long)CS * K;            // per-batch A stride
    long sB_h = (long)CDK * K;           // per-head weight stride
    long sC_b = (long)CH * CS * CDK;
    long sC_h = (long)CS * CDK;

    const __half* ga = Ah + zb * sA_b + (long)(m0 + tid) * K;
    const __half* gb = Bh + zh_ * sB_h + (long)tid * K;
    __half* Chp = Ch + zb * sC_b + zh_ * sC_h;
    const float* bias = bb + (long)zh_ * CDK;
    gemm_body<false>(smem, ga, gb, bias, Chp, K, CDK, m0, 0, 1.f, tid, wid, lane);
}

// ---------------- softmax over the QUERY axis (half2 vectorized) ------
// grid (CB*CH, CS/64); block 512 = 16 warps; each lane owns 2 columns.
__global__ void __launch_bounds__(512) softmax_q2(const __half* __restrict__ Sc,
                                                  __half* __restrict__ oh) {
    __shared__ float2 sm[16][32], sl[16][32];
    long base = (long)blockIdx.x * CS * CS + blockIdx.y * 64;
    int w = threadIdx.x >> 5, lane = threadIdx.x & 31;
    const __half* p = Sc + base + (long)w * 32 * CS + lane * 2;
    float v0[32], v1[32];
    float m0 = -1e30f, l0 = 0.f, m1 = -1e30f, l1 = 0.f;
    #pragma unroll
    for (int i = 0; i < 32; ++i) {
        __half2 x2 = *(const __half2*)(p + (long)i * CS);
        float x0 = __half2float(x2.x), x1 = __half2float(x2.y);
        v0[i] = x0; v1[i] = x1;
        float nm0 = fmaxf(m0, x0);
        l0 = l0 * __expf(m0 - nm0) + __expf(x0 - nm0);
        m0 = nm0;
        float nm1 = fmaxf(m1, x1);
        l1 = l1 * __expf(m1 - nm1) + __expf(x1 - nm1);
        m1 = nm1;
    }
    sm[w][lane] = make_float2(m0, m1);
    sl[w][lane] = make_float2(l0, l1);
    __syncthreads();
    float M0 = -1e30f, M1 = -1e30f;
    #pragma unroll
    for (int ww = 0; ww < 16; ++ww) {
        M0 = fmaxf(M0, sm[ww][lane].x);
        M1 = fmaxf(M1, sm[ww][lane].y);
    }
    float L0 = 0.f, L1 = 0.f;
    #pragma unroll
    for (int ww = 0; ww < 16; ++ww) {
        L0 += sl[ww][lane].x * __expf(sm[ww][lane].x - M0);
        L1 += sl[ww][lane].y * __expf(sm[ww][lane].y - M1);
    }
    float inv0 = 1.f / L0, inv1 = 1.f / L1;
    __half* po = oh + base + (long)w * 32 * CS + lane * 2;
    #pragma unroll
    for (int i = 0; i < 32; ++i) {
        __half2 e2;
        e2.x = __float2half(__expf(v0[i] - M0) * inv0);
        e2.y = __float2half(__expf(v1[i] - M1) * inv1);
        *(__half2*)(po + (long)i * CS) = e2;
    }
}

// ---------------- batch-norm (half2 vectorized) ----------
// OMODE: 0 = write f32 (final output), 1 = write fp16 hi
template<int OMODE>
__global__ void bn16(const __half* __restrict__ x,
                     const __half* __restrict__ add, int addw,
                     float* __restrict__ outf,
                     __half* __restrict__ oh) {
    int j2 = blockIdx.x * blockDim.x + threadIdx.x;
    if (j2 >= CS * CD2 / 2) return;
    int j = j2 * 2;
    const long SD = (long)CS * CD2;
    int s = j >> 10;
    int e = j & 1023;
    int ae = e & (addw - 1);
    long aoff = (long)s * addw + ae;

    float v0[CB], v1[CB];
    float sum0 = 0.f, sum1 = 0.f;
    #pragma unroll
    for (int b = 0; b < CB; ++b) {
        __half2 xa = *(const __half2*)(x + (long)b * SD + j);
        __half2 ad = *(const __half2*)(add + (long)b * CS * addw + aoff);
        float t0 = __half2float(xa.x) + __half2float(ad.x);
        float t1 = __half2float(xa.y) + __half2float(ad.y);
        v0[b] = t0; v1[b] = t1;
        sum0 += t0; sum1 += t1;
    }
    float mean0 = sum0 * (1.f / CB), mean1 = sum1 * (1.f / CB);
    float var0 = 0.f, var1 = 0.f;
    #pragma unroll
    for (int b = 0; b < CB; ++b) {
        float d0 = v0[b] - mean0, d1 = v1[b] - mean1;
        var0 += d0 * d0; var1 += d1 * d1;
    }
    float rstd0 = rsqrtf(var0 * (1.f / CB) + 1e-3f);
    float rstd1 = rsqrtf(var1 * (1.f / CB) + 1e-3f);
    #pragma unroll
    for (int b = 0; b < CB; ++b) {
        float o0 = (v0[b] - mean0) * rstd0;
        float o1 = (v1[b] - mean1) * rstd1;
        if (OMODE == 0) {
            *(float2*)(outf + (long)b * SD + j) = make_float2(o0, o1);
        } else {
            __half2 hh;
            hh.x = __float2half(o0); hh.y = __float2half(o1);
            *(__half2*)(oh + (long)b * SD + j) = hh;
        }
    }
}

// ---------------- host orchestration ----------------
struct Ptrs {
    float* f32;
    __half* hb;
};

static void run_attn(int Din, const __half* xh,
                     const __half* WqT, const __half* WkT, const __half* WvT,
                     const float* bq, const float* bk, const float* bv,
                     const __half* WoT, const float* bo, Ptrs p, __half* aout)
{
    __half *qh = p.hb + HB_QH;
    __half *kh = p.hb + HB_KH;
    __half *vh = p.hb + HB_VH;
    __half *vth = p.hb + HB_VTH;
    __half *sch = p.hb + HB_SCH;
    __half *ath = p.hb + HB_ATH;
    __half *zh = p.hb + HB_ZH;

    // merged QKV: one launch, 2304 CTAs
    gemm_qkv<<<dim3(3, CS / 128, CB * CH), 128, GSMEM>>>(
        xh, WqT, WkT, WvT, bq, bk, bv, qh, kh, vh, Din);

    // V transpose: [z][t][dk] -> [z][dk][t]
    transpose_hh<<<dim3(CDK / 32, CS / 32, CB * CH), dim3(32, 8)>>>(vh, vth, CS, CDK);

    // scores = Q @ K^T * 1/sqrt(dk) -> fp16
    gemm3<false><<<dim3(CS / 128, CS / 128, CB * CH), 128, GSMEM>>>(
        qh, kh, nullptr, sch,
        CDK, CDK, CDK, CS, 1,
        (long)CS * CDK, 0, (long)CS * CDK, 0, (long)CS * CS, 0, 0,
        0.08838834764831845f);

    softmax_q2<<<dim3(CB * CH, CS / 64), 512>>>(sch, ath);

    // z = attn @ V^T
    gemm3<false><<<dim3(1, CS / 128, CB * CH), 128, GSMEM>>>(
        ath, vth, nullptr, zh,
        CS, CS, CS, CHD, CH,
        (long)CH * CS * CS, (long)CS * CS,
        (long)CH * CDK * CS, (long)CDK * CS,
        (long)CS * CHD, CDK, 0, 1.f);

    // out projection: (B*S,768) @ (768,1024) -> fp16
    gemm3<false><<<dim3(CD2 / 128, (CB * CS) / 128, 1), 128, GSMEM>>>(
        zh, WoT, bo, aout,
        CHD, CHD, CHD, CD2, 1, 0, 0, 0, 0, 0, 0, 0, 1.f);
}

extern "C" void kernel_launch(void* const* d_in, const int* in_sizes, int n_in,
                              void* d_out, int out_size)
{
    const float* X    = (const float*)d_in[0];
    const float* Wq1  = (const float*)d_in[1];
    const float* Wk1  = (const float*)d_in[2];
    const float* Wv1  = (const float*)d_in[3];
    const float* bq1  = (const float*)d_in[4];
    const float* bk1  = (const float*)d_in[5];
    const float* bv1  = (const float*)d_in[6];
    const float* Wo1  = (const float*)d_in[7];
    const float* bo1  = (const float*)d_in[8];
    const float* Wff1 = (const float*)d_in[9];
    const float* bff1 = (const float*)d_in[10];
    const float* Wq2  = (const float*)d_in[11];
    const float* Wk2  = (const float*)d_in[12];
    const float* Wv2  = (const float*)d_in[13];
    const float* bq2  = (const float*)d_in[14];
    const float* bk2  = (const float*)d_in[15];
    const float* bv2  = (const float*)d_in[16];
    const float* Wo2  = (const float*)d_in[17];
    const float* bo2  = (const float*)d_in[18];
    const float* Wff2 = (const float*)d_in[19];
    const float* bff2 = (const float*)d_in[20];
    float* out = (float*)d_out;

    float* sb = nullptr;
    cudaGetSymbolAddress((void**)&sb, g_scratch);
    Ptrs p;
    p.f32 = sb;
    p.hb = (__half*)(sb + F32_END);

    cudaFuncSetAttribute(gemm3<false>, cudaFuncAttributeMaxDynamicSharedMemorySize, GSMEM);
    cudaFuncSetAttribute(gemm3<true>,  cudaFuncAttributeMaxDynamicSharedMemorySize, GSMEM);
    cudaFuncSetAttribute(gemm_qkv,     cudaFuncAttributeMaxDynamicSharedMemorySize, GSMEM);

    // ----- weight transpose + hi convert -----
    dim3 tb(32, 8);
    transpose_hi<<<dim3(CDK/32, CE/32, CH),   tb>>>(Wq1, p.hb+HB_W1Q, CE,  CDK);
    transpose_hi<<<dim3(CDK/32, CE/32, CH),   tb>>>(Wk1, p.hb+HB_W1K, CE,  CDK);
    transpose_hi<<<dim3(CDK/32, CE/32, CH),   tb>>>(Wv1, p.hb+HB_W1V, CE,  CDK);
    transpose_hi<<<dim3(CD2/32, CHD/32, 1),   tb>>>(Wo1, p.hb+HB_W1O, CHD, CD2);
    transpose_hi<<<dim3(CD2/32, CD2/32, 1),   tb>>>(Wff1,p.hb+HB_W1F, CD2, CD2);
    transpose_hi<<<dim3(CDK/32, CD2/32, CH),  tb>>>(Wq2, p.hb+HB_W2Q, CD2, CDK);
    transpose_hi<<<dim3(CDK/32, CD2/32, CH),  tb>>>(Wk2, p.hb+HB_W2K, CD2, CDK);
    transpose_hi<<<dim3(CDK/32, CD2/32, CH),  tb>>>(Wv2, p.hb+HB_W2V, CD2, CDK);
    transpose_hi<<<dim3(CD2/32, CHD/32, 1),   tb>>>(Wo2, p.hb+HB_W2O, CHD, CD2);
    transpose_hi<<<dim3(CD2/32, CD2/32, 1),   tb>>>(Wff2,p.hb+HB_W2F, CD2, CD2);

    // ----- positional encoding -----
    float* pos = sb + OF_POS;
    posgen_kernel<<<(CS * CE + 255) / 256, 256>>>(pos);
    addpos_hi<<<(unsigned)((NB_XP + 255) / 256), 256>>>(X, pos,
        p.hb + HB_XPH, NB_XP);

    __half* ah  = p.hb + HB_AH;
    __half* fh  = p.hb + HB_FH;
    __half* n1h = p.hb + HB_N1H;
    __half* n2h = p.hb + HB_N2H;
    __half* n3h = p.hb + HB_N3H;
    int nbn = (CS * CD2 / 2 + 255) / 256;
    dim3 gff(CD2 / 128, (CB * CS) / 128, 1);

    // ----- block 1: attention (Din = 512) -----
    run_attn(CE, p.hb + HB_XPH,
             p.hb+HB_W1Q, p.hb+HB_W1K, p.hb+HB_W1V, bq1, bk1, bv1,
             p.hb+HB_W1O, bo1, p, ah);
    bn16<1><<<nbn, 256>>>(ah, p.hb + HB_XPH, CE, nullptr, n1h);

    // ----- block 2: FFN -----
    gemm3<true><<<gff, 128, GSMEM>>>(
        n1h, p.hb + HB_W1F, bff1, fh,
        CD2, CD2, CD2, CD2, 1, 0, 0, 0, 0, 0, 0, 0, 1.f);
    bn16<1><<<nbn, 256>>>(fh, n1h, CD2, nullptr, n2h);

    // ----- block 3: attention (Din = 1024) -----
    run_attn(CD2, n2h,
             p.hb+HB_W2Q, p.hb+HB_W2K, p.hb+HB_W2V, bq2, bk2, bv2,
             p.hb+HB_W2O, bo2, p, ah);
    bn16<1><<<nbn, 256>>>(ah, n2h, CD2, nullptr, n3h);

    // ----- block 4: FFN -----
    gemm3<true><<<gff, 128, GSMEM>>>(
        n3h, p.hb + HB_W2F, bff2, fh,
        CD2, CD2, CD2, CD2, 1, 0, 0, 0, 0, 0, 0, 0, 1.f);
    bn16<0><<<nbn, 256>>>(fh, n3h, CD2, out, nullptr);
}

// round 13
// speedup vs baseline: 2.2674x; 1.0299x over previous
#include <cuda_runtime.h>
#include <cuda_fp16.h>
#include <cstdint>
#include <math.h>

#define CB 32
#define CS 512
#define CE 512
#define CDK 128
#define CH 6
#define CD2 1024
#define CHD 768

// ---------------- sizes (elements) ----------------
constexpr long NB_XP  = (long)CB*CS*CE;
constexpr long NB_QKV = (long)CB*CH*CS*CDK;
constexpr long NB_SC  = (long)CB*CH*CS*CS;
constexpr long NB_Z   = (long)CB*CS*CHD;
constexpr long NB_D2  = (long)CB*CS*CD2;
constexpr long NW_QKV1 = (long)CH*CE*CDK;
constexpr long NW_QKV2 = (long)CH*CD2*CDK;
constexpr long NW_O   = (long)CHD*CD2;
constexpr long NW_F   = (long)CD2*CD2;

// ---------------- fp16 scratch offsets (half elems) ----------------
constexpr long HB_XPH = 0;
constexpr long HB_QH  = HB_XPH + NB_XP;
constexpr long HB_KH  = HB_QH + NB_QKV;
constexpr long HB_VTH = HB_KH + NB_QKV;
constexpr long HB_SCH = HB_VTH + NB_QKV;
constexpr long HB_ATH = HB_SCH + NB_SC;
constexpr long HB_ZH  = HB_ATH + NB_SC;
constexpr long HB_AH  = HB_ZH + NB_Z;
constexpr long HB_FH  = HB_AH + NB_D2;
constexpr long HB_N1H = HB_FH + NB_D2;
constexpr long HB_N2H = HB_N1H + NB_D2;
constexpr long HB_N3H = HB_N2H + NB_D2;
constexpr long HB_W1Q = HB_N3H + NB_D2;
constexpr long HB_W1K = HB_W1Q + NW_QKV1;
constexpr long HB_W1V = HB_W1K + NW_QKV1;
constexpr long HB_W1O = HB_W1V + NW_QKV1;
constexpr long HB_W1F = HB_W1O + NW_O;
constexpr long HB_W2Q = HB_W1F + NW_F;
constexpr long HB_W2K = HB_W2Q + NW_QKV2;
constexpr long HB_W2V = HB_W2K + NW_QKV2;
constexpr long HB_W2O = HB_W2V + NW_QKV2;
constexpr long HB_W2F = HB_W2O + NW_O;
constexpr long HB_END = HB_W2F + NW_F;

constexpr long SCRATCH_TOT = (HB_END + 1) / 2 + 64;
__device__ float g_scratch[SCRATCH_TOT];

// ---------------- helpers ----------------
__device__ __forceinline__ void cp16(uint32_t d, const void* s) {
    asm volatile("cp.async.cg.shared.global [%0], [%1], 16;\n" :: "r"(d), "l"(s));
}

#define MMA16816(c, a, b0, b1)                                              \
    asm volatile("mma.sync.aligned.m16n8k16.row.col.f32.f16.f16.f32 "       \
                 "{%0,%1,%2,%3},{%4,%5,%6,%7},{%8,%9},{%0,%1,%2,%3};"       \
                 : "+f"((c)[0]), "+f"((c)[1]), "+f"((c)[2]), "+f"((c)[3])   \
                 : "r"((a)[0]), "r"((a)[1]), "r"((a)[2]), "r"((a)[3]),      \
                   "r"(b0), "r"(b1))

// ---------------- positional encoding + add (fused) ----------------
__global__ void addpos_hi(const float* __restrict__ X,
                          __half* __restrict__ xh, long n) {
    long idx = (long)blockIdx.x * blockDim.x + threadIdx.x;
    if (idx >= n) return;
    int r = (int)(idx & (long)(CS * CE - 1));   // CS*CE is a power of two
    int e = r & 511;
    int s = r >> 9;
    int m = e >> 1;
    float ang = (m >= 128) ? (float)s * 1e-4f : (float)s;
    float pe = (e & 1) ? cosf(ang) : sinf(ang);
    xh[idx] = __float2half(X[idx] + pe);
}

// ---------------- batched transpose f32->hi (up to 3 tensors) ----------
__global__ void transpose_hi3(const float* __restrict__ i0,
                              const float* __restrict__ i1,
                              const float* __restrict__ i2,
                              __half* __restrict__ o0,
                              __half* __restrict__ o1,
                              __half* __restrict__ o2,
                              int R, int C, int zper) {
    __shared__ float t[32][33];
    int zz = blockIdx.z;
    int sel = zz / zper;
    int z = zz - sel * zper;
    const float* in = (sel == 0) ? i0 : (sel == 1) ? i1 : i2;
    __half* oh = (sel == 0) ? o0 : (sel == 1) ? o1 : o2;
    long zo = (long)z * R * C;
    int c0 = blockIdx.x * 32, r0 = blockIdx.y * 32;
    int tx = threadIdx.x, ty = threadIdx.y;
    #pragma unroll
    for (int i = 0; i < 32; i += 8)
        t[ty + i][tx] = in[zo + (long)(r0 + ty + i) * C + c0 + tx];
    __syncthreads();
    #pragma unroll
    for (int i = 0; i < 32; i += 8) {
        float v = t[tx][ty + i];
        long o = zo + (long)(c0 + ty + i) * R + r0 + tx;
        oh[o] = __float2half(v);
    }
}

// ================== GEMM core (shared device body) ==================
#define STGB 20480          // Ah 10240 | Bh 10240 (80B-pitch rows)
#define GSMEM 40960

template<bool TANH>
__device__ __forceinline__ void gemm_body(
    uint8_t* smem, const __half* ga_h, const __half* gb_h,
    const float* bias, __half* Chp,
    int K, int ldc, int m0, int n0, float alpha,
    int tid, int wid, int lane, bool transC)
{
    int g = lane >> 2, tig = lane & 3;
    int wm = (wid & 1) * 64, wn = (wid >> 1) * 64;
    uint32_t sbase = (uint32_t)__cvta_generic_to_shared(smem);

    float acc[4][8][4];
    #pragma unroll
    for (int i = 0; i < 4; ++i)
        #pragma unroll
        for (int j = 0; j < 8; ++j)
            #pragma unroll
            for (int q = 0; q < 4; ++q) acc[i][j][q] = 0.f;

    int nk = K / 32;
    {
        uint32_t d = sbase + tid * 80;
        #pragma unroll
        for (int c = 0; c < 4; ++c) {
            cp16(d + c * 16,         ga_h + c * 8);
            cp16(d + 10240 + c * 16, gb_h + c * 8);
        }
        asm volatile("cp.async.commit_group;");
    }

    for (int kc = 0; kc < nk; ++kc) {
        if (kc + 1 < nk) {
            int k0 = (kc + 1) * 32;
            uint32_t d = sbase + ((kc + 1) & 1) * STGB + tid * 80;
            #pragma unroll
            for (int c = 0; c < 4; ++c) {
                cp16(d + c * 16,         ga_h + k0 + c * 8);
                cp16(d + 10240 + c * 16, gb_h + k0 + c * 8);
            }
            asm volatile("cp.async.commit_group;");
            asm volatile("cp.async.wait_group 1;");
        } else {
            asm volatile("cp.async.wait_group 0;");
        }
        __syncthreads();

        const uint8_t* sb_ = smem + (kc & 1) * STGB;
        #pragma unroll
        for (int ks = 0; ks < 2; ++ks) {
            int cb = ks * 32 + tig * 4;
            uint32_t ah[4][4];
            #pragma unroll
            for (int mt = 0; mt < 4; ++mt) {
                const uint8_t* p = sb_ + (wm + mt * 16 + g) * 80 + cb;
                ah[mt][0] = *(const uint32_t*)(p);
                ah[mt][1] = *(const uint32_t*)(p + 8 * 80);
                ah[mt][2] = *(const uint32_t*)(p + 16);
                ah[mt][3] = *(const uint32_t*)(p + 8 * 80 + 16);
            }
            #pragma unroll
            for (int nt = 0; nt < 8; ++nt) {
                const uint8_t* pb = sb_ + 10240 + (wn + nt * 8 + g) * 80 + cb;
                uint32_t bh0 = *(const uint32_t*)(pb);
                uint32_t bh1 = *(const uint32_t*)(pb + 16);
                #pragma unroll
                for (int mt = 0; mt < 4; ++mt)
                    MMA16816(acc[mt][nt], ah[mt], bh0, bh1);
            }
        }
        __syncthreads();
    }

    if (!transC) {
        #pragma unroll
        for (int nt = 0; nt < 8; ++nt) {
            int col = n0 + wn + nt * 8 + tig * 2;
            float bb0 = 0.f, bb1 = 0.f;
            if (bias) { bb0 = bias[col - n0]; bb1 = bias[col - n0 + 1]; }
            #pragma unroll
            for (int mt = 0; mt < 4; ++mt) {
                int r0 = m0 + wm + mt * 16 + g;
                float v00 = acc[mt][nt][0] * alpha + bb0;
                float v01 = acc[mt][nt][1] * alpha + bb1;
                float v10 = acc[mt][nt][2] * alpha + bb0;
                float v11 = acc[mt][nt][3] * alpha + bb1;
                if (TANH) { v00 = tanhf(v00); v01 = tanhf(v01); v10 = tanhf(v10); v11 = tanhf(v11); }
                __half2 hh;
                hh.x = __float2half(v00); hh.y = __float2half(v01);
                *(__half2*)(Chp + (long)r0 * ldc + col) = hh;
                hh.x = __float2half(v10); hh.y = __float2half(v11);
                *(__half2*)(Chp + (long)(r0 + 8) * ldc + col) = hh;
            }
        }
    } else {
        // stage tile transposed in smem as [dk][t], pitch 130 halves,
        // then write coalesced to Chp (V^T base) with row stride ldc (=CS).
        __half* st = (__half*)smem;
        #pragma unroll
        for (int nt = 0; nt < 8; ++nt) {
            int col = wn + nt * 8 + tig * 2;
            float bb0 = bias[col], bb1 = bias[col + 1];
            #pragma unroll
            for (int mt = 0; mt < 4; ++mt) {
                int r0 = wm + mt * 16 + g;
                st[(long)col * 130 + r0]           = __float2half(acc[mt][nt][0] + bb0);
                st[(long)(col + 1) * 130 + r0]     = __float2half(acc[mt][nt][1] + bb1);
                st[(long)col * 130 + r0 + 8]       = __float2half(acc[mt][nt][2] + bb0);
                st[(long)(col + 1) * 130 + r0 + 8] = __float2half(acc[mt][nt][3] + bb1);
            }
        }
        __syncthreads();
        int dk0 = tid >> 6;             // 0 or 1
        int t2 = (tid & 63) * 2;        // 0..126 even
        #pragma unroll
        for (int d0 = 0; d0 < 128; d0 += 2) {
            int dk = d0 + dk0;
            __half2 v;
            v.x = st[(long)dk * 130 + t2];
            v.y = st[(long)dk * 130 + t2 + 1];
            *(__half2*)(Chp + (long)dk * ldc + m0 + t2) = v;
        }
    }
}

// ---------------- generic GEMM (fp16 out) ----------------
template<bool TANH>
__global__ void __launch_bounds__(128, 2) gemm3(
    const __half* __restrict__ Ah,
    const __half* __restrict__ Bh,
    const float* __restrict__ biasb,
    __half* __restrict__ Ch,
    int K, int lda, int ldb, int ldc, int Hdiv,
    long sA_b, long sA_h, long sB_b, long sB_h,
    long sC_b, long sC_h, long sBias_h, float alpha)
{
    extern __shared__ uint8_t smem[];
    int z = blockIdx.z, zb = z / Hdiv, zh_ = z - zb * Hdiv;
    int m0 = blockIdx.y * 128, n0 = blockIdx.x * 128;
    int tid = threadIdx.x, wid = tid >> 5, lane = tid & 31;
    const __half* ga = Ah + zb * sA_b + zh_ * sA_h + (long)(m0 + tid) * lda;
    const __half* gb = Bh + zb * sB_b + zh_ * sB_h + (long)(n0 + tid) * ldb;
    __half* Chp = Ch + zb * sC_b + zh_ * sC_h;
    const float* bias = biasb ? biasb + (long)zh_ * sBias_h + n0 : nullptr;
    gemm_body<TANH>(smem, ga, gb, bias, Chp, K, ldc, m0, n0, alpha, tid, wid, lane, false);
}

// ---------------- merged QKV GEMM: blockIdx.x selects q/k/v -------------
// V output is written TRANSPOSED: [z][dk][t] (fused V transpose).
__global__ void __launch_bounds__(128, 2) gemm_qkv(
    const __half* __restrict__ Ah,
    const __half* __restrict__ Bq, const __half* __restrict__ Bk,
    const __half* __restrict__ Bv,
    const float* __restrict__ bq, const float* __restrict__ bk,
    const float* __restrict__ bv,
    __half* __restrict__ Cq, __half* __restrict__ Ck, __half* __restrict__ Cvt,
    int K)
{
    extern __shared__ uint8_t smem[];
    int sel = blockIdx.x;
    int z = blockIdx.z, zb = z / CH, zh_ = z - zb * CH;
    int m0 = blockIdx.y * 128;
    int tid = threadIdx.x, wid = tid >> 5, lane = tid & 31;

    const __half* Bh = (sel == 0) ? Bq : (sel == 1) ? Bk : Bv;
    const float* bb  = (sel == 0) ? bq : (sel == 1) ? bk : bv;

    long sA_b = (long)CS * K;
    long sB_h = (long)CDK * K;

    const __half* ga = Ah + zb * sA_b + (long)(m0 + tid) * K;
    const __half* gb = Bh + zh_ * sB_h + (long)tid * K;
    const float* bias = bb + (long)zh_ * CDK;

    if (sel < 2) {
        __half* Ch = (sel == 0) ? Cq : Ck;
        __half* Chp = Ch + zb * (long)CH * CS * CDK + zh_ * (long)CS * CDK;
        gemm_body<false>(smem, ga, gb, bias, Chp, K, CDK, m0, 0, 1.f, tid, wid, lane, false);
    } else {
        __half* Chp = Cvt + zb * (long)CH * CDK * CS + zh_ * (long)CDK * CS;
        gemm_body<false>(smem, ga, gb, bias, Chp, K, CS, m0, 0, 1.f, tid, wid, lane, true);
    }
}

// ---------------- softmax over the QUERY axis (half2 vectorized) ------
__global__ void __launch_bounds__(512) softmax_q2(const __half* __restrict__ Sc,
                                                  __half* __restrict__ oh) {
    __shared__ float2 sm[16][32], sl[16][32];
    long base = (long)blockIdx.x * CS * CS + blockIdx.y * 64;
    int w = threadIdx.x >> 5, lane = threadIdx.x & 31;
    const __half* p = Sc + base + (long)w * 32 * CS + lane * 2;
    float v0[32], v1[32];
    float m0 = -1e30f, l0 = 0.f, m1 = -1e30f, l1 = 0.f;
    #pragma unroll
    for (int i = 0; i < 32; ++i) {
        __half2 x2 = *(const __half2*)(p + (long)i * CS);
        float x0 = __half2float(x2.x), x1 = __half2float(x2.y);
        v0[i] = x0; v1[i] = x1;
        float nm0 = fmaxf(m0, x0);
        l0 = l0 * __expf(m0 - nm0) + __expf(x0 - nm0);
        m0 = nm0;
        float nm1 = fmaxf(m1, x1);
        l1 = l1 * __expf(m1 - nm1) + __expf(x1 - nm1);
        m1 = nm1;
    }
    sm[w][lane] = make_float2(m0, m1);
    sl[w][lane] = make_float2(l0, l1);
    __syncthreads();
    float M0 = -1e30f, M1 = -1e30f;
    #pragma unroll
    for (int ww = 0; ww < 16; ++ww) {
        M0 = fmaxf(M0, sm[ww][lane].x);
        M1 = fmaxf(M1, sm[ww][lane].y);
    }
    float L0 = 0.f, L1 = 0.f;
    #pragma unroll
    for (int ww = 0; ww < 16; ++ww) {
        L0 += sl[ww][lane].x * __expf(sm[ww][lane].x - M0);
        L1 += sl[ww][lane].y * __expf(sm[ww][lane].y - M1);
    }
    float inv0 = 1.f / L0, inv1 = 1.f / L1;
    __half* po = oh + base + (long)w * 32 * CS + lane * 2;
    #pragma unroll
    for (int i = 0; i < 32; ++i) {
        __half2 e2;
        e2.x = __float2half(__expf(v0[i] - M0) * inv0);
        e2.y = __float2half(__expf(v1[i] - M1) * inv1);
        *(__half2*)(po + (long)i * CS) = e2;
    }
}

// ---------------- batch-norm (half2 vectorized) ----------
template<int OMODE>
__global__ void bn16(const __half* __restrict__ x,
                     const __half* __restrict__ add, int addw,
                     float* __restrict__ outf,
                     __half* __restrict__ oh) {
    int j2 = blockIdx.x * blockDim.x + threadIdx.x;
    if (j2 >= CS * CD2 / 2) return;
    int j = j2 * 2;
    const long SD = (long)CS * CD2;
    int s = j >> 10;
    int e = j & 1023;
    int ae = e & (addw - 1);
    long aoff = (long)s * addw + ae;

    float v0[CB], v1[CB];
    float sum0 = 0.f, sum1 = 0.f;
    #pragma unroll
    for (int b = 0; b < CB; ++b) {
        __half2 xa = *(const __half2*)(x + (long)b * SD + j);
        __half2 ad = *(const __half2*)(add + (long)b * CS * addw + aoff);
        float t0 = __half2float(xa.x) + __half2float(ad.x);
        float t1 = __half2float(xa.y) + __half2float(ad.y);
        v0[b] = t0; v1[b] = t1;
        sum0 += t0; sum1 += t1;
    }
    float mean0 = sum0 * (1.f / CB), mean1 = sum1 * (1.f / CB);
    float var0 = 0.f, var1 = 0.f;
    #pragma unroll
    for (int b = 0; b < CB; ++b) {
        float d0 = v0[b] - mean0, d1 = v1[b] - mean1;
        var0 += d0 * d0; var1 += d1 * d1;
    }
    float rstd0 = rsqrtf(var0 * (1.f / CB) + 1e-3f);
    float rstd1 = rsqrtf(var1 * (1.f / CB) + 1e-3f);
    #pragma unroll
    for (int b = 0; b < CB; ++b) {
        float o0 = (v0[b] - mean0) * rstd0;
        float o1 = (v1[b] - mean1) * rstd1;
        if (OMODE == 0) {
            *(float2*)(outf + (long)b * SD + j) = make_float2(o0, o1);
        } else {
            __half2 hh;
            hh.x = __float2half(o0); hh.y = __float2half(o1);
            *(__half2*)(oh + (long)b * SD + j) = hh;
        }
    }
}

// ---------------- host orchestration ----------------
struct Ptrs {
    __half* hb;
};

static void run_attn(int Din, const __half* xh,
                     const __half* WqT, const __half* WkT, const __half* WvT,
                     const float* bq, const float* bk, const float* bv,
                     const __half* WoT, const float* bo, Ptrs p, __half* aout)
{
    __half *qh = p.hb + HB_QH;
    __half *kh = p.hb + HB_KH;
    __half *vth = p.hb + HB_VTH;
    __half *sch = p.hb + HB_SCH;
    __half *ath = p.hb + HB_ATH;
    __half *zh = p.hb + HB_ZH;

    // merged QKV (V written transposed)
    gemm_qkv<<<dim3(3, CS / 128, CB * CH), 128, GSMEM>>>(
        xh, WqT, WkT, WvT, bq, bk, bv, qh, kh, vth, Din);

    // scores = Q @ K^T * 1/sqrt(dk) -> fp16
    gemm3<false><<<dim3(CS / 128, CS / 128, CB * CH), 128, GSMEM>>>(
        qh, kh, nullptr, sch,
        CDK, CDK, CDK, CS, 1,
        (long)CS * CDK, 0, (long)CS * CDK, 0, (long)CS * CS, 0, 0,
        0.08838834764831845f);

    softmax_q2<<<dim3(CB * CH, CS / 64), 512>>>(sch, ath);

    // z = attn @ V^T
    gemm3<false><<<dim3(1, CS / 128, CB * CH), 128, GSMEM>>>(
        ath, vth, nullptr, zh,
        CS, CS, CS, CHD, CH,
        (long)CH * CS * CS, (long)CS * CS,
        (long)CH * CDK * CS, (long)CDK * CS,
        (long)CS * CHD, CDK, 0, 1.f);

    // out projection: (B*S,768) @ (768,1024) -> fp16
    gemm3<false><<<dim3(CD2 / 128, (CB * CS) / 128, 1), 128, GSMEM>>>(
        zh, WoT, bo, aout,
        CHD, CHD, CHD, CD2, 1, 0, 0, 0, 0, 0, 0, 0, 1.f);
}

extern "C" void kernel_launch(void* const* d_in, const int* in_sizes, int n_in,
                              void* d_out, int out_size)
{
    const float* X    = (const float*)d_in[0];
    const float* Wq1  = (const float*)d_in[1];
    const float* Wk1  = (const float*)d_in[2];
    const float* Wv1  = (const float*)d_in[3];
    const float* bq1  = (const float*)d_in[4];
    const float* bk1  = (const float*)d_in[5];
    const float* bv1  = (const float*)d_in[6];
    const float* Wo1  = (const float*)d_in[7];
    const float* bo1  = (const float*)d_in[8];
    const float* Wff1 = (const float*)d_in[9];
    const float* bff1 = (const float*)d_in[10];
    const float* Wq2  = (const float*)d_in[11];
    const float* Wk2  = (const float*)d_in[12];
    const float* Wv2  = (const float*)d_in[13];
    const float* bq2  = (const float*)d_in[14];
    const float* bk2  = (const float*)d_in[15];
    const float* bv2  = (const float*)d_in[16];
    const float* Wo2  = (const float*)d_in[17];
    const float* bo2  = (const float*)d_in[18];
    const float* Wff2 = (const float*)d_in[19];
    const float* bff2 = (const float*)d_in[20];
    float* out = (float*)d_out;

    float* sb = nullptr;
    cudaGetSymbolAddress((void**)&sb, g_scratch);
    Ptrs p;
    p.hb = (__half*)sb;

    cudaFuncSetAttribute(gemm3<false>, cudaFuncAttributeMaxDynamicSharedMemorySize, GSMEM);
    cudaFuncSetAttribute(gemm3<true>,  cudaFuncAttributeMaxDynamicSharedMemorySize, GSMEM);
    cudaFuncSetAttribute(gemm_qkv,     cudaFuncAttributeMaxDynamicSharedMemorySize, GSMEM);

    // ----- batched weight transposes (4 launches) -----
    dim3 tb(32, 8);
    transpose_hi3<<<dim3(CDK/32, CE/32, 3*CH), tb>>>(
        Wq1, Wk1, Wv1, p.hb+HB_W1Q, p.hb+HB_W1K, p.hb+HB_W1V, CE, CDK, CH);
    transpose_hi3<<<dim3(CDK/32, CD2/32, 3*CH), tb>>>(
        Wq2, Wk2, Wv2, p.hb+HB_W2Q, p.hb+HB_W2K, p.hb+HB_W2V, CD2, CDK, CH);
    transpose_hi3<<<dim3(CD2/32, CHD/32, 2), tb>>>(
        Wo1, Wo2, Wo1, p.hb+HB_W1O, p.hb+HB_W2O, p.hb+HB_W1O, CHD, CD2, 1);
    transpose_hi3<<<dim3(CD2/32, CD2/32, 2), tb>>>(
        Wff1, Wff2, Wff1, p.hb+HB_W1F, p.hb+HB_W2F, p.hb+HB_W1F, CD2, CD2, 1);

    // ----- positional encoding fused into input convert -----
    addpos_hi<<<(unsigned)((NB_XP + 255) / 256), 256>>>(X, p.hb + HB_XPH, NB_XP);

    __half* ah  = p.hb + HB_AH;
    __half* fh  = p.hb + HB_FH;
    __half* n1h = p.hb + HB_N1H;
    __half* n2h = p.hb + HB_N2H;
    __half* n3h = p.hb + HB_N3H;
    int nbn = (CS * CD2 / 2 + 255) / 256;
    dim3 gff(CD2 / 128, (CB * CS) / 128, 1);

    // ----- block 1: attention (Din = 512) -----
    run_attn(CE, p.hb + HB_XPH,
             p.hb+HB_W1Q, p.hb+HB_W1K, p.hb+HB_W1V, bq1, bk1, bv1,
             p.hb+HB_W1O, bo1, p, ah);
    bn16<1><<<nbn, 256>>>(ah, p.hb + HB_XPH, CE, nullptr, n1h);

    // ----- block 2: FFN -----
    gemm3<true><<<gff, 128, GSMEM>>>(
        n1h, p.hb + HB_W1F, bff1, fh,
        CD2, CD2, CD2, CD2, 1, 0, 0, 0, 0, 0, 0, 0, 1.f);
    bn16<1><<<nbn, 256>>>(fh, n1h, CD2, nullptr, n2h);

    // ----- block 3: attention (Din = 1024) -----
    run_attn(CD2, n2h,
             p.hb+HB_W2Q, p.hb+HB_W2K, p.hb+HB_W2V, bq2, bk2, bv2,
             p.hb+HB_W2O, bo2, p, ah);
    bn16<1><<<nbn, 256>>>(ah, n2h, CD2, nullptr, n3h);

    // ----- block 4: FFN -----
    gemm3<true><<<gff, 128, GSMEM>>>(
        n3h, p.hb + HB_W2F, bff2, fh,
        CD2, CD2, CD2, CD2, 1, 0, 0, 0, 0, 0, 0, 0, 1.f);
    bn16<0><<<nbn, 256>>>(fh, n3h, CD2, out, nullptr);
}

// round 14
// speedup vs baseline: 2.3197x; 1.0231x over previous
#include <cuda_runtime.h>
#include <cuda_fp16.h>
#include <cstdint>
#include <math.h>

#define CB 32
#define CS 512
#define CE 512
#define CDK 128
#define CH 6
#define CD2 1024
#define CHD 768

// ---------------- sizes (elements) ----------------
constexpr long NB_XP  = (long)CB*CS*CE;
constexpr long NB_QKV = (long)CB*CH*CS*CDK;
constexpr long NB_SC  = (long)CB*CH*CS*CS;
constexpr long NB_Z   = (long)CB*CS*CHD;
constexpr long NB_D2  = (long)CB*CS*CD2;
constexpr long NW_QKV1 = (long)CH*CE*CDK;
constexpr long NW_QKV2 = (long)CH*CD2*CDK;
constexpr long NW_O   = (long)CHD*CD2;
constexpr long NW_F   = (long)CD2*CD2;

// ---------------- fp16 scratch offsets (half elems) ----------------
constexpr long HB_XPH = 0;
constexpr long HB_QH  = HB_XPH + NB_XP;
constexpr long HB_KH  = HB_QH + NB_QKV;
constexpr long HB_VTH = HB_KH + NB_QKV;
constexpr long HB_SCH = HB_VTH + NB_QKV;
constexpr long HB_ATH = HB_SCH + NB_SC;
constexpr long HB_ZH  = HB_ATH + NB_SC;
constexpr long HB_AH  = HB_ZH + NB_Z;
constexpr long HB_FH  = HB_AH + NB_D2;
constexpr long HB_N1H = HB_FH + NB_D2;
constexpr long HB_N2H = HB_N1H + NB_D2;
constexpr long HB_N3H = HB_N2H + NB_D2;
constexpr long HB_W1Q = HB_N3H + NB_D2;
constexpr long HB_W1K = HB_W1Q + NW_QKV1;
constexpr long HB_W1V = HB_W1K + NW_QKV1;
constexpr long HB_W1O = HB_W1V + NW_QKV1;
constexpr long HB_W1F = HB_W1O + NW_O;
constexpr long HB_W2Q = HB_W1F + NW_F;
constexpr long HB_W2K = HB_W2Q + NW_QKV2;
constexpr long HB_W2V = HB_W2K + NW_QKV2;
constexpr long HB_W2O = HB_W2V + NW_QKV2;
constexpr long HB_W2F = HB_W2O + NW_O;
constexpr long HB_END = HB_W2F + NW_F;

constexpr long SCRATCH_TOT = (HB_END + 1) / 2 + 64;
__device__ float g_scratch[SCRATCH_TOT];

// ---------------- helpers ----------------
__device__ __forceinline__ void cp16(uint32_t d, const void* s) {
    asm volatile("cp.async.cg.shared.global [%0], [%1], 16;\n" :: "r"(d), "l"(s));
}

#define MMA16816(c, a, b0, b1)                                              \
    asm volatile("mma.sync.aligned.m16n8k16.row.col.f32.f16.f16.f32 "       \
                 "{%0,%1,%2,%3},{%4,%5,%6,%7},{%8,%9},{%0,%1,%2,%3};"       \
                 : "+f"((c)[0]), "+f"((c)[1]), "+f"((c)[2]), "+f"((c)[3])   \
                 : "r"((a)[0]), "r"((a)[1]), "r"((a)[2]), "r"((a)[3]),      \
                   "r"(b0), "r"(b1))

// ---------------- positional encoding + add (fused) ----------------
__global__ void addpos_hi(const float* __restrict__ X,
                          __half* __restrict__ xh, long n) {
    long idx = (long)blockIdx.x * blockDim.x + threadIdx.x;
    if (idx >= n) return;
    int r = (int)(idx & (long)(CS * CE - 1));
    int e = r & 511;
    int s = r >> 9;
    int m = e >> 1;
    float ang = (m >= 128) ? (float)s * 1e-4f : (float)s;
    float pe = (e & 1) ? cosf(ang) : sinf(ang);
    xh[idx] = __float2half(X[idx] + pe);
}

// ---------------- batched transpose f32->hi (up to 3 tensors) ----------
__global__ void transpose_hi3(const float* __restrict__ i0,
                              const float* __restrict__ i1,
                              const float* __restrict__ i2,
                              __half* __restrict__ o0,
                              __half* __restrict__ o1,
                              __half* __restrict__ o2,
                              int R, int C, int zper) {
    __shared__ float t[32][33];
    int zz = blockIdx.z;
    int sel = zz / zper;
    int z = zz - sel * zper;
    const float* in = (sel == 0) ? i0 : (sel == 1) ? i1 : i2;
    __half* oh = (sel == 0) ? o0 : (sel == 1) ? o1 : o2;
    long zo = (long)z * R * C;
    int c0 = blockIdx.x * 32, r0 = blockIdx.y * 32;
    int tx = threadIdx.x, ty = threadIdx.y;
    #pragma unroll
    for (int i = 0; i < 32; i += 8)
        t[ty + i][tx] = in[zo + (long)(r0 + ty + i) * C + c0 + tx];
    __syncthreads();
    #pragma unroll
    for (int i = 0; i < 32; i += 8) {
        float v = t[tx][ty + i];
        long o = zo + (long)(c0 + ty + i) * R + r0 + tx;
        oh[o] = __float2half(v);
    }
}

// ================== GEMM core (shared device body) ==================
#define STGB 20480          // Ah 10240 | Bh 10240 (80B-pitch rows)
#define GSMEM 40960

template<bool TANH>
__device__ __forceinline__ void gemm_body(
    uint8_t* smem, const __half* ga_h, const __half* gb_h,
    const float* bias, __half* Chp,
    int K, int ldc, int m0, int n0, float alpha,
    int tid, int wid, int lane, bool transC)
{
    int g = lane >> 2, tig = lane & 3;
    int wm = (wid & 1) * 64, wn = (wid >> 1) * 64;
    uint32_t sbase = (uint32_t)__cvta_generic_to_shared(smem);

    float acc[4][8][4];
    #pragma unroll
    for (int i = 0; i < 4; ++i)
        #pragma unroll
        for (int j = 0; j < 8; ++j)
            #pragma unroll
            for (int q = 0; q < 4; ++q) acc[i][j][q] = 0.f;

    int nk = K / 32;
    {
        uint32_t d = sbase + tid * 80;
        #pragma unroll
        for (int c = 0; c < 4; ++c) {
            cp16(d + c * 16,         ga_h + c * 8);
            cp16(d + 10240 + c * 16, gb_h + c * 8);
        }
        asm volatile("cp.async.commit_group;");
    }

    for (int kc = 0; kc < nk; ++kc) {
        if (kc + 1 < nk) {
            int k0 = (kc + 1) * 32;
            uint32_t d = sbase + ((kc + 1) & 1) * STGB + tid * 80;
            #pragma unroll
            for (int c = 0; c < 4; ++c) {
                cp16(d + c * 16,         ga_h + k0 + c * 8);
                cp16(d + 10240 + c * 16, gb_h + k0 + c * 8);
            }
            asm volatile("cp.async.commit_group;");
            asm volatile("cp.async.wait_group 1;");
        } else {
            asm volatile("cp.async.wait_group 0;");
        }
        __syncthreads();

        const uint8_t* sb_ = smem + (kc & 1) * STGB;
        #pragma unroll
        for (int ks = 0; ks < 2; ++ks) {
            int cb = ks * 32 + tig * 4;
            uint32_t ah[4][4];
            #pragma unroll
            for (int mt = 0; mt < 4; ++mt) {
                const uint8_t* p = sb_ + (wm + mt * 16 + g) * 80 + cb;
                ah[mt][0] = *(const uint32_t*)(p);
                ah[mt][1] = *(const uint32_t*)(p + 8 * 80);
                ah[mt][2] = *(const uint32_t*)(p + 16);
                ah[mt][3] = *(const uint32_t*)(p + 8 * 80 + 16);
            }
            #pragma unroll
            for (int nt = 0; nt < 8; ++nt) {
                const uint8_t* pb = sb_ + 10240 + (wn + nt * 8 + g) * 80 + cb;
                uint32_t bh0 = *(const uint32_t*)(pb);
                uint32_t bh1 = *(const uint32_t*)(pb + 16);
                #pragma unroll
                for (int mt = 0; mt < 4; ++mt)
                    MMA16816(acc[mt][nt], ah[mt], bh0, bh1);
            }
        }
        __syncthreads();
    }

    if (!transC) {
        #pragma unroll
        for (int nt = 0; nt < 8; ++nt) {
            int col = n0 + wn + nt * 8 + tig * 2;
            float bb0 = 0.f, bb1 = 0.f;
            if (bias) { bb0 = bias[col - n0]; bb1 = bias[col - n0 + 1]; }
            #pragma unroll
            for (int mt = 0; mt < 4; ++mt) {
                int r0 = m0 + wm + mt * 16 + g;
                float v00 = acc[mt][nt][0] * alpha + bb0;
                float v01 = acc[mt][nt][1] * alpha + bb1;
                float v10 = acc[mt][nt][2] * alpha + bb0;
                float v11 = acc[mt][nt][3] * alpha + bb1;
                if (TANH) { v00 = tanhf(v00); v01 = tanhf(v01); v10 = tanhf(v10); v11 = tanhf(v11); }
                __half2 hh;
                hh.x = __float2half(v00); hh.y = __float2half(v01);
                *(__half2*)(Chp + (long)r0 * ldc + col) = hh;
                hh.x = __float2half(v10); hh.y = __float2half(v11);
                *(__half2*)(Chp + (long)(r0 + 8) * ldc + col) = hh;
            }
        }
    } else {
        __half* st = (__half*)smem;
        #pragma unroll
        for (int nt = 0; nt < 8; ++nt) {
            int col = wn + nt * 8 + tig * 2;
            float bb0 = bias[col], bb1 = bias[col + 1];
            #pragma unroll
            for (int mt = 0; mt < 4; ++mt) {
                int r0 = wm + mt * 16 + g;
                st[(long)col * 130 + r0]           = __float2half(acc[mt][nt][0] + bb0);
                st[(long)(col + 1) * 130 + r0]     = __float2half(acc[mt][nt][1] + bb1);
                st[(long)col * 130 + r0 + 8]       = __float2half(acc[mt][nt][2] + bb0);
                st[(long)(col + 1) * 130 + r0 + 8] = __float2half(acc[mt][nt][3] + bb1);
            }
        }
        __syncthreads();
        int dk0 = tid >> 6;
        int t2 = (tid & 63) * 2;
        #pragma unroll
        for (int d0 = 0; d0 < 128; d0 += 2) {
            int dk = d0 + dk0;
            __half2 v;
            v.x = st[(long)dk * 130 + t2];
            v.y = st[(long)dk * 130 + t2 + 1];
            *(__half2*)(Chp + (long)dk * ldc + m0 + t2) = v;
        }
    }
}

// ---------------- generic GEMM (fp16 out) ----------------
template<bool TANH>
__global__ void __launch_bounds__(128, 2) gemm3(
    const __half* __restrict__ Ah,
    const __half* __restrict__ Bh,
    const float* __restrict__ biasb,
    __half* __restrict__ Ch,
    int K, int lda, int ldb, int ldc, int Hdiv,
    long sA_b, long sA_h, long sB_b, long sB_h,
    long sC_b, long sC_h, long sBias_h, float alpha)
{
    extern __shared__ uint8_t smem[];
    int z = blockIdx.z, zb = z / Hdiv, zh_ = z - zb * Hdiv;
    int m0 = blockIdx.y * 128, n0 = blockIdx.x * 128;
    int tid = threadIdx.x, wid = tid >> 5, lane = tid & 31;
    const __half* ga = Ah + zb * sA_b + zh_ * sA_h + (long)(m0 + tid) * lda;
    const __half* gb = Bh + zb * sB_b + zh_ * sB_h + (long)(n0 + tid) * ldb;
    __half* Chp = Ch + zb * sC_b + zh_ * sC_h;
    const float* bias = biasb ? biasb + (long)zh_ * sBias_h + n0 : nullptr;
    gemm_body<TANH>(smem, ga, gb, bias, Chp, K, ldc, m0, n0, alpha, tid, wid, lane, false);
}

// ---------------- merged QKV GEMM (V written transposed) ---------------
__global__ void __launch_bounds__(128, 2) gemm_qkv(
    const __half* __restrict__ Ah,
    const __half* __restrict__ Bq, const __half* __restrict__ Bk,
    const __half* __restrict__ Bv,
    const float* __restrict__ bq, const float* __restrict__ bk,
    const float* __restrict__ bv,
    __half* __restrict__ Cq, __half* __restrict__ Ck, __half* __restrict__ Cvt,
    int K)
{
    extern __shared__ uint8_t smem[];
    int sel = blockIdx.x;
    int z = blockIdx.z, zb = z / CH, zh_ = z - zb * CH;
    int m0 = blockIdx.y * 128;
    int tid = threadIdx.x, wid = tid >> 5, lane = tid & 31;

    const __half* Bh = (sel == 0) ? Bq : (sel == 1) ? Bk : Bv;
    const float* bb  = (sel == 0) ? bq : (sel == 1) ? bk : bv;

    long sA_b = (long)CS * K;
    long sB_h = (long)CDK * K;

    const __half* ga = Ah + zb * sA_b + (long)(m0 + tid) * K;
    const __half* gb = Bh + zh_ * sB_h + (long)tid * K;
    const float* bias = bb + (long)zh_ * CDK;

    if (sel < 2) {
        __half* Ch = (sel == 0) ? Cq : Ck;
        __half* Chp = Ch + zb * (long)CH * CS * CDK + zh_ * (long)CS * CDK;
        gemm_body<false>(smem, ga, gb, bias, Chp, K, CDK, m0, 0, 1.f, tid, wid, lane, false);
    } else {
        __half* Chp = Cvt + zb * (long)CH * CDK * CS + zh_ * (long)CDK * CS;
        gemm_body<false>(smem, ga, gb, bias, Chp, K, CS, m0, 0, 1.f, tid, wid, lane, true);
    }
}

// ---------------- softmax over the QUERY axis (two-pass, 1 exp/elem) ---
__global__ void __launch_bounds__(512) softmax_q2(const __half* __restrict__ Sc,
                                                  __half* __restrict__ oh) {
    __shared__ float2 sm[16][32], sl[16][32];
    long base = (long)blockIdx.x * CS * CS + blockIdx.y * 64;
    int w = threadIdx.x >> 5, lane = threadIdx.x & 31;
    const __half* p = Sc + base + (long)w * 32 * CS + lane * 2;
    float v0[32], v1[32];
    // pass 1: load + local max (FMA pipe only)
    float m0 = -1e30f, m1 = -1e30f;
    #pragma unroll
    for (int i = 0; i < 32; ++i) {
        __half2 x2 = *(const __half2*)(p + (long)i * CS);
        float x0 = __half2float(x2.x), x1 = __half2float(x2.y);
        v0[i] = x0; v1[i] = x1;
        m0 = fmaxf(m0, x0);
        m1 = fmaxf(m1, x1);
    }
    // pass 2: exponentiate in place + local sum (1 exp per element)
    float l0 = 0.f, l1 = 0.f;
    #pragma unroll
    for (int i = 0; i < 32; ++i) {
        v0[i] = __expf(v0[i] - m0); l0 += v0[i];
        v1[i] = __expf(v1[i] - m1); l1 += v1[i];
    }
    sm[w][lane] = make_float2(m0, m1);
    sl[w][lane] = make_float2(l0, l1);
    __syncthreads();
    float M0 = -1e30f, M1 = -1e30f;
    #pragma unroll
    for (int ww = 0; ww < 16; ++ww) {
        M0 = fmaxf(M0, sm[ww][lane].x);
        M1 = fmaxf(M1, sm[ww][lane].y);
    }
    float L0 = 0.f, L1 = 0.f;
    #pragma unroll
    for (int ww = 0; ww < 16; ++ww) {
        L0 += sl[ww][lane].x * __expf(sm[ww][lane].x - M0);
        L1 += sl[ww][lane].y * __expf(sm[ww][lane].y - M1);
    }
    // fold local->global rebase and normalization into one scale
    float sc0 = __expf(m0 - M0) / L0;
    float sc1 = __expf(m1 - M1) / L1;
    __half* po = oh + base + (long)w * 32 * CS + lane * 2;
    #pragma unroll
    for (int i = 0; i < 32; ++i) {
        __half2 e2;
        e2.x = __float2half(v0[i] * sc0);
        e2.y = __float2half(v1[i] * sc1);
        *(__half2*)(po + (long)i * CS) = e2;
    }
}

// ---------------- batch-norm (half2 vectorized) ----------
template<int OMODE>
__global__ void bn16(const __half* __restrict__ x,
                     const __half* __restrict__ add, int addw,
                     float* __restrict__ outf,
                     __half* __restrict__ oh) {
    int j2 = blockIdx.x * blockDim.x + threadIdx.x;
    if (j2 >= CS * CD2 / 2) return;
    int j = j2 * 2;
    const long SD = (long)CS * CD2;
    int s = j >> 10;
    int e = j & 1023;
    int ae = e & (addw - 1);
    long aoff = (long)s * addw + ae;

    float v0[CB], v1[CB];
    float sum0 = 0.f, sum1 = 0.f;
    #pragma unroll
    for (int b = 0; b < CB; ++b) {
        __half2 xa = *(const __half2*)(x + (long)b * SD + j);
        __half2 ad = *(const __half2*)(add + (long)b * CS * addw + aoff);
        float t0 = __half2float(xa.x) + __half2float(ad.x);
        float t1 = __half2float(xa.y) + __half2float(ad.y);
        v0[b] = t0; v1[b] = t1;
        sum0 += t0; sum1 += t1;
    }
    float mean0 = sum0 * (1.f / CB), mean1 = sum1 * (1.f / CB);
    float var0 = 0.f, var1 = 0.f;
    #pragma unroll
    for (int b = 0; b < CB; ++b) {
        float d0 = v0[b] - mean0, d1 = v1[b] - mean1;
        var0 += d0 * d0; var1 += d1 * d1;
    }
    float rstd0 = rsqrtf(var0 * (1.f / CB) + 1e-3f);
    float rstd1 = rsqrtf(var1 * (1.f / CB) + 1e-3f);
    #pragma unroll
    for (int b = 0; b < CB; ++b) {
        float o0 = (v0[b] - mean0) * rstd0;
        float o1 = (v1[b] - mean1) * rstd1;
        if (OMODE == 0) {
            *(float2*)(outf + (long)b * SD + j) = make_float2(o0, o1);
        } else {
            __half2 hh;
            hh.x = __float2half(o0); hh.y = __float2half(o1);
            *(__half2*)(oh + (long)b * SD + j) = hh;
        }
    }
}

// ---------------- host orchestration ----------------
struct Ptrs {
    __half* hb;
};

static void run_attn(int Din, const __half* xh,
                     const __half* WqT, const __half* WkT, const __half* WvT,
                     const float* bq, const float* bk, const float* bv,
                     const __half* WoT, const float* bo, Ptrs p, __half* aout)
{
    __half *qh = p.hb + HB_QH;
    __half *kh = p.hb + HB_KH;
    __half *vth = p.hb + HB_VTH;
    __half *sch = p.hb + HB_SCH;
    __half *ath = p.hb + HB_ATH;
    __half *zh = p.hb + HB_ZH;

    gemm_qkv<<<dim3(3, CS / 128, CB * CH), 128, GSMEM>>>(
        xh, WqT, WkT, WvT, bq, bk, bv, qh, kh, vth, Din);

    gemm3<false><<<dim3(CS / 128, CS / 128, CB * CH), 128, GSMEM>>>(
        qh, kh, nullptr, sch,
        CDK, CDK, CDK, CS, 1,
        (long)CS * CDK, 0, (long)CS * CDK, 0, (long)CS * CS, 0, 0,
        0.08838834764831845f);

    softmax_q2<<<dim3(CB * CH, CS / 64), 512>>>(sch, ath);

    gemm3<false><<<dim3(1, CS / 128, CB * CH), 128, GSMEM>>>(
        ath, vth, nullptr, zh,
        CS, CS, CS, CHD, CH,
        (long)CH * CS * CS, (long)CS * CS,
        (long)CH * CDK * CS, (long)CDK * CS,
        (long)CS * CHD, CDK, 0, 1.f);

    gemm3<false><<<dim3(CD2 / 128, (CB * CS) / 128, 1), 128, GSMEM>>>(
        zh, WoT, bo, aout,
        CHD, CHD, CHD, CD2, 1, 0, 0, 0, 0, 0, 0, 0, 1.f);
}

extern "C" void kernel_launch(void* const* d_in, const int* in_sizes, int n_in,
                              void* d_out, int out_size)
{
    const float* X    = (const float*)d_in[0];
    const float* Wq1  = (const float*)d_in[1];
    const float* Wk1  = (const float*)d_in[2];
    const float* Wv1  = (const float*)d_in[3];
    const float* bq1  = (const float*)d_in[4];
    const float* bk1  = (const float*)d_in[5];
    const float* bv1  = (const float*)d_in[6];
    const float* Wo1  = (const float*)d_in[7];
    const float* bo1  = (const float*)d_in[8];
    const float* Wff1 = (const float*)d_in[9];
    const float* bff1 = (const float*)d_in[10];
    const float* Wq2  = (const float*)d_in[11];
    const float* Wk2  = (const float*)d_in[12];
    const float* Wv2  = (const float*)d_in[13];
    const float* bq2  = (const float*)d_in[14];
    const float* bk2  = (const float*)d_in[15];
    const float* bv2  = (const float*)d_in[16];
    const float* Wo2  = (const float*)d_in[17];
    const float* bo2  = (const float*)d_in[18];
    const float* Wff2 = (const float*)d_in[19];
    const float* bff2 = (const float*)d_in[20];
    float* out = (float*)d_out;

    float* sb = nullptr;
    cudaGetSymbolAddress((void**)&sb, g_scratch);
    Ptrs p;
    p.hb = (__half*)sb;

    cudaFuncSetAttribute(gemm3<false>, cudaFuncAttributeMaxDynamicSharedMemorySize, GSMEM);
    cudaFuncSetAttribute(gemm3<true>,  cudaFuncAttributeMaxDynamicSharedMemorySize, GSMEM);
    cudaFuncSetAttribute(gemm_qkv,     cudaFuncAttributeMaxDynamicSharedMemorySize, GSMEM);

    // ----- batched weight transposes (4 launches) -----
    dim3 tb(32, 8);
    transpose_hi3<<<dim3(CDK/32, CE/32, 3*CH), tb>>>(
        Wq1, Wk1, Wv1, p.hb+HB_W1Q, p.hb+HB_W1K, p.hb+HB_W1V, CE, CDK, CH);
    transpose_hi3<<<dim3(CDK/32, CD2/32, 3*CH), tb>>>(
        Wq2, Wk2, Wv2, p.hb+HB_W2Q, p.hb+HB_W2K, p.hb+HB_W2V, CD2, CDK, CH);
    transpose_hi3<<<dim3(CD2/32, CHD/32, 2), tb>>>(
        Wo1, Wo2, Wo1, p.hb+HB_W1O, p.hb+HB_W2O, p.hb+HB_W1O, CHD, CD2, 1);
    transpose_hi3<<<dim3(CD2/32, CD2/32, 2), tb>>>(
        Wff1, Wff2, Wff1, p.hb+HB_W1F, p.hb+HB_W2F, p.hb+HB_W1F, CD2, CD2, 1);

    // ----- positional encoding fused into input convert -----
    addpos_hi<<<(unsigned)((NB_XP + 255) / 256), 256>>>(X, p.hb + HB_XPH, NB_XP);

    __half* ah  = p.hb + HB_AH;
    __half* fh  = p.hb + HB_FH;
    __half* n1h = p.hb + HB_N1H;
    __half* n2h = p.hb + HB_N2H;
    __half* n3h = p.hb + HB_N3H;
    int nbn = (CS * CD2 / 2 + 255) / 256;
    dim3 gff(CD2 / 128, (CB * CS) / 128, 1);

    // ----- block 1: attention (Din = 512) -----
    run_attn(CE, p.hb + HB_XPH,
             p.hb+HB_W1Q, p.hb+HB_W1K, p.hb+HB_W1V, bq1, bk1, bv1,
             p.hb+HB_W1O, bo1, p, ah);
    bn16<1><<<nbn, 256>>>(ah, p.hb + HB_XPH, CE, nullptr, n1h);

    // ----- block 2: FFN -----
    gemm3<true><<<gff, 128, GSMEM>>>(
        n1h, p.hb + HB_W1F, bff1, fh,
        CD2, CD2, CD2, CD2, 1, 0, 0, 0, 0, 0, 0, 0, 1.f);
    bn16<1><<<nbn, 256>>>(fh, n1h, CD2, nullptr, n2h);

    // ----- block 3: attention (Din = 1024) -----
    run_attn(CD2, n2h,
             p.hb+HB_W2Q, p.hb+HB_W2K, p.hb+HB_W2V, bq2, bk2, bv2,
             p.hb+HB_W2O, bo2, p, ah);
    bn16<1><<<nbn, 256>>>(ah, n2h, CD2, nullptr, n3h);

    // ----- block 4: FFN -----
    gemm3<true><<<gff, 128, GSMEM>>>(
        n3h, p.hb + HB_W2F, bff2, fh,
        CD2, CD2, CD2, CD2, 1, 0, 0, 0, 0, 0, 0, 0, 1.f);
    bn16<0><<<nbn, 256>>>(fh, n3h, CD2, out, nullptr);
}

// round 15
// speedup vs baseline: 2.3376x; 1.0077x over previous
#include <cuda_runtime.h>
#include <cuda_fp16.h>
#include <cstdint>
#include <math.h>

#define CB 32
#define CS 512
#define CE 512
#define CDK 128
#define CH 6
#define CD2 1024
#define CHD 768

// ---------------- sizes (elements) ----------------
constexpr long NB_XP  = (long)CB*CS*CE;
constexpr long NB_QKV = (long)CB*CH*CS*CDK;
constexpr long NB_SC  = (long)CB*CH*CS*CS;
constexpr long NB_Z   = (long)CB*CS*CHD;
constexpr long NB_D2  = (long)CB*CS*CD2;
constexpr long NW_QKV1 = (long)CH*CE*CDK;
constexpr long NW_QKV2 = (long)CH*CD2*CDK;
constexpr long NW_O   = (long)CHD*CD2;
constexpr long NW_F   = (long)CD2*CD2;

// ---------------- fp16 scratch offsets (half elems) ----------------
constexpr long HB_XPH = 0;
constexpr long HB_QH  = HB_XPH + NB_XP;
constexpr long HB_KH  = HB_QH + NB_QKV;
constexpr long HB_VTH = HB_KH + NB_QKV;
constexpr long HB_SCH = HB_VTH + NB_QKV;
constexpr long HB_ATH = HB_SCH + NB_SC;
constexpr long HB_ZH  = HB_ATH + NB_SC;
constexpr long HB_AH  = HB_ZH + NB_Z;
constexpr long HB_FH  = HB_AH + NB_D2;
constexpr long HB_N1H = HB_FH + NB_D2;
constexpr long HB_N2H = HB_N1H + NB_D2;
constexpr long HB_N3H = HB_N2H + NB_D2;
constexpr long HB_W1Q = HB_N3H + NB_D2;
constexpr long HB_W1K = HB_W1Q + NW_QKV1;
constexpr long HB_W1V = HB_W1K + NW_QKV1;
constexpr long HB_W1O = HB_W1V + NW_QKV1;
constexpr long HB_W1F = HB_W1O + NW_O;
constexpr long HB_W2Q = HB_W1F + NW_F;
constexpr long HB_W2K = HB_W2Q + NW_QKV2;
constexpr long HB_W2V = HB_W2K + NW_QKV2;
constexpr long HB_W2O = HB_W2V + NW_QKV2;
constexpr long HB_W2F = HB_W2O + NW_O;
constexpr long HB_END = HB_W2F + NW_F;

constexpr long SCRATCH_TOT = (HB_END + 1) / 2 + 64;
__device__ float g_scratch[SCRATCH_TOT];

// ---------------- helpers ----------------
__device__ __forceinline__ void cp16(uint32_t d, const void* s) {
    asm volatile("cp.async.cg.shared.global [%0], [%1], 16;\n" :: "r"(d), "l"(s));
}

#define MMA16816(c, a, b0, b1)                                              \
    asm volatile("mma.sync.aligned.m16n8k16.row.col.f32.f16.f16.f32 "       \
                 "{%0,%1,%2,%3},{%4,%5,%6,%7},{%8,%9},{%0,%1,%2,%3};"       \
                 : "+f"((c)[0]), "+f"((c)[1]), "+f"((c)[2]), "+f"((c)[3])   \
                 : "r"((a)[0]), "r"((a)[1]), "r"((a)[2]), "r"((a)[3]),      \
                   "r"(b0), "r"(b1))

#define MMA16816H(c, a, b0, b1)                                             \
    asm volatile("mma.sync.aligned.m16n8k16.row.col.f16.f16.f16.f16 "       \
                 "{%0,%1},{%2,%3,%4,%5},{%6,%7},{%0,%1};"                   \
                 : "+r"((c)[0]), "+r"((c)[1])                               \
                 : "r"((a)[0]), "r"((a)[1]), "r"((a)[2]), "r"((a)[3]),      \
                   "r"(b0), "r"(b1))

// ---------------- positional encoding + add (fused) ----------------
__global__ void addpos_hi(const float* __restrict__ X,
                          __half* __restrict__ xh, long n) {
    long idx = (long)blockIdx.x * blockDim.x + threadIdx.x;
    if (idx >= n) return;
    int r = (int)(idx & (long)(CS * CE - 1));
    int e = r & 511;
    int s = r >> 9;
    int m = e >> 1;
    float ang = (m >= 128) ? (float)s * 1e-4f : (float)s;
    float pe = (e & 1) ? cosf(ang) : sinf(ang);
    xh[idx] = __float2half(X[idx] + pe);
}

// ---------------- batched transpose f32->hi (up to 3 tensors) ----------
__global__ void transpose_hi3(const float* __restrict__ i0,
                              const float* __restrict__ i1,
                              const float* __restrict__ i2,
                              __half* __restrict__ o0,
                              __half* __restrict__ o1,
                              __half* __restrict__ o2,
                              int R, int C, int zper) {
    __shared__ float t[32][33];
    int zz = blockIdx.z;
    int sel = zz / zper;
    int z = zz - sel * zper;
    const float* in = (sel == 0) ? i0 : (sel == 1) ? i1 : i2;
    __half* oh = (sel == 0) ? o0 : (sel == 1) ? o1 : o2;
    long zo = (long)z * R * C;
    int c0 = blockIdx.x * 32, r0 = blockIdx.y * 32;
    int tx = threadIdx.x, ty = threadIdx.y;
    #pragma unroll
    for (int i = 0; i < 32; i += 8)
        t[ty + i][tx] = in[zo + (long)(r0 + ty + i) * C + c0 + tx];
    __syncthreads();
    #pragma unroll
    for (int i = 0; i < 32; i += 8) {
        float v = t[tx][ty + i];
        long o = zo + (long)(c0 + ty + i) * R + r0 + tx;
        oh[o] = __float2half(v);
    }
}

// ================== GEMM core (fp32 accum, shared device body) =========
#define STGB 20480
#define GSMEM 40960

template<bool TANH>
__device__ __forceinline__ void gemm_body(
    uint8_t* smem, const __half* ga_h, const __half* gb_h,
    const float* bias, __half* Chp,
    int K, int ldc, int m0, int n0, float alpha,
    int tid, int wid, int lane, bool transC)
{
    int g = lane >> 2, tig = lane & 3;
    int wm = (wid & 1) * 64, wn = (wid >> 1) * 64;
    uint32_t sbase = (uint32_t)__cvta_generic_to_shared(smem);

    float acc[4][8][4];
    #pragma unroll
    for (int i = 0; i < 4; ++i)
        #pragma unroll
        for (int j = 0; j < 8; ++j)
            #pragma unroll
            for (int q = 0; q < 4; ++q) acc[i][j][q] = 0.f;

    int nk = K / 32;
    {
        uint32_t d = sbase + tid * 80;
        #pragma unroll
        for (int c = 0; c < 4; ++c) {
            cp16(d + c * 16,         ga_h + c * 8);
            cp16(d + 10240 + c * 16, gb_h + c * 8);
        }
        asm volatile("cp.async.commit_group;");
    }

    for (int kc = 0; kc < nk; ++kc) {
        if (kc + 1 < nk) {
            int k0 = (kc + 1) * 32;
            uint32_t d = sbase + ((kc + 1) & 1) * STGB + tid * 80;
            #pragma unroll
            for (int c = 0; c < 4; ++c) {
                cp16(d + c * 16,         ga_h + k0 + c * 8);
                cp16(d + 10240 + c * 16, gb_h + k0 + c * 8);
            }
            asm volatile("cp.async.commit_group;");
            asm volatile("cp.async.wait_group 1;");
        } else {
            asm volatile("cp.async.wait_group 0;");
        }
        __syncthreads();

        const uint8_t* sb_ = smem + (kc & 1) * STGB;
        #pragma unroll
        for (int ks = 0; ks < 2; ++ks) {
            int cb = ks * 32 + tig * 4;
            uint32_t ah[4][4];
            #pragma unroll
            for (int mt = 0; mt < 4; ++mt) {
                const uint8_t* p = sb_ + (wm + mt * 16 + g) * 80 + cb;
                ah[mt][0] = *(const uint32_t*)(p);
                ah[mt][1] = *(const uint32_t*)(p + 8 * 80);
                ah[mt][2] = *(const uint32_t*)(p + 16);
                ah[mt][3] = *(const uint32_t*)(p + 8 * 80 + 16);
            }
            #pragma unroll
            for (int nt = 0; nt < 8; ++nt) {
                const uint8_t* pb = sb_ + 10240 + (wn + nt * 8 + g) * 80 + cb;
                uint32_t bh0 = *(const uint32_t*)(pb);
                uint32_t bh1 = *(const uint32_t*)(pb + 16);
                #pragma unroll
                for (int mt = 0; mt < 4; ++mt)
                    MMA16816(acc[mt][nt], ah[mt], bh0, bh1);
            }
        }
        __syncthreads();
    }

    if (!transC) {
        #pragma unroll
        for (int nt = 0; nt < 8; ++nt) {
            int col = n0 + wn + nt * 8 + tig * 2;
            float bb0 = 0.f, bb1 = 0.f;
            if (bias) { bb0 = bias[col - n0]; bb1 = bias[col - n0 + 1]; }
            #pragma unroll
            for (int mt = 0; mt < 4; ++mt) {
                int r0 = m0 + wm + mt * 16 + g;
                float v00 = acc[mt][nt][0] * alpha + bb0;
                float v01 = acc[mt][nt][1] * alpha + bb1;
                float v10 = acc[mt][nt][2] * alpha + bb0;
                float v11 = acc[mt][nt][3] * alpha + bb1;
                if (TANH) { v00 = tanhf(v00); v01 = tanhf(v01); v10 = tanhf(v10); v11 = tanhf(v11); }
                __half2 hh;
                hh.x = __float2half(v00); hh.y = __float2half(v01);
                *(__half2*)(Chp + (long)r0 * ldc + col) = hh;
                hh.x = __float2half(v10); hh.y = __float2half(v11);
                *(__half2*)(Chp + (long)(r0 + 8) * ldc + col) = hh;
            }
        }
    } else {
        __half* st = (__half*)smem;
        #pragma unroll
        for (int nt = 0; nt < 8; ++nt) {
            int col = wn + nt * 8 + tig * 2;
            float bb0 = bias[col], bb1 = bias[col + 1];
            #pragma unroll
            for (int mt = 0; mt < 4; ++mt) {
                int r0 = wm + mt * 16 + g;
                st[(long)col * 130 + r0]           = __float2half(acc[mt][nt][0] + bb0);
                st[(long)(col + 1) * 130 + r0]     = __float2half(acc[mt][nt][1] + bb1);
                st[(long)col * 130 + r0 + 8]       = __float2half(acc[mt][nt][2] + bb0);
                st[(long)(col + 1) * 130 + r0 + 8] = __float2half(acc[mt][nt][3] + bb1);
            }
        }
        __syncthreads();
        int dk0 = tid >> 6;
        int t2 = (tid & 63) * 2;
        #pragma unroll
        for (int d0 = 0; d0 < 128; d0 += 2) {
            int dk = d0 + dk0;
            __half2 v;
            v.x = st[(long)dk * 130 + t2];
            v.y = st[(long)dk * 130 + t2 + 1];
            *(__half2*)(Chp + (long)dk * ldc + m0 + t2) = v;
        }
    }
}

// ---------------- generic GEMM (fp16 out) ----------------
template<bool TANH>
__global__ void __launch_bounds__(128, 2) gemm3(
    const __half* __restrict__ Ah,
    const __half* __restrict__ Bh,
    const float* __restrict__ biasb,
    __half* __restrict__ Ch,
    int K, int lda, int ldb, int ldc, int Hdiv,
    long sA_b, long sA_h, long sB_b, long sB_h,
    long sC_b, long sC_h, long sBias_h, float alpha)
{
    extern __shared__ uint8_t smem[];
    int z = blockIdx.z, zb = z / Hdiv, zh_ = z - zb * Hdiv;
    int m0 = blockIdx.y * 128, n0 = blockIdx.x * 128;
    int tid = threadIdx.x, wid = tid >> 5, lane = tid & 31;
    const __half* ga = Ah + zb * sA_b + zh_ * sA_h + (long)(m0 + tid) * lda;
    const __half* gb = Bh + zb * sB_b + zh_ * sB_h + (long)(n0 + tid) * ldb;
    __half* Chp = Ch + zb * sC_b + zh_ * sC_h;
    const float* bias = biasb ? biasb + (long)zh_ * sBias_h + n0 : nullptr;
    gemm_body<TANH>(smem, ga, gb, bias, Chp, K, ldc, m0, n0, alpha, tid, wid, lane, false);
}

// ---------------- merged QKV GEMM (V written transposed) ---------------
__global__ void __launch_bounds__(128, 2) gemm_qkv(
    const __half* __restrict__ Ah,
    const __half* __restrict__ Bq, const __half* __restrict__ Bk,
    const __half* __restrict__ Bv,
    const float* __restrict__ bq, const float* __restrict__ bk,
    const float* __restrict__ bv,
    __half* __restrict__ Cq, __half* __restrict__ Ck, __half* __restrict__ Cvt,
    int K)
{
    extern __shared__ uint8_t smem[];
    int sel = blockIdx.x;
    int z = blockIdx.z, zb = z / CH, zh_ = z - zb * CH;
    int m0 = blockIdx.y * 128;
    int tid = threadIdx.x, wid = tid >> 5, lane = tid & 31;

    const __half* Bh = (sel == 0) ? Bq : (sel == 1) ? Bk : Bv;
    const float* bb  = (sel == 0) ? bq : (sel == 1) ? bk : bv;

    long sA_b = (long)CS * K;
    long sB_h = (long)CDK * K;

    const __half* ga = Ah + zb * sA_b + (long)(m0 + tid) * K;
    const __half* gb = Bh + zh_ * sB_h + (long)tid * K;
    const float* bias = bb + (long)zh_ * CDK;

    if (sel < 2) {
        __half* Ch = (sel == 0) ? Cq : Ck;
        __half* Chp = Ch + zb * (long)CH * CS * CDK + zh_ * (long)CS * CDK;
        gemm_body<false>(smem, ga, gb, bias, Chp, K, CDK, m0, 0, 1.f, tid, wid, lane, false);
    } else {
        __half* Chp = Cvt + zb * (long)CH * CDK * CS + zh_ * (long)CDK * CS;
        gemm_body<false>(smem, ga, gb, bias, Chp, K, CS, m0, 0, 1.f, tid, wid, lane, true);
    }
}

// ---------------- scores GEMM with fp16 accumulators -------------------
// sc[z][s][t] = alpha * Q[z][s][:] . K[z][t][:]   (K = CDK = 128, 4 chunks)
__global__ void __launch_bounds__(128, 2) gemm_sc(
    const __half* __restrict__ Q, const __half* __restrict__ Kh,
    __half* __restrict__ Sc, float alpha)
{
    extern __shared__ uint8_t smem[];
    int z = blockIdx.z;
    int m0 = blockIdx.y * 128, n0 = blockIdx.x * 128;
    int tid = threadIdx.x, wid = tid >> 5, lane = tid & 31;
    int g = lane >> 2, tig = lane & 3;
    int wm = (wid & 1) * 64, wn = (wid >> 1) * 64;
    uint32_t sbase = (uint32_t)__cvta_generic_to_shared(smem);

    const __half* ga = Q + (long)z * CS * CDK + (long)(m0 + tid) * CDK;
    const __half* gb = Kh + (long)z * CS * CDK + (long)(n0 + tid) * CDK;

    uint32_t hacc[4][8][2];
    #pragma unroll
    for (int i = 0; i < 4; ++i)
        #pragma unroll
        for (int j = 0; j < 8; ++j) { hacc[i][j][0] = 0u; hacc[i][j][1] = 0u; }

    const int nk = CDK / 32;   // 4
    {
        uint32_t d = sbase + tid * 80;
        #pragma unroll
        for (int c = 0; c < 4; ++c) {
            cp16(d + c * 16,         ga + c * 8);
            cp16(d + 10240 + c * 16, gb + c * 8);
        }
        asm volatile("cp.async.commit_group;");
    }
    for (int kc = 0; kc < nk; ++kc) {
        if (kc + 1 < nk) {
            int k0 = (kc + 1) * 32;
            uint32_t d = sbase + ((kc + 1) & 1) * STGB + tid * 80;
            #pragma unroll
            for (int c = 0; c < 4; ++c) {
                cp16(d + c * 16,         ga + k0 + c * 8);
                cp16(d + 10240 + c * 16, gb + k0 + c * 8);
            }
            asm volatile("cp.async.commit_group;");
            asm volatile("cp.async.wait_group 1;");
        } else {
            asm volatile("cp.async.wait_group 0;");
        }
        __syncthreads();

        const uint8_t* sb_ = smem + (kc & 1) * STGB;
        #pragma unroll
        for (int ks = 0; ks < 2; ++ks) {
            int cb = ks * 32 + tig * 4;
            uint32_t ah[4][4];
            #pragma unroll
            for (int mt = 0; mt < 4; ++mt) {
                const uint8_t* p = sb_ + (wm + mt * 16 + g) * 80 + cb;
                ah[mt][0] = *(const uint32_t*)(p);
                ah[mt][1] = *(const uint32_t*)(p + 8 * 80);
                ah[mt][2] = *(const uint32_t*)(p + 16);
                ah[mt][3] = *(const uint32_t*)(p + 8 * 80 + 16);
            }
            #pragma unroll
            for (int nt = 0; nt < 8; ++nt) {
                const uint8_t* pb = sb_ + 10240 + (wn + nt * 8 + g) * 80 + cb;
                uint32_t bh0 = *(const uint32_t*)(pb);
                uint32_t bh1 = *(const uint32_t*)(pb + 16);
                #pragma unroll
                for (int mt = 0; mt < 4; ++mt)
                    MMA16816H(hacc[mt][nt], ah[mt], bh0, bh1);
            }
        }
        __syncthreads();
    }

    __half2 al2 = __float2half2_rn(alpha);
    __half* Chp = Sc + (long)z * CS * CS;
    #pragma unroll
    for (int nt = 0; nt < 8; ++nt) {
        int col = n0 + wn + nt * 8 + tig * 2;
        #pragma unroll
        for (int mt = 0; mt < 4; ++mt) {
            int r0 = m0 + wm + mt * 16 + g;
            __half2 lo = *(__half2*)&hacc[mt][nt][0];
            __half2 hi = *(__half2*)&hacc[mt][nt][1];
            *(__half2*)(Chp + (long)r0 * CS + col) = __hmul2(lo, al2);
            *(__half2*)(Chp + (long)(r0 + 8) * CS + col) = __hmul2(hi, al2);
        }
    }
}

// ---------------- softmax over the QUERY axis (packed regs) -----------
__global__ void __launch_bounds__(512) softmax_q2(const __half* __restrict__ Sc,
                                                  __half* __restrict__ oh) {
    __shared__ float2 sm[16][32], sl[16][32];
    long base = (long)blockIdx.x * CS * CS + blockIdx.y * 64;
    int w = threadIdx.x >> 5, lane = threadIdx.x & 31;
    const __half* p = Sc + base + (long)w * 32 * CS + lane * 2;
    __half2 v2[32];
    // pass 1: load + packed max
    __half2 hm = __float2half2_rn(-60000.f);
    #pragma unroll
    for (int i = 0; i < 32; ++i) {
        v2[i] = *(const __half2*)(p + (long)i * CS);
        hm = __hmax2(hm, v2[i]);
    }
    float m0 = __half2float(__low2half(hm));
    float m1 = __half2float(__high2half(hm));
    // pass 2: exp + local sum; store exp packed in place
    float l0 = 0.f, l1 = 0.f;
    #pragma unroll
    for (int i = 0; i < 32; ++i) {
        float e0 = __expf(__half2float(__low2half(v2[i])) - m0);
        float e1 = __expf(__half2float(__high2half(v2[i])) - m1);
        l0 += e0; l1 += e1;
        v2[i] = __floats2half2_rn(e0, e1);
    }
    sm[w][lane] = make_float2(m0, m1);
    sl[w][lane] = make_float2(l0, l1);
    __syncthreads();
    float M0 = -1e30f, M1 = -1e30f;
    #pragma unroll
    for (int ww = 0; ww < 16; ++ww) {
        M0 = fmaxf(M0, sm[ww][lane].x);
        M1 = fmaxf(M1, sm[ww][lane].y);
    }
    float L0 = 0.f, L1 = 0.f;
    #pragma unroll
    for (int ww = 0; ww < 16; ++ww) {
        L0 += sl[ww][lane].x * __expf(sm[ww][lane].x - M0);
        L1 += sl[ww][lane].y * __expf(sm[ww][lane].y - M1);
    }
    __half2 sc2 = __floats2half2_rn(__expf(m0 - M0) / L0, __expf(m1 - M1) / L1);
    __half* po = oh + base + (long)w * 32 * CS + lane * 2;
    #pragma unroll
    for (int i = 0; i < 32; ++i)
        *(__half2*)(po + (long)i * CS) = __hmul2(v2[i], sc2);
}

// ---------------- batch-norm, fp16-out variant (packed regs) -----------
__global__ void bn16_h(const __half* __restrict__ x,
                       const __half* __restrict__ add, int addw,
                       __half* __restrict__ oh) {
    int j2 = blockIdx.x * blockDim.x + threadIdx.x;
    if (j2 >= CS * CD2 / 2) return;
    int j = j2 * 2;
    const long SD = (long)CS * CD2;
    int s = j >> 10;
    int e = j & 1023;
    int ae = e & (addw - 1);
    long aoff = (long)s * addw + ae;

    __half2 t2[CB];
    float sum0 = 0.f, sum1 = 0.f, sq0 = 0.f, sq1 = 0.f;
    #pragma unroll
    for (int b = 0; b < CB; ++b) {
        __half2 xa = *(const __half2*)(x + (long)b * SD + j);
        __half2 ad = *(const __half2*)(add + (long)b * CS * addw + aoff);
        float t0 = __half2float(__low2half(xa)) + __half2float(__low2half(ad));
        float t1 = __half2float(__high2half(xa)) + __half2float(__high2half(ad));
        t2[b] = __floats2half2_rn(t0, t1);
        sum0 += t0; sum1 += t1;
        sq0 += t0 * t0; sq1 += t1 * t1;
    }
    float mean0 = sum0 * (1.f / CB), mean1 = sum1 * (1.f / CB);
    float var0 = sq0 * (1.f / CB) - mean0 * mean0;
    float var1 = sq1 * (1.f / CB) - mean1 * mean1;
    float rstd0 = rsqrtf(var0 + 1e-3f);
    float rstd1 = rsqrtf(var1 + 1e-3f);
    #pragma unroll
    for (int b = 0; b < CB; ++b) {
        float o0 = (__half2float(__low2half(t2[b])) - mean0) * rstd0;
        float o1 = (__half2float(__high2half(t2[b])) - mean1) * rstd1;
        *(__half2*)(oh + (long)b * SD + j) = __floats2half2_rn(o0, o1);
    }
}

// ---------------- batch-norm, f32-out variant (final) ------------------
__global__ void bn16_f(const __half* __restrict__ x,
                       const __half* __restrict__ add, int addw,
                       float* __restrict__ outf) {
    int j2 = blockIdx.x * blockDim.x + threadIdx.x;
    if (j2 >= CS * CD2 / 2) return;
    int j = j2 * 2;
    const long SD = (long)CS * CD2;
    int s = j >> 10;
    int e = j & 1023;
    int ae = e & (addw - 1);
    long aoff = (long)s * addw + ae;

    float v0[CB], v1[CB];
    float sum0 = 0.f, sum1 = 0.f;
    #pragma unroll
    for (int b = 0; b < CB; ++b) {
        __half2 xa = *(const __half2*)(x + (long)b * SD + j);
        __half2 ad = *(const __half2*)(add + (long)b * CS * addw + aoff);
        float t0 = __half2float(__low2half(xa)) + __half2float(__low2half(ad));
        float t1 = __half2float(__high2half(xa)) + __half2float(__high2half(ad));
        v0[b] = t0; v1[b] = t1;
        sum0 += t0; sum1 += t1;
    }
    float mean0 = sum0 * (1.f / CB), mean1 = sum1 * (1.f / CB);
    float var0 = 0.f, var1 = 0.f;
    #pragma unroll
    for (int b = 0; b < CB; ++b) {
        float d0 = v0[b] - mean0, d1 = v1[b] - mean1;
        var0 += d0 * d0; var1 += d1 * d1;
    }
    float rstd0 = rsqrtf(var0 * (1.f / CB) + 1e-3f);
    float rstd1 = rsqrtf(var1 * (1.f / CB) + 1e-3f);
    #pragma unroll
    for (int b = 0; b < CB; ++b) {
        float o0 = (v0[b] - mean0) * rstd0;
        float o1 = (v1[b] - mean1) * rstd1;
        *(float2*)(outf + (long)b * SD + j) = make_float2(o0, o1);
    }
}

// ---------------- host orchestration ----------------
struct Ptrs {
    __half* hb;
};

static void run_attn(int Din, const __half* xh,
                     const __half* WqT, const __half* WkT, const __half* WvT,
                     const float* bq, const float* bk, const float* bv,
                     const __half* WoT, const float* bo, Ptrs p, __half* aout)
{
    __half *qh = p.hb + HB_QH;
    __half *kh = p.hb + HB_KH;
    __half *vth = p.hb + HB_VTH;
    __half *sch = p.hb + HB_SCH;
    __half *ath = p.hb + HB_ATH;
    __half *zh = p.hb + HB_ZH;

    gemm_qkv<<<dim3(3, CS / 128, CB * CH), 128, GSMEM>>>(
        xh, WqT, WkT, WvT, bq, bk, bv, qh, kh, vth, Din);

    // scores = Q @ K^T * 1/sqrt(dk), fp16 accumulators
    gemm_sc<<<dim3(CS / 128, CS / 128, CB * CH), 128, GSMEM>>>(
        qh, kh, sch, 0.08838834764831845f);

    softmax_q2<<<dim3(CB * CH, CS / 64), 512>>>(sch, ath);

    gemm3<false><<<dim3(1, CS / 128, CB * CH), 128, GSMEM>>>(
        ath, vth, nullptr, zh,
        CS, CS, CS, CHD, CH,
        (long)CH * CS * CS, (long)CS * CS,
        (long)CH * CDK * CS, (long)CDK * CS,
        (long)CS * CHD, CDK, 0, 1.f);

    gemm3<false><<<dim3(CD2 / 128, (CB * CS) / 128, 1), 128, GSMEM>>>(
        zh, WoT, bo, aout,
        CHD, CHD, CHD, CD2, 1, 0, 0, 0, 0, 0, 0, 0, 1.f);
}

extern "C" void kernel_launch(void* const* d_in, const int* in_sizes, int n_in,
                              void* d_out, int out_size)
{
    const float* X    = (const float*)d_in[0];
    const float* Wq1  = (const float*)d_in[1];
    const float* Wk1  = (const float*)d_in[2];
    const float* Wv1  = (const float*)d_in[3];
    const float* bq1  = (const float*)d_in[4];
    const float* bk1  = (const float*)d_in[5];
    const float* bv1  = (const float*)d_in[6];
    const float* Wo1  = (const float*)d_in[7];
    const float* bo1  = (const float*)d_in[8];
    const float* Wff1 = (const float*)d_in[9];
    const float* bff1 = (const float*)d_in[10];
    const float* Wq2  = (const float*)d_in[11];
    const float* Wk2  = (const float*)d_in[12];
    const float* Wv2  = (const float*)d_in[13];
    const float* bq2  = (const float*)d_in[14];
    const float* bk2  = (const float*)d_in[15];
    const float* bv2  = (const float*)d_in[16];
    const float* Wo2  = (const float*)d_in[17];
    const float* bo2  = (const float*)d_in[18];
    const float* Wff2 = (const float*)d_in[19];
    const float* bff2 = (const float*)d_in[20];
    float* out = (float*)d_out;

    float* sb = nullptr;
    cudaGetSymbolAddress((void**)&sb, g_scratch);
    Ptrs p;
    p.hb = (__half*)sb;

    cudaFuncSetAttribute(gemm3<false>, cudaFuncAttributeMaxDynamicSharedMemorySize, GSMEM);
    cudaFuncSetAttribute(gemm3<true>,  cudaFuncAttributeMaxDynamicSharedMemorySize, GSMEM);
    cudaFuncSetAttribute(gemm_qkv,     cudaFuncAttributeMaxDynamicSharedMemorySize, GSMEM);
    cudaFuncSetAttribute(gemm_sc,      cudaFuncAttributeMaxDynamicSharedMemorySize, GSMEM);

    // ----- batched weight transposes (4 launches) -----
    dim3 tb(32, 8);
    transpose_hi3<<<dim3(CDK/32, CE/32, 3*CH), tb>>>(
        Wq1, Wk1, Wv1, p.hb+HB_W1Q, p.hb+HB_W1K, p.hb+HB_W1V, CE, CDK, CH);
    transpose_hi3<<<dim3(CDK/32, CD2/32, 3*CH), tb>>>(
        Wq2, Wk2, Wv2, p.hb+HB_W2Q, p.hb+HB_W2K, p.hb+HB_W2V, CD2, CDK, CH);
    transpose_hi3<<<dim3(CD2/32, CHD/32, 2), tb>>>(
        Wo1, Wo2, Wo1, p.hb+HB_W1O, p.hb+HB_W2O, p.hb+HB_W1O, CHD, CD2, 1);
    transpose_hi3<<<dim3(CD2/32, CD2/32, 2), tb>>>(
        Wff1, Wff2, Wff1, p.hb+HB_W1F, p.hb+HB_W2F, p.hb+HB_W1F, CD2, CD2, 1);

    addpos_hi<<<(unsigned)((NB_XP + 255) / 256), 256>>>(X, p.hb + HB_XPH, NB_XP);

    __half* ah  = p.hb + HB_AH;
    __half* fh  = p.hb + HB_FH;
    __half* n1h = p.hb + HB_N1H;
    __half* n2h = p.hb + HB_N2H;
    __half* n3h = p.hb + HB_N3H;
    int nbn = (CS * CD2 / 2 + 255) / 256;
    dim3 gff(CD2 / 128, (CB * CS) / 128, 1);

    // ----- block 1: attention (Din = 512) -----
    run_attn(CE, p.hb + HB_XPH,
             p.hb+HB_W1Q, p.hb+HB_W1K, p.hb+HB_W1V, bq1, bk1, bv1,
             p.hb+HB_W1O, bo1, p, ah);
    bn16_h<<<nbn, 256>>>(ah, p.hb + HB_XPH, CE, n1h);

    // ----- block 2: FFN -----
    gemm3<true><<<gff, 128, GSMEM>>>(
        n1h, p.hb + HB_W1F, bff1, fh,
        CD2, CD2, CD2, CD2, 1, 0, 0, 0, 0, 0, 0, 0, 1.f);
    bn16_h<<<nbn, 256>>>(fh, n1h, CD2, n2h);

    // ----- block 3: attention (Din = 1024) -----
    run_attn(CD2, n2h,
             p.hb+HB_W2Q, p.hb+HB_W2K, p.hb+HB_W2V, bq2, bk2, bv2,
             p.hb+HB_W2O, bo2, p, ah);
    bn16_h<<<nbn, 256>>>(ah, n2h, CD2, n3h);

    // ----- block 4: FFN -----
    gemm3<true><<<gff, 128, GSMEM>>>(
        n3h, p.hb + HB_W2F, bff2, fh,
        CD2, CD2, CD2, CD2, 1, 0, 0, 0, 0, 0, 0, 0, 1.f);
    bn16_f<<<nbn, 256>>>(fh, n3h, CD2, out);
}

// round 16
// speedup vs baseline: 2.3788x; 1.0176x over previous
#include <cuda_runtime.h>
#include <cuda_fp16.h>
#include <cstdint>
#include <math.h>

#define CB 32
#define CS 512
#define CE 512
#define CDK 128
#define CH 6
#define CD2 1024
#define CHD 768

// ---------------- sizes (elements) ----------------
constexpr long NB_XP  = (long)CB*CS*CE;
constexpr long NB_QKV = (long)CB*CH*CS*CDK;
constexpr long NB_SC  = (long)CB*CH*CS*CS;
constexpr long NB_Z   = (long)CB*CS*CHD;
constexpr long NB_D2  = (long)CB*CS*CD2;
constexpr long NW_QKV1 = (long)CH*CE*CDK;
constexpr long NW_QKV2 = (long)CH*CD2*CDK;
constexpr long NW_O   = (long)CHD*CD2;
constexpr long NW_F   = (long)CD2*CD2;

// ---------------- fp16 scratch offsets (half elems) ----------------
constexpr long HB_XPH = 0;
constexpr long HB_QH  = HB_XPH + NB_XP;
constexpr long HB_KH  = HB_QH + NB_QKV;
constexpr long HB_VTH = HB_KH + NB_QKV;
constexpr long HB_SCH = HB_VTH + NB_QKV;
constexpr long HB_ATH = HB_SCH + NB_SC;
constexpr long HB_ZH  = HB_ATH + NB_SC;
constexpr long HB_AH  = HB_ZH + NB_Z;
constexpr long HB_FH  = HB_AH + NB_D2;
constexpr long HB_N1H = HB_FH + NB_D2;
constexpr long HB_N2H = HB_N1H + NB_D2;
constexpr long HB_N3H = HB_N2H + NB_D2;
constexpr long HB_W1Q = HB_N3H + NB_D2;
constexpr long HB_W1K = HB_W1Q + NW_QKV1;
constexpr long HB_W1V = HB_W1K + NW_QKV1;
constexpr long HB_W1O = HB_W1V + NW_QKV1;
constexpr long HB_W1F = HB_W1O + NW_O;
constexpr long HB_W2Q = HB_W1F + NW_F;
constexpr long HB_W2K = HB_W2Q + NW_QKV2;
constexpr long HB_W2V = HB_W2K + NW_QKV2;
constexpr long HB_W2O = HB_W2V + NW_QKV2;
constexpr long HB_W2F = HB_W2O + NW_O;
constexpr long HB_END = HB_W2F + NW_F;

constexpr long SCRATCH_TOT = (HB_END + 1) / 2 + 64;
__device__ float g_scratch[SCRATCH_TOT];

// ---------------- helpers ----------------
__device__ __forceinline__ void cp16(uint32_t d, const void* s) {
    asm volatile("cp.async.cg.shared.global [%0], [%1], 16;\n" :: "r"(d), "l"(s));
}

#define MMA16816(c, a, b0, b1)                                              \
    asm volatile("mma.sync.aligned.m16n8k16.row.col.f32.f16.f16.f32 "       \
                 "{%0,%1,%2,%3},{%4,%5,%6,%7},{%8,%9},{%0,%1,%2,%3};"       \
                 : "+f"((c)[0]), "+f"((c)[1]), "+f"((c)[2]), "+f"((c)[3])   \
                 : "r"((a)[0]), "r"((a)[1]), "r"((a)[2]), "r"((a)[3]),      \
                   "r"(b0), "r"(b1))

#define MMA16816H(c, a, b0, b1)                                             \
    asm volatile("mma.sync.aligned.m16n8k16.row.col.f16.f16.f16.f16 "       \
                 "{%0,%1},{%2,%3,%4,%5},{%6,%7},{%0,%1};"                   \
                 : "+r"((c)[0]), "+r"((c)[1])                               \
                 : "r"((a)[0]), "r"((a)[1]), "r"((a)[2]), "r"((a)[3]),      \
                   "r"(b0), "r"(b1))

// ---------------- positional encoding + add (fused) ----------------
__global__ void addpos_hi(const float* __restrict__ X,
                          __half* __restrict__ xh, long n) {
    long idx = (long)blockIdx.x * blockDim.x + threadIdx.x;
    if (idx >= n) return;
    int r = (int)(idx & (long)(CS * CE - 1));
    int e = r & 511;
    int s = r >> 9;
    int m = e >> 1;
    float ang = (m >= 128) ? (float)s * 1e-4f : (float)s;
    float pe = (e & 1) ? cosf(ang) : sinf(ang);
    xh[idx] = __float2half(X[idx] + pe);
}

// ---------------- batched transpose f32->hi (up to 3 tensors) ----------
__global__ void transpose_hi3(const float* __restrict__ i0,
                              const float* __restrict__ i1,
                              const float* __restrict__ i2,
                              __half* __restrict__ o0,
                              __half* __restrict__ o1,
                              __half* __restrict__ o2,
                              int R, int C, int zper) {
    __shared__ float t[32][33];
    int zz = blockIdx.z;
    int sel = zz / zper;
    int z = zz - sel * zper;
    const float* in = (sel == 0) ? i0 : (sel == 1) ? i1 : i2;
    __half* oh = (sel == 0) ? o0 : (sel == 1) ? o1 : o2;
    long zo = (long)z * R * C;
    int c0 = blockIdx.x * 32, r0 = blockIdx.y * 32;
    int tx = threadIdx.x, ty = threadIdx.y;
    #pragma unroll
    for (int i = 0; i < 32; i += 8)
        t[ty + i][tx] = in[zo + (long)(r0 + ty + i) * C + c0 + tx];
    __syncthreads();
    #pragma unroll
    for (int i = 0; i < 32; i += 8) {
        float v = t[tx][ty + i];
        long o = zo + (long)(c0 + ty + i) * R + r0 + tx;
        oh[o] = __float2half(v);
    }
}

// ================== GEMM core, BK=64 (fp32 accum) ==================
// Stage: A 128x64 half @0 (pitch 144B), B 128x64 half @18432. 2 stages.
#define STGB 36864
#define GSMEM 73728

template<bool TANH>
__device__ __forceinline__ void gemm_body(
    uint8_t* smem, const __half* ga_h, const __half* gb_h,
    const float* bias, __half* Chp,
    int K, int ldc, int m0, int n0, float alpha,
    int tid, int wid, int lane, bool transC)
{
    int g = lane >> 2, tig = lane & 3;
    int wm = (wid & 1) * 64, wn = (wid >> 1) * 64;
    uint32_t sbase = (uint32_t)__cvta_generic_to_shared(smem);

    float acc[4][8][4];
    #pragma unroll
    for (int i = 0; i < 4; ++i)
        #pragma unroll
        for (int j = 0; j < 8; ++j)
            #pragma unroll
            for (int q = 0; q < 4; ++q) acc[i][j][q] = 0.f;

    int nk = K / 64;
    {
        uint32_t d = sbase + tid * 144;
        #pragma unroll
        for (int c = 0; c < 8; ++c) {
            cp16(d + c * 16,         ga_h + c * 8);
            cp16(d + 18432 + c * 16, gb_h + c * 8);
        }
        asm volatile("cp.async.commit_group;");
    }

    for (int kc = 0; kc < nk; ++kc) {
        if (kc + 1 < nk) {
            int k0 = (kc + 1) * 64;
            uint32_t d = sbase + ((kc + 1) & 1) * STGB + tid * 144;
            #pragma unroll
            for (int c = 0; c < 8; ++c) {
                cp16(d + c * 16,         ga_h + k0 + c * 8);
                cp16(d + 18432 + c * 16, gb_h + k0 + c * 8);
            }
            asm volatile("cp.async.commit_group;");
            asm volatile("cp.async.wait_group 1;");
        } else {
            asm volatile("cp.async.wait_group 0;");
        }
        __syncthreads();

        const uint8_t* sb_ = smem + (kc & 1) * STGB;
        #pragma unroll
        for (int ks = 0; ks < 4; ++ks) {
            int cb = ks * 32 + tig * 4;
            uint32_t ah[4][4];
            #pragma unroll
            for (int mt = 0; mt < 4; ++mt) {
                const uint8_t* p = sb_ + (wm + mt * 16 + g) * 144 + cb;
                ah[mt][0] = *(const uint32_t*)(p);
                ah[mt][1] = *(const uint32_t*)(p + 8 * 144);
                ah[mt][2] = *(const uint32_t*)(p + 16);
                ah[mt][3] = *(const uint32_t*)(p + 8 * 144 + 16);
            }
            #pragma unroll
            for (int nt = 0; nt < 8; ++nt) {
                const uint8_t* pb = sb_ + 18432 + (wn + nt * 8 + g) * 144 + cb;
                uint32_t bh0 = *(const uint32_t*)(pb);
                uint32_t bh1 = *(const uint32_t*)(pb + 16);
                #pragma unroll
                for (int mt = 0; mt < 4; ++mt)
                    MMA16816(acc[mt][nt], ah[mt], bh0, bh1);
            }
        }
        __syncthreads();
    }

    if (!transC) {
        #pragma unroll
        for (int nt = 0; nt < 8; ++nt) {
            int col = n0 + wn + nt * 8 + tig * 2;
            float bb0 = 0.f, bb1 = 0.f;
            if (bias) { bb0 = bias[col - n0]; bb1 = bias[col - n0 + 1]; }
            #pragma unroll
            for (int mt = 0; mt < 4; ++mt) {
                int r0 = m0 + wm + mt * 16 + g;
                float v00 = acc[mt][nt][0] * alpha + bb0;
                float v01 = acc[mt][nt][1] * alpha + bb1;
                float v10 = acc[mt][nt][2] * alpha + bb0;
                float v11 = acc[mt][nt][3] * alpha + bb1;
                if (TANH) { v00 = tanhf(v00); v01 = tanhf(v01); v10 = tanhf(v10); v11 = tanhf(v11); }
                __half2 hh;
                hh.x = __float2half(v00); hh.y = __float2half(v01);
                *(__half2*)(Chp + (long)r0 * ldc + col) = hh;
                hh.x = __float2half(v10); hh.y = __float2half(v11);
                *(__half2*)(Chp + (long)(r0 + 8) * ldc + col) = hh;
            }
        }
    } else {
        __half* st = (__half*)smem;
        #pragma unroll
        for (int nt = 0; nt < 8; ++nt) {
            int col = wn + nt * 8 + tig * 2;
            float bb0 = bias[col], bb1 = bias[col + 1];
            #pragma unroll
            for (int mt = 0; mt < 4; ++mt) {
                int r0 = wm + mt * 16 + g;
                st[(long)col * 130 + r0]           = __float2half(acc[mt][nt][0] + bb0);
                st[(long)(col + 1) * 130 + r0]     = __float2half(acc[mt][nt][1] + bb1);
                st[(long)col * 130 + r0 + 8]       = __float2half(acc[mt][nt][2] + bb0);
                st[(long)(col + 1) * 130 + r0 + 8] = __float2half(acc[mt][nt][3] + bb1);
            }
        }
        __syncthreads();
        int dk0 = tid >> 6;
        int t2 = (tid & 63) * 2;
        #pragma unroll
        for (int d0 = 0; d0 < 128; d0 += 2) {
            int dk = d0 + dk0;
            __half2 v;
            v.x = st[(long)dk * 130 + t2];
            v.y = st[(long)dk * 130 + t2 + 1];
            *(__half2*)(Chp + (long)dk * ldc + m0 + t2) = v;
        }
    }
}

// ---------------- generic GEMM (fp16 out) ----------------
template<bool TANH>
__global__ void __launch_bounds__(128, 2) gemm3(
    const __half* __restrict__ Ah,
    const __half* __restrict__ Bh,
    const float* __restrict__ biasb,
    __half* __restrict__ Ch,
    int K, int lda, int ldb, int ldc, int Hdiv,
    long sA_b, long sA_h, long sB_b, long sB_h,
    long sC_b, long sC_h, long sBias_h, float alpha)
{
    extern __shared__ uint8_t smem[];
    int z = blockIdx.z, zb = z / Hdiv, zh_ = z - zb * Hdiv;
    int m0 = blockIdx.y * 128, n0 = blockIdx.x * 128;
    int tid = threadIdx.x, wid = tid >> 5, lane = tid & 31;
    const __half* ga = Ah + zb * sA_b + zh_ * sA_h + (long)(m0 + tid) * lda;
    const __half* gb = Bh + zb * sB_b + zh_ * sB_h + (long)(n0 + tid) * ldb;
    __half* Chp = Ch + zb * sC_b + zh_ * sC_h;
    const float* bias = biasb ? biasb + (long)zh_ * sBias_h + n0 : nullptr;
    gemm_body<TANH>(smem, ga, gb, bias, Chp, K, ldc, m0, n0, alpha, tid, wid, lane, false);
}

// ---------------- merged QKV GEMM (V written transposed) ---------------
__global__ void __launch_bounds__(128, 2) gemm_qkv(
    const __half* __restrict__ Ah,
    const __half* __restrict__ Bq, const __half* __restrict__ Bk,
    const __half* __restrict__ Bv,
    const float* __restrict__ bq, const float* __restrict__ bk,
    const float* __restrict__ bv,
    __half* __restrict__ Cq, __half* __restrict__ Ck, __half* __restrict__ Cvt,
    int K)
{
    extern __shared__ uint8_t smem[];
    int sel = blockIdx.x;
    int z = blockIdx.z, zb = z / CH, zh_ = z - zb * CH;
    int m0 = blockIdx.y * 128;
    int tid = threadIdx.x, wid = tid >> 5, lane = tid & 31;

    const __half* Bh = (sel == 0) ? Bq : (sel == 1) ? Bk : Bv;
    const float* bb  = (sel == 0) ? bq : (sel == 1) ? bk : bv;

    long sA_b = (long)CS * K;
    long sB_h = (long)CDK * K;

    const __half* ga = Ah + zb * sA_b + (long)(m0 + tid) * K;
    const __half* gb = Bh + zh_ * sB_h + (long)tid * K;
    const float* bias = bb + (long)zh_ * CDK;

    if (sel < 2) {
        __half* Ch = (sel == 0) ? Cq : Ck;
        __half* Chp = Ch + zb * (long)CH * CS * CDK + zh_ * (long)CS * CDK;
        gemm_body<false>(smem, ga, gb, bias, Chp, K, CDK, m0, 0, 1.f, tid, wid, lane, false);
    } else {
        __half* Chp = Cvt + zb * (long)CH * CDK * CS + zh_ * (long)CDK * CS;
        gemm_body<false>(smem, ga, gb, bias, Chp, K, CS, m0, 0, 1.f, tid, wid, lane, true);
    }
}

// ---------------- scores GEMM with fp16 accumulators, BK=64 ------------
__global__ void __launch_bounds__(128, 2) gemm_sc(
    const __half* __restrict__ Q, const __half* __restrict__ Kh,
    __half* __restrict__ Sc, float alpha)
{
    extern __shared__ uint8_t smem[];
    int z = blockIdx.z;
    int m0 = blockIdx.y * 128, n0 = blockIdx.x * 128;
    int tid = threadIdx.x, wid = tid >> 5, lane = tid & 31;
    int g = lane >> 2, tig = lane & 3;
    int wm = (wid & 1) * 64, wn = (wid >> 1) * 64;
    uint32_t sbase = (uint32_t)__cvta_generic_to_shared(smem);

    const __half* ga = Q + (long)z * CS * CDK + (long)(m0 + tid) * CDK;
    const __half* gb = Kh + (long)z * CS * CDK + (long)(n0 + tid) * CDK;

    uint32_t hacc[4][8][2];
    #pragma unroll
    for (int i = 0; i < 4; ++i)
        #pragma unroll
        for (int j = 0; j < 8; ++j) { hacc[i][j][0] = 0u; hacc[i][j][1] = 0u; }

    const int nk = CDK / 64;   // 2
    {
        uint32_t d = sbase + tid * 144;
        #pragma unroll
        for (int c = 0; c < 8; ++c) {
            cp16(d + c * 16,         ga + c * 8);
            cp16(d + 18432 + c * 16, gb + c * 8);
        }
        asm volatile("cp.async.commit_group;");
    }
    for (int kc = 0; kc < nk; ++kc) {
        if (kc + 1 < nk) {
            int k0 = (kc + 1) * 64;
            uint32_t d = sbase + ((kc + 1) & 1) * STGB + tid * 144;
            #pragma unroll
            for (int c = 0; c < 8; ++c) {
                cp16(d + c * 16,         ga + k0 + c * 8);
                cp16(d + 18432 + c * 16, gb + k0 + c * 8);
            }
            asm volatile("cp.async.commit_group;");
            asm volatile("cp.async.wait_group 1;");
        } else {
            asm volatile("cp.async.wait_group 0;");
        }
        __syncthreads();

        const uint8_t* sb_ = smem + (kc & 1) * STGB;
        #pragma unroll
        for (int ks = 0; ks < 4; ++ks) {
            int cb = ks * 32 + tig * 4;
            uint32_t ah[4][4];
            #pragma unroll
            for (int mt = 0; mt < 4; ++mt) {
                const uint8_t* p = sb_ + (wm + mt * 16 + g) * 144 + cb;
                ah[mt][0] = *(const uint32_t*)(p);
                ah[mt][1] = *(const uint32_t*)(p + 8 * 144);
                ah[mt][2] = *(const uint32_t*)(p + 16);
                ah[mt][3] = *(const uint32_t*)(p + 8 * 144 + 16);
            }
            #pragma unroll
            for (int nt = 0; nt < 8; ++nt) {
                const uint8_t* pb = sb_ + 18432 + (wn + nt * 8 + g) * 144 + cb;
                uint32_t bh0 = *(const uint32_t*)(pb);
                uint32_t bh1 = *(const uint32_t*)(pb + 16);
                #pragma unroll
                for (int mt = 0; mt < 4; ++mt)
                    MMA16816H(hacc[mt][nt], ah[mt], bh0, bh1);
            }
        }
        __syncthreads();
    }

    __half2 al2 = __float2half2_rn(alpha);
    __half* Chp = Sc + (long)z * CS * CS;
    #pragma unroll
    for (int nt = 0; nt < 8; ++nt) {
        int col = n0 + wn + nt * 8 + tig * 2;
        #pragma unroll
        for (int mt = 0; mt < 4; ++mt) {
            int r0 = m0 + wm + mt * 16 + g;
            __half2 lo = *(__half2*)&hacc[mt][nt][0];
            __half2 hi = *(__half2*)&hacc[mt][nt][1];
            *(__half2*)(Chp + (long)r0 * CS + col) = __hmul2(lo, al2);
            *(__half2*)(Chp + (long)(r0 + 8) * CS + col) = __hmul2(hi, al2);
        }
    }
}

// ---------------- softmax over the QUERY axis (packed regs) -----------
__global__ void __launch_bounds__(512) softmax_q2(const __half* __restrict__ Sc,
                                                  __half* __restrict__ oh) {
    __shared__ float2 sm[16][32], sl[16][32];
    long base = (long)blockIdx.x * CS * CS + blockIdx.y * 64;
    int w = threadIdx.x >> 5, lane = threadIdx.x & 31;
    const __half* p = Sc + base + (long)w * 32 * CS + lane * 2;
    __half2 v2[32];
    __half2 hm = __float2half2_rn(-60000.f);
    #pragma unroll
    for (int i = 0; i < 32; ++i) {
        v2[i] = *(const __half2*)(p + (long)i * CS);
        hm = __hmax2(hm, v2[i]);
    }
    float m0 = __half2float(__low2half(hm));
    float m1 = __half2float(__high2half(hm));
    float l0 = 0.f, l1 = 0.f;
    #pragma unroll
    for (int i = 0; i < 32; ++i) {
        float e0 = __expf(__half2float(__low2half(v2[i])) - m0);
        float e1 = __expf(__half2float(__high2half(v2[i])) - m1);
        l0 += e0; l1 += e1;
        v2[i] = __floats2half2_rn(e0, e1);
    }
    sm[w][lane] = make_float2(m0, m1);
    sl[w][lane] = make_float2(l0, l1);
    __syncthreads();
    float M0 = -1e30f, M1 = -1e30f;
    #pragma unroll
    for (int ww = 0; ww < 16; ++ww) {
        M0 = fmaxf(M0, sm[ww][lane].x);
        M1 = fmaxf(M1, sm[ww][lane].y);
    }
    float L0 = 0.f, L1 = 0.f;
    #pragma unroll
    for (int ww = 0; ww < 16; ++ww) {
        L0 += sl[ww][lane].x * __expf(sm[ww][lane].x - M0);
        L1 += sl[ww][lane].y * __expf(sm[ww][lane].y - M1);
    }
    __half2 sc2 = __floats2half2_rn(__expf(m0 - M0) / L0, __expf(m1 - M1) / L1);
    __half* po = oh + base + (long)w * 32 * CS + lane * 2;
    #pragma unroll
    for (int i = 0; i < 32; ++i)
        *(__half2*)(po + (long)i * CS) = __hmul2(v2[i], sc2);
}

// ---------------- batch-norm, fp16-out variant (packed regs) -----------
__global__ void bn16_h(const __half* __restrict__ x,
                       const __half* __restrict__ add, int addw,
                       __half* __restrict__ oh) {
    int j2 = blockIdx.x * blockDim.x + threadIdx.x;
    if (j2 >= CS * CD2 / 2) return;
    int j = j2 * 2;
    const long SD = (long)CS * CD2;
    int s = j >> 10;
    int e = j & 1023;
    int ae = e & (addw - 1);
    long aoff = (long)s * addw + ae;

    __half2 t2[CB];
    float sum0 = 0.f, sum1 = 0.f, sq0 = 0.f, sq1 = 0.f;
    #pragma unroll
    for (int b = 0; b < CB; ++b) {
        __half2 xa = *(const __half2*)(x + (long)b * SD + j);
        __half2 ad = *(const __half2*)(add + (long)b * CS * addw + aoff);
        float t0 = __half2float(__low2half(xa)) + __half2float(__low2half(ad));
        float t1 = __half2float(__high2half(xa)) + __half2float(__high2half(ad));
        t2[b] = __floats2half2_rn(t0, t1);
        sum0 += t0; sum1 += t1;
        sq0 += t0 * t0; sq1 += t1 * t1;
    }
    float mean0 = sum0 * (1.f / CB), mean1 = sum1 * (1.f / CB);
    float var0 = sq0 * (1.f / CB) - mean0 * mean0;
    float var1 = sq1 * (1.f / CB) - mean1 * mean1;
    float rstd0 = rsqrtf(var0 + 1e-3f);
    float rstd1 = rsqrtf(var1 + 1e-3f);
    #pragma unroll
    for (int b = 0; b < CB; ++b) {
        float o0 = (__half2float(__low2half(t2[b])) - mean0) * rstd0;
        float o1 = (__half2float(__high2half(t2[b])) - mean1) * rstd1;
        *(__half2*)(oh + (long)b * SD + j) = __floats2half2_rn(o0, o1);
    }
}

// ---------------- batch-norm, f32-out variant (final) ------------------
__global__ void bn16_f(const __half* __restrict__ x,
                       const __half* __restrict__ add, int addw,
                       float* __restrict__ outf) {
    int j2 = blockIdx.x * blockDim.x + threadIdx.x;
    if (j2 >= CS * CD2 / 2) return;
    int j = j2 * 2;
    const long SD = (long)CS * CD2;
    int s = j >> 10;
    int e = j & 1023;
    int ae = e & (addw - 1);
    long aoff = (long)s * addw + ae;

    float v0[CB], v1[CB];
    float sum0 = 0.f, sum1 = 0.f;
    #pragma unroll
    for (int b = 0; b < CB; ++b) {
        __half2 xa = *(const __half2*)(x + (long)b * SD + j);
        __half2 ad = *(const __half2*)(add + (long)b * CS * addw + aoff);
        float t0 = __half2float(__low2half(xa)) + __half2float(__low2half(ad));
        float t1 = __half2float(__high2half(xa)) + __half2float(__high2half(ad));
        v0[b] = t0; v1[b] = t1;
        sum0 += t0; sum1 += t1;
    }
    float mean0 = sum0 * (1.f / CB), mean1 = sum1 * (1.f / CB);
    float var0 = 0.f, var1 = 0.f;
    #pragma unroll
    for (int b = 0; b < CB; ++b) {
        float d0 = v0[b] - mean0, d1 = v1[b] - mean1;
        var0 += d0 * d0; var1 += d1 * d1;
    }
    float rstd0 = rsqrtf(var0 * (1.f / CB) + 1e-3f);
    float rstd1 = rsqrtf(var1 * (1.f / CB) + 1e-3f);
    #pragma unroll
    for (int b = 0; b < CB; ++b) {
        float o0 = (v0[b] - mean0) * rstd0;
        float o1 = (v1[b] - mean1) * rstd1;
        *(float2*)(outf + (long)b * SD + j) = make_float2(o0, o1);
    }
}

// ---------------- host orchestration ----------------
struct Ptrs {
    __half* hb;
};

static void run_attn(int Din, const __half* xh,
                     const __half* WqT, const __half* WkT, const __half* WvT,
                     const float* bq, const float* bk, const float* bv,
                     const __half* WoT, const float* bo, Ptrs p, __half* aout)
{
    __half *qh = p.hb + HB_QH;
    __half *kh = p.hb + HB_KH;
    __half *vth = p.hb + HB_VTH;
    __half *sch = p.hb + HB_SCH;
    __half *ath = p.hb + HB_ATH;
    __half *zh = p.hb + HB_ZH;

    gemm_qkv<<<dim3(3, CS / 128, CB * CH), 128, GSMEM>>>(
        xh, WqT, WkT, WvT, bq, bk, bv, qh, kh, vth, Din);

    gemm_sc<<<dim3(CS / 128, CS / 128, CB * CH), 128, GSMEM>>>(
        qh, kh, sch, 0.08838834764831845f);

    softmax_q2<<<dim3(CB * CH, CS / 64), 512>>>(sch, ath);

    gemm3<false><<<dim3(1, CS / 128, CB * CH), 128, GSMEM>>>(
        ath, vth, nullptr, zh,
        CS, CS, CS, CHD, CH,
        (long)CH * CS * CS, (long)CS * CS,
        (long)CH * CDK * CS, (long)CDK * CS,
        (long)CS * CHD, CDK, 0, 1.f);

    gemm3<false><<<dim3(CD2 / 128, (CB * CS) / 128, 1), 128, GSMEM>>>(
        zh, WoT, bo, aout,
        CHD, CHD, CHD, CD2, 1, 0, 0, 0, 0, 0, 0, 0, 1.f);
}

extern "C" void kernel_launch(void* const* d_in, const int* in_sizes, int n_in,
                              void* d_out, int out_size)
{
    const float* X    = (const float*)d_in[0];
    const float* Wq1  = (const float*)d_in[1];
    const float* Wk1  = (const float*)d_in[2];
    const float* Wv1  = (const float*)d_in[3];
    const float* bq1  = (const float*)d_in[4];
    const float* bk1  = (const float*)d_in[5];
    const float* bv1  = (const float*)d_in[6];
    const float* Wo1  = (const float*)d_in[7];
    const float* bo1  = (const float*)d_in[8];
    const float* Wff1 = (const float*)d_in[9];
    const float* bff1 = (const float*)d_in[10];
    const float* Wq2  = (const float*)d_in[11];
    const float* Wk2  = (const float*)d_in[12];
    const float* Wv2  = (const float*)d_in[13];
    const float* bq2  = (const float*)d_in[14];
    const float* bk2  = (const float*)d_in[15];
    const float* bv2  = (const float*)d_in[16];
    const float* Wo2  = (const float*)d_in[17];
    const float* bo2  = (const float*)d_in[18];
    const float* Wff2 = (const float*)d_in[19];
    const float* bff2 = (const float*)d_in[20];
    float* out = (float*)d_out;

    float* sb = nullptr;
    cudaGetSymbolAddress((void**)&sb, g_scratch);
    Ptrs p;
    p.hb = (__half*)sb;

    cudaFuncSetAttribute(gemm3<false>, cudaFuncAttributeMaxDynamicSharedMemorySize, GSMEM);
    cudaFuncSetAttribute(gemm3<true>,  cudaFuncAttributeMaxDynamicSharedMemorySize, GSMEM);
    cudaFuncSetAttribute(gemm_qkv,     cudaFuncAttributeMaxDynamicSharedMemorySize, GSMEM);
    cudaFuncSetAttribute(gemm_sc,      cudaFuncAttributeMaxDynamicSharedMemorySize, GSMEM);

    // ----- batched weight transposes (4 launches) -----
    dim3 tb(32, 8);
    transpose_hi3<<<dim3(CDK/32, CE/32, 3*CH), tb>>>(
        Wq1, Wk1, Wv1, p.hb+HB_W1Q, p.hb+HB_W1K, p.hb+HB_W1V, CE, CDK, CH);
    transpose_hi3<<<dim3(CDK/32, CD2/32, 3*CH), tb>>>(
        Wq2, Wk2, Wv2, p.hb+HB_W2Q, p.hb+HB_W2K, p.hb+HB_W2V, CD2, CDK, CH);
    transpose_hi3<<<dim3(CD2/32, CHD/32, 2), tb>>>(
        Wo1, Wo2, Wo1, p.hb+HB_W1O, p.hb+HB_W2O, p.hb+HB_W1O, CHD, CD2, 1);
    transpose_hi3<<<dim3(CD2/32, CD2/32, 2), tb>>>(
        Wff1, Wff2, Wff1, p.hb+HB_W1F, p.hb+HB_W2F, p.hb+HB_W1F, CD2, CD2, 1);

    addpos_hi<<<(unsigned)((NB_XP + 255) / 256), 256>>>(X, p.hb + HB_XPH, NB_XP);

    __half* ah  = p.hb + HB_AH;
    __half* fh  = p.hb + HB_FH;
    __half* n1h = p.hb + HB_N1H;
    __half* n2h = p.hb + HB_N2H;
    __half* n3h = p.hb + HB_N3H;
    int nbn = (CS * CD2 / 2 + 255) / 256;
    dim3 gff(CD2 / 128, (CB * CS) / 128, 1);

    // ----- block 1: attention (Din = 512) -----
    run_attn(CE, p.hb + HB_XPH,
             p.hb+HB_W1Q, p.hb+HB_W1K, p.hb+HB_W1V, bq1, bk1, bv1,
             p.hb+HB_W1O, bo1, p, ah);
    bn16_h<<<nbn, 256>>>(ah, p.hb + HB_XPH, CE, n1h);

    // ----- block 2: FFN -----
    gemm3<true><<<gff, 128, GSMEM>>>(
        n1h, p.hb + HB_W1F, bff1, fh,
        CD2, CD2, CD2, CD2, 1, 0, 0, 0, 0, 0, 0, 0, 1.f);
    bn16_h<<<nbn, 256>>>(fh, n1h, CD2, n2h);

    // ----- block 3: attention (Din = 1024) -----
    run_attn(CD2, n2h,
             p.hb+HB_W2Q, p.hb+HB_W2K, p.hb+HB_W2V, bq2, bk2, bv2,
             p.hb+HB_W2O, bo2, p, ah);
    bn16_h<<<nbn, 256>>>(ah, n2h, CD2, n3h);

    // ----- block 4: FFN -----
    gemm3<true><<<gff, 128, GSMEM>>>(
        n3h, p.hb + HB_W2F, bff2, fh,
        CD2, CD2, CD2, CD2, 1, 0, 0, 0, 0, 0, 0, 0, 1.f);
    bn16_f<<<nbn, 256>>>(fh, n3h, CD2, out);
}